// round 1
// baseline (speedup 1.0000x reference)
#include <cuda_runtime.h>
#include <cuda_bf16.h>
#include <math.h>

// ---------------- problem constants ----------------
#define NNODES 32768
#define D      384
#define EFEAT  768
#define BATCH  64
#define SEQ    512
#define NGRAPH 512
#define NEDGES 1048576
#define KIN    300
#define EPS    1e-5f

// ---------------- device scratch (static, no allocs) ----------------
__device__ float g_bufA[(size_t)NNODES * D];
__device__ float g_bufB[(size_t)NNODES * D];
__device__ float g_bufC[(size_t)NNODES * D];
__device__ int   g_degi[NNODES];
__device__ float g_isq[NNODES];
__device__ int   g_off[NNODES + 1];
__device__ int   g_cursor[NNODES];
__device__ int   g_csr[NEDGES];
__device__ float g_sum[7 * EFEAT];
__device__ float g_sq[7 * EFEAT];
__device__ float g_hsent[BATCH * EFEAT];
__device__ float g_flat[BATCH * EFEAT];
__device__ float g_outc[BATCH * EFEAT];
__device__ float g_att[BATCH * EFEAT];
__device__ int   g_sel[BATCH * 2];

// ---------------- zero scratch ----------------
__global__ void zero_kernel() {
    int i = blockIdx.x * blockDim.x + threadIdx.x;
    if (i < NNODES) g_degi[i] = 0;
    if (i < 7 * EFEAT) { g_sum[i] = 0.f; g_sq[i] = 0.f; }
    if (i < BATCH * EFEAT) g_hsent[i] = 0.f;
}

// ---------------- sentence mean ----------------
__global__ void hsent_kernel(const float* __restrict__ lh, const float* __restrict__ fh) {
    int b = blockIdx.x, chunk = blockIdx.y, t = threadIdx.x;
    size_t base = ((size_t)b * SEQ + chunk * 128) * EFEAT + t;
    float s = 0.f;
    for (int ss = 0; ss < 128; ss++) {
        s += lh[base + (size_t)ss * EFEAT] + fh[base + (size_t)ss * EFEAT];
    }
    atomicAdd(&g_hsent[b * EFEAT + t], s * (0.5f / 512.0f));
}

// ---------------- tiled SGEMM: C = relu?(A[MxK] @ W[KxN] + bias) ----------------
#define BM 128
#define BN 128
#define BKK 8
__global__ void __launch_bounds__(256, 2)
sgemm_kernel(const float* __restrict__ A, const float* __restrict__ W,
             const float* __restrict__ bias, float* __restrict__ C,
             int M, int N, int K, int do_relu) {
    __shared__ __align__(16) float As[BKK][BM];
    __shared__ __align__(16) float Bs[BKK][BN];
    int tid = threadIdx.x;
    int bm = blockIdx.y * BM;
    int bn = blockIdx.x * BN;
    int tx = tid & 15, ty = tid >> 4;

    float acc[8][8];
#pragma unroll
    for (int i = 0; i < 8; i++)
#pragma unroll
        for (int j = 0; j < 8; j++) acc[i][j] = 0.f;

    int arow = tid >> 1;
    int acol0 = (tid & 1) * 4;
    int brow = tid >> 5;
    int bcol0 = (tid & 31) * 4;

    for (int k0 = 0; k0 < K; k0 += BKK) {
#pragma unroll
        for (int i = 0; i < 4; i++) {
            int kk = k0 + acol0 + i;
            As[acol0 + i][arow] = (kk < K) ? A[(size_t)(bm + arow) * K + kk] : 0.f;
        }
        {
            int kk = k0 + brow;
#pragma unroll
            for (int i = 0; i < 4; i++) {
                Bs[brow][bcol0 + i] = (kk < K) ? W[(size_t)kk * N + bn + bcol0 + i] : 0.f;
            }
        }
        __syncthreads();
#pragma unroll
        for (int k = 0; k < BKK; k++) {
            float a[8], b[8];
            *(float4*)&a[0] = *(const float4*)&As[k][ty * 8];
            *(float4*)&a[4] = *(const float4*)&As[k][ty * 8 + 4];
            *(float4*)&b[0] = *(const float4*)&Bs[k][tx * 8];
            *(float4*)&b[4] = *(const float4*)&Bs[k][tx * 8 + 4];
#pragma unroll
            for (int i = 0; i < 8; i++)
#pragma unroll
                for (int j = 0; j < 8; j++) acc[i][j] += a[i] * b[j];
        }
        __syncthreads();
    }
#pragma unroll
    for (int i = 0; i < 8; i++) {
        int row = bm + ty * 8 + i;
#pragma unroll
        for (int j = 0; j < 8; j++) {
            int col = bn + tx * 8 + j;
            float v = acc[i][j];
            if (bias) v += bias[col];
            if (do_relu) v = fmaxf(v, 0.f);
            C[(size_t)row * N + col] = v;
        }
    }
}

// ---------------- column stats ----------------
__global__ void stats_kernel(const float* __restrict__ X, int M, int N,
                             float* __restrict__ sum, float* __restrict__ sq) {
    int col = threadIdx.x;
    int rows_per = (M + gridDim.x - 1) / gridDim.x;
    int r0 = blockIdx.x * rows_per;
    int r1 = min(M, r0 + rows_per);
    float s = 0.f, q = 0.f;
    for (int r = r0; r < r1; r++) {
        float v = X[(size_t)r * N + col];
        s += v; q += v * v;
    }
    atomicAdd(&sum[col], s);
    atomicAdd(&sq[col], q);
}

// ---------------- BN apply ----------------
__global__ void bn_apply_kernel(const float* __restrict__ X, float* __restrict__ Y,
                                int M, int N,
                                const float* __restrict__ sum, const float* __restrict__ sq,
                                const float* __restrict__ gam, const float* __restrict__ bet) {
    size_t idx = (size_t)blockIdx.x * blockDim.x + threadIdx.x;
    size_t tot = (size_t)M * N;
    if (idx >= tot) return;
    int col = (int)(idx % N);
    float invM = 1.0f / (float)M;
    float m = sum[col] * invM;
    float v = sq[col] * invM - m * m;
    Y[idx] = gam[col] * (X[idx] - m) * rsqrtf(v + EPS) + bet[col];
}

// ---------------- degree histogram ----------------
__global__ void deg_kernel(const int* __restrict__ dst) {
    int e = blockIdx.x * blockDim.x + threadIdx.x;
    if (e < NEDGES) atomicAdd(&g_degi[dst[e]], 1);
}

__global__ void isq_kernel() {
    int n = blockIdx.x * blockDim.x + threadIdx.x;
    if (n < NNODES) g_isq[n] = rsqrtf((float)g_degi[n] + 1.0f);
}

// ---------------- single-block exclusive scan ----------------
__global__ void scan_kernel() {
    __shared__ int sh[1024];
    int tid = threadIdx.x;
    int base = tid * 32;
    int local[32];
    int s = 0;
    for (int i = 0; i < 32; i++) { local[i] = s; s += g_degi[base + i]; }
    sh[tid] = s;
    __syncthreads();
    for (int off = 1; off < 1024; off <<= 1) {
        int v = 0;
        if (tid >= off) v = sh[tid - off];
        __syncthreads();
        if (tid >= off) sh[tid] += v;
        __syncthreads();
    }
    int prev = (tid == 0) ? 0 : sh[tid - 1];
    for (int i = 0; i < 32; i++) {
        g_off[base + i] = prev + local[i];
        g_cursor[base + i] = prev + local[i];
    }
    if (tid == 1023) g_off[NNODES] = sh[1023];
}

// ---------------- CSR scatter ----------------
__global__ void scatter_kernel(const int* __restrict__ src, const int* __restrict__ dst) {
    int e = blockIdx.x * blockDim.x + threadIdx.x;
    if (e < NEDGES) {
        int d = dst[e];
        int p = atomicAdd(&g_cursor[d], 1);
        g_csr[p] = src[e];
    }
}

// ---------------- GCN aggregation (atomic-free, per-node block) ----------------
__global__ void __launch_bounds__(128)
agg_kernel(const float* __restrict__ xw, const float* __restrict__ bias,
           float* __restrict__ out) {
    int n = blockIdx.x;
    int t = threadIdx.x;
    float isqn = g_isq[n];
    const float* selfrow = xw + (size_t)n * D;
    float sc = isqn * isqn;
    float a0 = selfrow[t] * sc;
    float a1 = selfrow[128 + t] * sc;
    float a2 = selfrow[256 + t] * sc;

    int beg = g_off[n], end = g_off[n + 1];
    __shared__ int ssrc[128];
    __shared__ float scoef[128];
    for (int p = beg; p < end; p += 128) {
        int cnt = min(128, end - p);
        __syncthreads();
        if (t < cnt) {
            int s = g_csr[p + t];
            ssrc[t] = s;
            scoef[t] = g_isq[s] * isqn;
        }
        __syncthreads();
        for (int j = 0; j < cnt; j++) {
            int s = ssrc[j];
            float c = scoef[j];
            const float* row = xw + (size_t)s * D;
            a0 += row[t] * c;
            a1 += row[128 + t] * c;
            a2 += row[256 + t] * c;
        }
    }
    out[(size_t)n * D + t]       = fmaxf(a0 + bias[t], 0.f);
    out[(size_t)n * D + 128 + t] = fmaxf(a1 + bias[128 + t], 0.f);
    out[(size_t)n * D + 256 + t] = fmaxf(a2 + bias[256 + t], 0.f);
}

// ---------------- masked-node selection ----------------
__global__ void sel_kernel(const int* __restrict__ mask) {
    int b = threadIdx.x;  // 64 threads
    int c = 0;
    for (int i = 0; i < NGRAPH; i++) {
        if (mask[b * NGRAPH + i]) {
            if (c < 2) g_sel[b * 2 + c] = i;
            c++;
        }
    }
}

__global__ void gather_kernel(const float* __restrict__ X) {
    int b = blockIdx.x >> 1;
    int j = blockIdx.x & 1;
    int node = b * NGRAPH + g_sel[b * 2 + j];
    g_flat[b * EFEAT + j * D + threadIdx.x] = X[(size_t)node * D + threadIdx.x];
}

// ---------------- outc pre-BN: relu(flat @ w_cat + b_cat) ----------------
__global__ void cat_gemm_kernel(const float* __restrict__ Wc, const float* __restrict__ bc) {
    __shared__ float sh[EFEAT];
    int b = blockIdx.x, t = threadIdx.x;
    sh[t] = g_flat[b * EFEAT + t];
    __syncthreads();
    float s = bc[t];
    for (int k = 0; k < EFEAT; k++) s += sh[k] * Wc[(size_t)k * EFEAT + t];
    g_outc[b * EFEAT + t] = fmaxf(s, 0.f);
}

// ---------------- att = BN1(hsent) + BN0(outc) (outc BN already applied) --------
__global__ void att_kernel(const float* __restrict__ gam, const float* __restrict__ bet) {
    int b = blockIdx.x, t = threadIdx.x;
    float m = g_sum[6 * EFEAT + t] / (float)BATCH;
    float v = g_sq[6 * EFEAT + t] / (float)BATCH - m * m;
    float h = gam[t] * (g_hsent[b * EFEAT + t] - m) * rsqrtf(v + EPS) + bet[t];
    g_att[b * EFEAT + t] = h + g_outc[b * EFEAT + t];
}

// ---------------- final: out = att @ w_out + b_out ----------------
__global__ void out_kernel(const float* __restrict__ wout, const float* __restrict__ bout,
                           float* __restrict__ out) {
    int i = threadIdx.x;  // 192
    int b = i / 3, c = i % 3;
    float s = bout[c];
    for (int e = 0; e < EFEAT; e++) s += g_att[b * EFEAT + e] * wout[e * 3 + c];
    out[i] = s;
}

// ============================== launch ==============================
extern "C" void kernel_launch(void* const* d_in, const int* in_sizes, int n_in,
                              void* d_out, int out_size) {
    const float* last_h  = (const float*)d_in[0];
    const float* first_h = (const float*)d_in[1];
    const float* x_nodes = (const float*)d_in[2];
    const int*   eidx    = (const int*)d_in[3];
    const int*   mask    = (const int*)d_in[4];
    const float* w_pre1  = (const float*)d_in[5];
    const float* b_pre1  = (const float*)d_in[6];
    const float* w_pre2  = (const float*)d_in[7];
    const float* b_pre2  = (const float*)d_in[8];
    const float* w_conv  = (const float*)d_in[9];
    const float* b_conv  = (const float*)d_in[10];
    const float* bng_g   = (const float*)d_in[11];
    const float* bng_b   = (const float*)d_in[12];
    const float* w_post1 = (const float*)d_in[13];
    const float* b_post1 = (const float*)d_in[14];
    const float* w_post2 = (const float*)d_in[15];
    const float* b_post2 = (const float*)d_in[16];
    const float* w_cat   = (const float*)d_in[17];
    const float* b_cat   = (const float*)d_in[18];
    const float* bn_g    = (const float*)d_in[19];
    const float* bn_b    = (const float*)d_in[20];
    const float* w_out   = (const float*)d_in[21];
    const float* b_out   = (const float*)d_in[22];
    float* out = (float*)d_out;

    const int* esrc = eidx;
    const int* edst = eidx + NEDGES;

    float *bufA, *bufB, *bufC, *sum, *sq, *outc;
    cudaGetSymbolAddress((void**)&bufA, g_bufA);
    cudaGetSymbolAddress((void**)&bufB, g_bufB);
    cudaGetSymbolAddress((void**)&bufC, g_bufC);
    cudaGetSymbolAddress((void**)&sum, g_sum);
    cudaGetSymbolAddress((void**)&sq, g_sq);
    cudaGetSymbolAddress((void**)&outc, g_outc);

    dim3 gemm_grid(D / BN, NNODES / BM);       // (3, 256)
    int bn_blocks = (NNODES * D + 255) / 256;

    zero_kernel<<<192, 256>>>();

    // sentence branch
    hsent_kernel<<<dim3(BATCH, 4), EFEAT>>>(last_h, first_h);

    // degree / CSR
    deg_kernel<<<NEDGES / 256, 256>>>(edst);
    isq_kernel<<<NNODES / 256, 256>>>();
    scan_kernel<<<1, 1024>>>();
    scatter_kernel<<<NEDGES / 256, 256>>>(esrc, edst);

    // pre-MLP 1 -> BN row 0
    sgemm_kernel<<<gemm_grid, 256>>>(x_nodes, w_pre1, b_pre1, bufA, NNODES, D, KIN, 1);
    stats_kernel<<<64, D>>>(bufA, NNODES, D, sum + 0 * EFEAT, sq + 0 * EFEAT);
    bn_apply_kernel<<<bn_blocks, 256>>>(bufA, bufB, NNODES, D, sum + 0 * EFEAT, sq + 0 * EFEAT,
                                        bng_g + 0 * D, bng_b + 0 * D);

    // pre-MLP 2 -> BN row 1 ; bufB = GCN input
    sgemm_kernel<<<gemm_grid, 256>>>(bufB, w_pre2, b_pre2, bufA, NNODES, D, D, 1);
    stats_kernel<<<64, D>>>(bufA, NNODES, D, sum + 1 * EFEAT, sq + 1 * EFEAT);
    bn_apply_kernel<<<bn_blocks, 256>>>(bufA, bufB, NNODES, D, sum + 1 * EFEAT, sq + 1 * EFEAT,
                                        bng_g + 1 * D, bng_b + 1 * D);

    // only conv i=2 survives (reference overwrites out each iteration)
    sgemm_kernel<<<gemm_grid, 256>>>(bufB, w_conv + 2 * D * D, nullptr, bufA, NNODES, D, D, 0);

    // GCN aggregation + bias + relu -> BN row 4
    agg_kernel<<<NNODES, 128>>>(bufA, b_conv + 2 * D, bufC);
    stats_kernel<<<64, D>>>(bufC, NNODES, D, sum + 2 * EFEAT, sq + 2 * EFEAT);
    bn_apply_kernel<<<bn_blocks, 256>>>(bufC, bufA, NNODES, D, sum + 2 * EFEAT, sq + 2 * EFEAT,
                                        bng_g + 4 * D, bng_b + 4 * D);

    // post-MLP 1 -> BN row 5
    sgemm_kernel<<<gemm_grid, 256>>>(bufA, w_post1, b_post1, bufC, NNODES, D, D, 1);
    stats_kernel<<<64, D>>>(bufC, NNODES, D, sum + 3 * EFEAT, sq + 3 * EFEAT);
    bn_apply_kernel<<<bn_blocks, 256>>>(bufC, bufA, NNODES, D, sum + 3 * EFEAT, sq + 3 * EFEAT,
                                        bng_g + 5 * D, bng_b + 5 * D);

    // post-MLP 2 -> BN row 6
    sgemm_kernel<<<gemm_grid, 256>>>(bufA, w_post2, b_post2, bufC, NNODES, D, D, 1);
    stats_kernel<<<64, D>>>(bufC, NNODES, D, sum + 4 * EFEAT, sq + 4 * EFEAT);
    bn_apply_kernel<<<bn_blocks, 256>>>(bufC, bufB, NNODES, D, sum + 4 * EFEAT, sq + 4 * EFEAT,
                                        bng_g + 6 * D, bng_b + 6 * D);

    // gather masked nodes, cat-MLP, output head
    sel_kernel<<<1, BATCH>>>(mask);
    gather_kernel<<<BATCH * 2, D>>>(bufB);
    cat_gemm_kernel<<<BATCH, EFEAT>>>(w_cat, b_cat);
    stats_kernel<<<1, EFEAT>>>(outc, BATCH, EFEAT, sum + 5 * EFEAT, sq + 5 * EFEAT);
    bn_apply_kernel<<<(BATCH * EFEAT + 255) / 256, 256>>>(outc, outc, BATCH, EFEAT,
                                                          sum + 5 * EFEAT, sq + 5 * EFEAT,
                                                          bn_g + 0 * EFEAT, bn_b + 0 * EFEAT);
    float* hs;
    cudaGetSymbolAddress((void**)&hs, g_hsent);
    stats_kernel<<<1, EFEAT>>>(hs, BATCH, EFEAT, sum + 6 * EFEAT, sq + 6 * EFEAT);
    att_kernel<<<BATCH, EFEAT>>>(bn_g + 1 * EFEAT, bn_b + 1 * EFEAT);
    out_kernel<<<1, 192>>>(w_out, b_out, out);
}

// round 3
// speedup vs baseline: 2.0837x; 2.0837x over previous
#include <cuda_runtime.h>
#include <cuda_bf16.h>
#include <cstdint>
#include <math.h>

// ---------------- problem constants ----------------
#define NNODES 32768
#define D      384
#define EFEAT  768
#define BATCH  64
#define SEQ    512
#define NGRAPH 512
#define NEDGES 1048576
#define EPS    1e-5f

// ---------------- device scratch (static, no allocs) ----------------
__device__ float g_bufA[(size_t)NNODES * D];
__device__ float g_bufB[(size_t)NNODES * D];
__device__ float g_bufC[(size_t)NNODES * D];
__device__ int   g_degi[NNODES];
__device__ float g_isq[NNODES];
__device__ int   g_off[NNODES + 1];
__device__ int   g_cursor[NNODES];
__device__ int   g_csr[NEDGES];
__device__ float g_sum[7 * EFEAT];
__device__ float g_sq[7 * EFEAT];
__device__ float g_hsent[BATCH * EFEAT];
__device__ float g_flat[BATCH * EFEAT];
__device__ float g_outc[BATCH * EFEAT];
__device__ float g_att[BATCH * EFEAT];
__device__ int   g_sel[BATCH * 2];
// transposed weights, bf16 hi/lo split: [N=384][KPAD<=384]
__device__ __nv_bfloat16 g_wth[5][D * D];
__device__ __nv_bfloat16 g_wtl[5][D * D];
// folded BN affine coefficients (scale, shift) per column
__device__ float g_cscale[5][D];
__device__ float g_cshift[5][D];

// ================= helpers =================
__device__ __forceinline__ uint32_t smem_u32(const void* p) {
    uint32_t a;
    asm("{ .reg .u64 t; cvta.to.shared.u64 t, %1; cvt.u32.u64 %0, t; }" : "=r"(a) : "l"(p));
    return a;
}
__device__ __forceinline__ void ldsm4(uint32_t* r, uint32_t addr) {
    asm volatile("ldmatrix.sync.aligned.m8n8.x4.shared.b16 {%0,%1,%2,%3}, [%4];"
                 : "=r"(r[0]), "=r"(r[1]), "=r"(r[2]), "=r"(r[3]) : "r"(addr));
}
__device__ __forceinline__ void mma16816(float* c, const uint32_t* a, uint32_t b0, uint32_t b1) {
    asm volatile("mma.sync.aligned.m16n8k16.row.col.f32.bf16.bf16.f32 "
                 "{%0,%1,%2,%3},{%4,%5,%6,%7},{%8,%9},{%0,%1,%2,%3};"
                 : "+f"(c[0]), "+f"(c[1]), "+f"(c[2]), "+f"(c[3])
                 : "r"(a[0]), "r"(a[1]), "r"(a[2]), "r"(a[3]), "r"(b0), "r"(b1));
}

// ================= misc kernels =================
__global__ void zero_kernel() {
    int i = blockIdx.x * blockDim.x + threadIdx.x;
    if (i < NNODES) g_degi[i] = 0;
    if (i < 7 * EFEAT) { g_sum[i] = 0.f; g_sq[i] = 0.f; }
    if (i < BATCH * EFEAT) g_hsent[i] = 0.f;
}

__global__ void hsent_kernel(const float* __restrict__ lh, const float* __restrict__ fh) {
    int b = blockIdx.x, chunk = blockIdx.y, t = threadIdx.x;
    size_t base = ((size_t)b * SEQ + chunk * 128) * EFEAT + t;
    float s = 0.f;
    for (int ss = 0; ss < 128; ss++)
        s += lh[base + (size_t)ss * EFEAT] + fh[base + (size_t)ss * EFEAT];
    atomicAdd(&g_hsent[b * EFEAT + t], s * (0.5f / 512.0f));
}

// weight prep: W[K,N] f32 -> Wt_hi/lo [N][KPAD] bf16 (zero padded)
__global__ void wprep_kernel(const float* __restrict__ W, int K, int KPAD,
                             __nv_bfloat16* __restrict__ hi, __nv_bfloat16* __restrict__ lo) {
    int idx = blockIdx.x * blockDim.x + threadIdx.x;
    if (idx >= D * KPAD) return;
    int n = idx / KPAD, k = idx % KPAD;
    float v = (k < K) ? W[(size_t)k * D + n] : 0.f;
    __nv_bfloat16 h = __float2bfloat16_rn(v);
    hi[idx] = h;
    lo[idx] = __float2bfloat16_rn(v - __bfloat162float(h));
}

// column stats
__global__ void stats_kernel(const float* __restrict__ X, int M, int N,
                             float* __restrict__ sum, float* __restrict__ sq) {
    int col = threadIdx.x;
    int rows_per = (M + gridDim.x - 1) / gridDim.x;
    int r0 = blockIdx.x * rows_per;
    int r1 = min(M, r0 + rows_per);
    float s = 0.f, q = 0.f;
    for (int r = r0; r < r1; r++) {
        float v = X[(size_t)r * N + col];
        s += v; q += v * v;
    }
    atomicAdd(&sum[col], s);
    atomicAdd(&sq[col], q);
}

// BN -> per-column affine coefficients
__global__ void bncoef_kernel(const float* __restrict__ sum, const float* __restrict__ sq,
                              float Mf, const float* __restrict__ gam, const float* __restrict__ bet,
                              float* __restrict__ scale, float* __restrict__ shift) {
    int c = threadIdx.x;
    float m = sum[c] / Mf;
    float v = sq[c] / Mf - m * m;
    float s = gam[c] * rsqrtf(v + EPS);
    scale[c] = s;
    shift[c] = bet[c] - m * s;
}

// small BN apply (outc only)
__global__ void bn_apply_kernel(const float* __restrict__ X, float* __restrict__ Y,
                                int M, int N,
                                const float* __restrict__ sum, const float* __restrict__ sq,
                                const float* __restrict__ gam, const float* __restrict__ bet) {
    size_t idx = (size_t)blockIdx.x * blockDim.x + threadIdx.x;
    if (idx >= (size_t)M * N) return;
    int col = (int)(idx % N);
    float invM = 1.0f / (float)M;
    float m = sum[col] * invM;
    float v = sq[col] * invM - m * m;
    Y[idx] = gam[col] * (X[idx] - m) * rsqrtf(v + EPS) + bet[col];
}

// ================= mma.sync bf16x3 GEMM =================
// C[32768, 384] = relu?(affine(A) @ Wt^T + bias)
// A fp32 [M,K]; Wt bf16 hi/lo [384][KPAD] (row n, contiguous k)
// block tile 128(M) x 64(N), K-chunk 32; 8 warps (4m x 2n), warp tile 32x32
#define AROW 40   // padded row stride (halves) -> 80B, conflict-free ldmatrix
__global__ void __launch_bounds__(256, 2)
mma_gemm(const float* __restrict__ A,
         const __nv_bfloat16* __restrict__ Bh, const __nv_bfloat16* __restrict__ Bl,
         const float* __restrict__ scale, const float* __restrict__ shift,
         const float* __restrict__ bias, float* __restrict__ C,
         int K, int KPAD, int nchunks, int do_relu) {
    __shared__ __nv_bfloat16 sAh[128 * AROW];
    __shared__ __nv_bfloat16 sAl[128 * AROW];
    __shared__ __nv_bfloat16 sBh[64 * AROW];
    __shared__ __nv_bfloat16 sBl[64 * AROW];

    int tid = threadIdx.x;
    int wid = tid >> 5, lane = tid & 31;
    int bm = blockIdx.y * 128, bn = blockIdx.x * 64;
    int wm = wid & 3, wn = wid >> 2;   // 4 x 2 warp grid

    uint32_t baseAh = smem_u32(sAh), baseAl = smem_u32(sAl);
    uint32_t baseBh = smem_u32(sBh), baseBl = smem_u32(sBl);

    float acc[2][4][4];
#pragma unroll
    for (int i = 0; i < 2; i++)
#pragma unroll
        for (int j = 0; j < 4; j++)
#pragma unroll
            for (int k = 0; k < 4; k++) acc[i][j][k] = 0.f;

    // per-lane ldmatrix address components
    int g = lane >> 3, r = lane & 7;
    int frag_row = (g & 1) * 8 + r;      // row within 16-row tile
    int frag_col = (g >> 1) * 8;         // 0 or 8 within k16

    for (int chunk = 0; chunk < nchunks; chunk++) {
        // ---- stage A tile (128 x 32) with affine + hi/lo split ----
#pragma unroll
        for (int it = 0; it < 4; it++) {
            int i = tid + it * 256;          // 0..1023
            int row = i >> 3, c4 = i & 7;
            int gcol = chunk * 32 + c4 * 4;
            float4 v = make_float4(0.f, 0.f, 0.f, 0.f);
            if (gcol + 3 < K) {
                v = *(const float4*)(A + (size_t)(bm + row) * K + gcol);
                if (scale) {
                    float4 sc = *(const float4*)(scale + gcol);
                    float4 sh = *(const float4*)(shift + gcol);
                    v.x = v.x * sc.x + sh.x; v.y = v.y * sc.y + sh.y;
                    v.z = v.z * sc.z + sh.z; v.w = v.w * sc.w + sh.w;
                }
            }
            __nv_bfloat16 h0 = __float2bfloat16_rn(v.x), h1 = __float2bfloat16_rn(v.y);
            __nv_bfloat16 h2 = __float2bfloat16_rn(v.z), h3 = __float2bfloat16_rn(v.w);
            uint2 hw;
            hw.x = ((uint32_t)__bfloat16_as_ushort(h1) << 16) | __bfloat16_as_ushort(h0);
            hw.y = ((uint32_t)__bfloat16_as_ushort(h3) << 16) | __bfloat16_as_ushort(h2);
            __nv_bfloat16 l0 = __float2bfloat16_rn(v.x - __bfloat162float(h0));
            __nv_bfloat16 l1 = __float2bfloat16_rn(v.y - __bfloat162float(h1));
            __nv_bfloat16 l2 = __float2bfloat16_rn(v.z - __bfloat162float(h2));
            __nv_bfloat16 l3 = __float2bfloat16_rn(v.w - __bfloat162float(h3));
            uint2 lw;
            lw.x = ((uint32_t)__bfloat16_as_ushort(l1) << 16) | __bfloat16_as_ushort(l0);
            lw.y = ((uint32_t)__bfloat16_as_ushort(l3) << 16) | __bfloat16_as_ushort(l2);
            int off = row * AROW + c4 * 4;
            *(uint2*)&sAh[off] = hw;
            *(uint2*)&sAl[off] = lw;
        }
        // ---- stage B tile (64 x 32), already bf16 hi/lo ----
        {
            int row = tid >> 2, c = tid & 3;
            int gcol = chunk * 32 + c * 8;
            size_t src = (size_t)(bn + row) * KPAD + gcol;
            int off = row * AROW + c * 8;
            *(uint4*)&sBh[off] = *(const uint4*)(Bh + src);
            *(uint4*)&sBl[off] = *(const uint4*)(Bl + src);
        }
        __syncthreads();

        // ---- 2 k16 steps ----
#pragma unroll
        for (int ks = 0; ks < 2; ks++) {
            int k0 = ks * 16;
            uint32_t ah[2][4], al[2][4], bh[2][4], bl[2][4];
#pragma unroll
            for (int mi = 0; mi < 2; mi++) {
                int row = wm * 32 + mi * 16 + frag_row;
                uint32_t off = (uint32_t)(row * AROW + k0 + frag_col) * 2;
                ldsm4(ah[mi], baseAh + off);
                ldsm4(al[mi], baseAl + off);
            }
#pragma unroll
            for (int j = 0; j < 2; j++) {
                int row = wn * 32 + j * 16 + frag_row;
                uint32_t off = (uint32_t)(row * AROW + k0 + frag_col) * 2;
                ldsm4(bh[j], baseBh + off);
                ldsm4(bl[j], baseBl + off);
            }
#pragma unroll
            for (int mi = 0; mi < 2; mi++)
#pragma unroll
                for (int nt = 0; nt < 4; nt++) {
                    int j = nt >> 1, sel = nt & 1;
                    mma16816(acc[mi][nt], ah[mi], bh[j][sel], bh[j][sel + 2]);
                    mma16816(acc[mi][nt], ah[mi], bl[j][sel], bl[j][sel + 2]);
                    mma16816(acc[mi][nt], al[mi], bh[j][sel], bh[j][sel + 2]);
                }
        }
        __syncthreads();
    }

    // ---- epilogue: bias + relu, fp32 store ----
    int tm = lane >> 2;
    int tn = (lane & 3) * 2;
#pragma unroll
    for (int mi = 0; mi < 2; mi++)
#pragma unroll
        for (int nt = 0; nt < 4; nt++) {
            int row0 = bm + wm * 32 + mi * 16 + tm;
            int col = bn + wn * 32 + nt * 8 + tn;
            float b0 = bias ? bias[col] : 0.f;
            float b1 = bias ? bias[col + 1] : 0.f;
            float v0 = acc[mi][nt][0] + b0, v1 = acc[mi][nt][1] + b1;
            float v2 = acc[mi][nt][2] + b0, v3 = acc[mi][nt][3] + b1;
            if (do_relu) {
                v0 = fmaxf(v0, 0.f); v1 = fmaxf(v1, 0.f);
                v2 = fmaxf(v2, 0.f); v3 = fmaxf(v3, 0.f);
            }
            *(float2*)(C + (size_t)row0 * D + col) = make_float2(v0, v1);
            *(float2*)(C + (size_t)(row0 + 8) * D + col) = make_float2(v2, v3);
        }
}

// ================= graph kernels =================
__global__ void deg_kernel(const int* __restrict__ dst) {
    int e = blockIdx.x * blockDim.x + threadIdx.x;
    if (e < NEDGES) atomicAdd(&g_degi[dst[e]], 1);
}
__global__ void isq_kernel() {
    int n = blockIdx.x * blockDim.x + threadIdx.x;
    if (n < NNODES) g_isq[n] = rsqrtf((float)g_degi[n] + 1.0f);
}
__global__ void scan_kernel() {
    __shared__ int sh[1024];
    int tid = threadIdx.x;
    int base = tid * 32;
    int local[32];
    int s = 0;
    for (int i = 0; i < 32; i++) { local[i] = s; s += g_degi[base + i]; }
    sh[tid] = s;
    __syncthreads();
    for (int off = 1; off < 1024; off <<= 1) {
        int v = 0;
        if (tid >= off) v = sh[tid - off];
        __syncthreads();
        if (tid >= off) sh[tid] += v;
        __syncthreads();
    }
    int prev = (tid == 0) ? 0 : sh[tid - 1];
    for (int i = 0; i < 32; i++) {
        g_off[base + i] = prev + local[i];
        g_cursor[base + i] = prev + local[i];
    }
    if (tid == 1023) g_off[NNODES] = sh[1023];
}
__global__ void scatter_kernel(const int* __restrict__ src, const int* __restrict__ dst) {
    int e = blockIdx.x * blockDim.x + threadIdx.x;
    if (e < NEDGES) {
        int d = dst[e];
        int p = atomicAdd(&g_cursor[d], 1);
        g_csr[p] = src[e];
    }
}

__global__ void __launch_bounds__(128)
agg_kernel(const float* __restrict__ xw, const float* __restrict__ bias,
           float* __restrict__ out) {
    int n = blockIdx.x;
    int t = threadIdx.x;
    float isqn = g_isq[n];
    const float* selfrow = xw + (size_t)n * D;
    float sc = isqn * isqn;
    float a0 = selfrow[t] * sc;
    float a1 = selfrow[128 + t] * sc;
    float a2 = selfrow[256 + t] * sc;

    int beg = g_off[n], end = g_off[n + 1];
    __shared__ int ssrc[128];
    __shared__ float scoef[128];
    for (int p = beg; p < end; p += 128) {
        int cnt = min(128, end - p);
        __syncthreads();
        if (t < cnt) {
            int s = g_csr[p + t];
            ssrc[t] = s;
            scoef[t] = g_isq[s] * isqn;
        }
        __syncthreads();
        for (int j = 0; j < cnt; j++) {
            int s = ssrc[j];
            float c = scoef[j];
            const float* row = xw + (size_t)s * D;
            a0 += row[t] * c;
            a1 += row[128 + t] * c;
            a2 += row[256 + t] * c;
        }
    }
    out[(size_t)n * D + t]       = fmaxf(a0 + bias[t], 0.f);
    out[(size_t)n * D + 128 + t] = fmaxf(a1 + bias[128 + t], 0.f);
    out[(size_t)n * D + 256 + t] = fmaxf(a2 + bias[256 + t], 0.f);
}

// ================= tail kernels =================
__global__ void sel_kernel(const int* __restrict__ mask) {
    int b = threadIdx.x;
    int c = 0;
    for (int i = 0; i < NGRAPH; i++) {
        if (mask[b * NGRAPH + i]) {
            if (c < 2) g_sel[b * 2 + c] = i;
            c++;
        }
    }
}
__global__ void gather_kernel(const float* __restrict__ X,
                              const float* __restrict__ scale, const float* __restrict__ shift) {
    int b = blockIdx.x >> 1;
    int j = blockIdx.x & 1;
    int node = b * NGRAPH + g_sel[b * 2 + j];
    int t = threadIdx.x;
    g_flat[b * EFEAT + j * D + t] = X[(size_t)node * D + t] * scale[t] + shift[t];
}
__global__ void cat_gemm_kernel(const float* __restrict__ Wc, const float* __restrict__ bc) {
    __shared__ float sh[EFEAT];
    int b = blockIdx.x, t = threadIdx.x;
    sh[t] = g_flat[b * EFEAT + t];
    __syncthreads();
    float s = bc[t];
    for (int k = 0; k < EFEAT; k++) s += sh[k] * Wc[(size_t)k * EFEAT + t];
    g_outc[b * EFEAT + t] = fmaxf(s, 0.f);
}
__global__ void att_kernel(const float* __restrict__ gam, const float* __restrict__ bet) {
    int b = blockIdx.x, t = threadIdx.x;
    float m = g_sum[6 * EFEAT + t] / (float)BATCH;
    float v = g_sq[6 * EFEAT + t] / (float)BATCH - m * m;
    float h = gam[t] * (g_hsent[b * EFEAT + t] - m) * rsqrtf(v + EPS) + bet[t];
    g_att[b * EFEAT + t] = h + g_outc[b * EFEAT + t];
}
__global__ void out_kernel(const float* __restrict__ wout, const float* __restrict__ bout,
                           float* __restrict__ out) {
    int i = threadIdx.x;  // 192
    int b = i / 3, c = i % 3;
    float s = bout[c];
    for (int e = 0; e < EFEAT; e++) s += g_att[b * EFEAT + e] * wout[e * 3 + c];
    out[i] = s;
}

// ============================== launch ==============================
extern "C" void kernel_launch(void* const* d_in, const int* in_sizes, int n_in,
                              void* d_out, int out_size) {
    const float* last_h  = (const float*)d_in[0];
    const float* first_h = (const float*)d_in[1];
    const float* x_nodes = (const float*)d_in[2];
    const int*   eidx    = (const int*)d_in[3];
    const int*   mask    = (const int*)d_in[4];
    const float* w_pre1  = (const float*)d_in[5];
    const float* b_pre1  = (const float*)d_in[6];
    const float* w_pre2  = (const float*)d_in[7];
    const float* b_pre2  = (const float*)d_in[8];
    const float* w_conv  = (const float*)d_in[9];
    const float* b_conv  = (const float*)d_in[10];
    const float* bng_g   = (const float*)d_in[11];
    const float* bng_b   = (const float*)d_in[12];
    const float* w_post1 = (const float*)d_in[13];
    const float* b_post1 = (const float*)d_in[14];
    const float* w_post2 = (const float*)d_in[15];
    const float* b_post2 = (const float*)d_in[16];
    const float* w_cat   = (const float*)d_in[17];
    const float* b_cat   = (const float*)d_in[18];
    const float* bn_g    = (const float*)d_in[19];
    const float* bn_b    = (const float*)d_in[20];
    const float* w_out   = (const float*)d_in[21];
    const float* b_out   = (const float*)d_in[22];
    float* out = (float*)d_out;

    const int* esrc = eidx;
    const int* edst = eidx + NEDGES;

    float *bufA, *bufB, *bufC, *sum, *sq, *outc, *hs, *csc, *csh;
    __nv_bfloat16 *wth, *wtl;
    cudaGetSymbolAddress((void**)&bufA, g_bufA);
    cudaGetSymbolAddress((void**)&bufB, g_bufB);
    cudaGetSymbolAddress((void**)&bufC, g_bufC);
    cudaGetSymbolAddress((void**)&sum, g_sum);
    cudaGetSymbolAddress((void**)&sq, g_sq);
    cudaGetSymbolAddress((void**)&outc, g_outc);
    cudaGetSymbolAddress((void**)&hs, g_hsent);
    cudaGetSymbolAddress((void**)&wth, g_wth);
    cudaGetSymbolAddress((void**)&wtl, g_wtl);
    cudaGetSymbolAddress((void**)&csc, g_cscale);
    cudaGetSymbolAddress((void**)&csh, g_cshift);

    zero_kernel<<<192, 256>>>();

    // sentence branch
    hsent_kernel<<<dim3(BATCH, 4), EFEAT>>>(last_h, first_h);

    // degree / CSR
    deg_kernel<<<NEDGES / 256, 256>>>(edst);
    isq_kernel<<<NNODES / 256, 256>>>();
    scan_kernel<<<1, 1024>>>();
    scatter_kernel<<<NEDGES / 256, 256>>>(esrc, edst);

    // weight prep (transpose + bf16 hi/lo split)
    wprep_kernel<<<(D * 320 + 255) / 256, 256>>>(w_pre1, 300, 320, wth + 0 * D * D, wtl + 0 * D * D);
    wprep_kernel<<<(D * D + 255) / 256, 256>>>(w_pre2, D, D, wth + 1 * D * D, wtl + 1 * D * D);
    wprep_kernel<<<(D * D + 255) / 256, 256>>>(w_conv + 2 * D * D, D, D, wth + 2 * D * D, wtl + 2 * D * D);
    wprep_kernel<<<(D * D + 255) / 256, 256>>>(w_post1, D, D, wth + 3 * D * D, wtl + 3 * D * D);
    wprep_kernel<<<(D * D + 255) / 256, 256>>>(w_post2, D, D, wth + 4 * D * D, wtl + 4 * D * D);

    const float Mf = (float)NNODES;
    dim3 gg(D / 64, NNODES / 128);   // (6, 256)

    // GEMM1: relu(x_nodes @ w_pre1 + b) -> bufA ; stats -> coef0 (bng row 0)
    mma_gemm<<<gg, 256>>>(x_nodes, wth + 0 * D * D, wtl + 0 * D * D,
                          nullptr, nullptr, b_pre1, bufA, 300, 320, 10, 1);
    stats_kernel<<<256, D>>>(bufA, NNODES, D, sum + 0 * EFEAT, sq + 0 * EFEAT);
    bncoef_kernel<<<1, D>>>(sum + 0 * EFEAT, sq + 0 * EFEAT, Mf, bng_g + 0 * D, bng_b + 0 * D,
                            csc + 0 * D, csh + 0 * D);

    // GEMM2: relu(BN0(bufA) @ w_pre2 + b) -> bufB ; stats -> coef1 (bng row 1)
    mma_gemm<<<gg, 256>>>(bufA, wth + 1 * D * D, wtl + 1 * D * D,
                          csc + 0 * D, csh + 0 * D, b_pre2, bufB, D, D, 12, 1);
    stats_kernel<<<256, D>>>(bufB, NNODES, D, sum + 1 * EFEAT, sq + 1 * EFEAT);
    bncoef_kernel<<<1, D>>>(sum + 1 * EFEAT, sq + 1 * EFEAT, Mf, bng_g + 1 * D, bng_b + 1 * D,
                            csc + 1 * D, csh + 1 * D);

    // GEMM3 (only conv i=2 survives): BN1(bufB) @ w_conv[2] -> bufA (no bias/relu)
    mma_gemm<<<gg, 256>>>(bufB, wth + 2 * D * D, wtl + 2 * D * D,
                          csc + 1 * D, csh + 1 * D, nullptr, bufA, D, D, 12, 0);

    // GCN aggregation + bias + relu -> bufC ; stats -> coef2 (bng row 4)
    agg_kernel<<<NNODES, 128>>>(bufA, b_conv + 2 * D, bufC);
    stats_kernel<<<256, D>>>(bufC, NNODES, D, sum + 2 * EFEAT, sq + 2 * EFEAT);
    bncoef_kernel<<<1, D>>>(sum + 2 * EFEAT, sq + 2 * EFEAT, Mf, bng_g + 4 * D, bng_b + 4 * D,
                            csc + 2 * D, csh + 2 * D);

    // GEMM4: relu(BN4(bufC) @ w_post1 + b) -> bufA ; stats -> coef3 (bng row 5)
    mma_gemm<<<gg, 256>>>(bufC, wth + 3 * D * D, wtl + 3 * D * D,
                          csc + 2 * D, csh + 2 * D, b_post1, bufA, D, D, 12, 1);
    stats_kernel<<<256, D>>>(bufA, NNODES, D, sum + 3 * EFEAT, sq + 3 * EFEAT);
    bncoef_kernel<<<1, D>>>(sum + 3 * EFEAT, sq + 3 * EFEAT, Mf, bng_g + 5 * D, bng_b + 5 * D,
                            csc + 3 * D, csh + 3 * D);

    // GEMM5: relu(BN5(bufA) @ w_post2 + b) -> bufB ; stats -> coef4 (bng row 6)
    mma_gemm<<<gg, 256>>>(bufA, wth + 4 * D * D, wtl + 4 * D * D,
                          csc + 3 * D, csh + 3 * D, b_post2, bufB, D, D, 12, 1);
    stats_kernel<<<256, D>>>(bufB, NNODES, D, sum + 4 * EFEAT, sq + 4 * EFEAT);
    bncoef_kernel<<<1, D>>>(sum + 4 * EFEAT, sq + 4 * EFEAT, Mf, bng_g + 6 * D, bng_b + 6 * D,
                            csc + 4 * D, csh + 4 * D);

    // gather masked nodes (BN6 applied inline), cat-MLP, output head
    sel_kernel<<<1, BATCH>>>(mask);
    gather_kernel<<<BATCH * 2, D>>>(bufB, csc + 4 * D, csh + 4 * D);
    cat_gemm_kernel<<<BATCH, EFEAT>>>(w_cat, b_cat);
    stats_kernel<<<1, EFEAT>>>(outc, BATCH, EFEAT, sum + 5 * EFEAT, sq + 5 * EFEAT);
    bn_apply_kernel<<<(BATCH * EFEAT + 255) / 256, 256>>>(outc, outc, BATCH, EFEAT,
                                                          sum + 5 * EFEAT, sq + 5 * EFEAT,
                                                          bn_g + 0 * EFEAT, bn_b + 0 * EFEAT);
    stats_kernel<<<1, EFEAT>>>(hs, BATCH, EFEAT, sum + 6 * EFEAT, sq + 6 * EFEAT);
    att_kernel<<<BATCH, EFEAT>>>(bn_g + 1 * EFEAT, bn_b + 1 * EFEAT);
    out_kernel<<<1, 192>>>(w_out, b_out, out);
}

// round 4
// speedup vs baseline: 2.1265x; 1.0205x over previous
#include <cuda_runtime.h>
#include <cuda_bf16.h>
#include <cstdint>
#include <math.h>

// ---------------- problem constants ----------------
#define NNODES 32768
#define D      384
#define EFEAT  768
#define BATCH  64
#define SEQ    512
#define NGRAPH 512
#define NEDGES 1048576
#define EPS    1e-5f

// ---------------- device scratch (static, no allocs) ----------------
__device__ __nv_bfloat16 g_x0h[(size_t)NNODES * 320];
__device__ __nv_bfloat16 g_x0l[(size_t)NNODES * 320];
__device__ __nv_bfloat16 g_h1[(size_t)NNODES * D];
__device__ __nv_bfloat16 g_l1[(size_t)NNODES * D];
__device__ __nv_bfloat16 g_h2[(size_t)NNODES * D];
__device__ __nv_bfloat16 g_l2[(size_t)NNODES * D];
__device__ float g_xw[(size_t)NNODES * D];
__device__ int   g_degi[NNODES];
__device__ float g_isq[NNODES];
__device__ int   g_off[NNODES + 1];
__device__ int   g_cursor[NNODES];
__device__ int   g_csr[NEDGES];
__device__ float g_sum[7 * EFEAT];
__device__ float g_sq[7 * EFEAT];
__device__ float g_hsent[BATCH * EFEAT];
__device__ float g_flat[BATCH * EFEAT];
__device__ float g_outc[BATCH * EFEAT];
__device__ float g_att[BATCH * EFEAT];
__device__ int   g_sel[BATCH * 2];
// folded transposed weights, bf16 hi/lo: [N=384][KPAD<=384]
__device__ __nv_bfloat16 g_wth[5][D * D];
__device__ __nv_bfloat16 g_wtl[5][D * D];
__device__ float g_biasf[5][D];
// BN affine coefficients per stage
__device__ float g_cscale[5][D];
__device__ float g_cshift[5][D];

// ================= helpers =================
__device__ __forceinline__ uint32_t smem_u32(const void* p) {
    uint32_t a;
    asm("{ .reg .u64 t; cvta.to.shared.u64 t, %1; cvt.u32.u64 %0, t; }" : "=r"(a) : "l"(p));
    return a;
}
__device__ __forceinline__ void ldsm4(uint32_t* r, uint32_t addr) {
    asm volatile("ldmatrix.sync.aligned.m8n8.x4.shared.b16 {%0,%1,%2,%3}, [%4];"
                 : "=r"(r[0]), "=r"(r[1]), "=r"(r[2]), "=r"(r[3]) : "r"(addr));
}
__device__ __forceinline__ void mma16816(float* c, const uint32_t* a, uint32_t b0, uint32_t b1) {
    asm volatile("mma.sync.aligned.m16n8k16.row.col.f32.bf16.bf16.f32 "
                 "{%0,%1,%2,%3},{%4,%5,%6,%7},{%8,%9},{%0,%1,%2,%3};"
                 : "+f"(c[0]), "+f"(c[1]), "+f"(c[2]), "+f"(c[3])
                 : "r"(a[0]), "r"(a[1]), "r"(a[2]), "r"(a[3]), "r"(b0), "r"(b1));
}
#define CP16(d, s) asm volatile("cp.async.cg.shared.global [%0], [%1], 16;" :: "r"(d), "l"(s) : "memory")
#define CP_COMMIT() asm volatile("cp.async.commit_group;" ::: "memory")
#define CP_WAIT1() asm volatile("cp.async.wait_group 1;" ::: "memory")
#define CP_WAIT0() asm volatile("cp.async.wait_group 0;" ::: "memory")

// stage layout (bytes): Ah@0 (10240) Al@10240 Bh@20480 (5120) Bl@25600 ; stride 30720
#define STAGE_STRIDE 30720
#define DYN_SMEM (2 * STAGE_STRIDE + 512)
#define AROW 40  // halves; 80B row pitch

// ================= misc kernels =================
__global__ void zero_kernel() {
    int i = blockIdx.x * blockDim.x + threadIdx.x;
    if (i < NNODES) g_degi[i] = 0;
    if (i < 7 * EFEAT) { g_sum[i] = 0.f; g_sq[i] = 0.f; }
    if (i < BATCH * EFEAT) g_hsent[i] = 0.f;
}

__global__ void hsent_kernel(const float* __restrict__ lh, const float* __restrict__ fh) {
    int b = blockIdx.x, chunk = blockIdx.y, t = threadIdx.x;
    size_t base = ((size_t)b * SEQ + chunk * 128) * EFEAT + t;
    float s = 0.f;
    for (int ss = 0; ss < 128; ss++)
        s += lh[base + (size_t)ss * EFEAT] + fh[base + (size_t)ss * EFEAT];
    atomicAdd(&g_hsent[b * EFEAT + t], s * (0.5f / 512.0f));
}

// x_nodes fp32 [N,300] -> hi/lo bf16 [N,320] zero-padded
__global__ void xprep_kernel(const float* __restrict__ X) {
    size_t idx = (size_t)blockIdx.x * blockDim.x + threadIdx.x;
    if (idx >= (size_t)NNODES * 320) return;
    int row = (int)(idx / 320), k = (int)(idx % 320);
    float v = (k < 300) ? X[(size_t)row * 300 + k] : 0.f;
    __nv_bfloat16 h = __float2bfloat16_rn(v);
    g_x0h[idx] = h;
    g_x0l[idx] = __float2bfloat16_rn(v - __bfloat162float(h));
}

// W[K,384] fp32 (+optional row scale) -> transposed hi/lo [384][KPAD]
__global__ void wfold_kernel(const float* __restrict__ W, int K, int KPAD,
                             const float* __restrict__ scale,
                             __nv_bfloat16* __restrict__ hi, __nv_bfloat16* __restrict__ lo) {
    int idx = blockIdx.x * blockDim.x + threadIdx.x;
    if (idx >= D * KPAD) return;
    int n = idx / KPAD, k = idx % KPAD;
    float v = 0.f;
    if (k < K) {
        v = W[(size_t)k * D + n];
        if (scale) v *= scale[k];
    }
    __nv_bfloat16 h = __float2bfloat16_rn(v);
    hi[idx] = h;
    lo[idx] = __float2bfloat16_rn(v - __bfloat162float(h));
}

// biasf[n] = base[n] + sum_k shift[k]*W[k,n]
__global__ void bfold_kernel(const float* __restrict__ W, int K,
                             const float* __restrict__ shift, const float* __restrict__ base,
                             float* __restrict__ outb) {
    int n = threadIdx.x;
    float s = base ? base[n] : 0.f;
    if (shift)
        for (int k = 0; k < K; k++) s += shift[k] * W[(size_t)k * D + n];
    outb[n] = s;
}

// fp32 column stats (tail use)
__global__ void stats_kernel(const float* __restrict__ X, int M, int N,
                             float* __restrict__ sum, float* __restrict__ sq) {
    int col = threadIdx.x;
    int rows_per = (M + gridDim.x - 1) / gridDim.x;
    int r0 = blockIdx.x * rows_per;
    int r1 = min(M, r0 + rows_per);
    float s = 0.f, q = 0.f;
    for (int r = r0; r < r1; r++) {
        float v = X[(size_t)r * N + col];
        s += v; q += v * v;
    }
    atomicAdd(&sum[col], s);
    atomicAdd(&sq[col], q);
}

// bf16 hi/lo column stats
__global__ void stats_bf16_kernel(const __nv_bfloat16* __restrict__ H,
                                  const __nv_bfloat16* __restrict__ L,
                                  float* __restrict__ sum, float* __restrict__ sq) {
    int col = threadIdx.x;
    int rows_per = (NNODES + gridDim.x - 1) / gridDim.x;
    int r0 = blockIdx.x * rows_per;
    int r1 = min(NNODES, r0 + rows_per);
    float s = 0.f, q = 0.f;
    for (int r = r0; r < r1; r++) {
        size_t i = (size_t)r * D + col;
        float v = __bfloat162float(H[i]) + __bfloat162float(L[i]);
        s += v; q += v * v;
    }
    atomicAdd(&sum[col], s);
    atomicAdd(&sq[col], q);
}

// BN -> per-column affine coefficients
__global__ void bncoef_kernel(const float* __restrict__ sum, const float* __restrict__ sq,
                              float Mf, const float* __restrict__ gam, const float* __restrict__ bet,
                              float* __restrict__ scale, float* __restrict__ shift) {
    int c = threadIdx.x;
    float m = sum[c] / Mf;
    float v = sq[c] / Mf - m * m;
    float s = gam[c] * rsqrtf(v + EPS);
    scale[c] = s;
    shift[c] = bet[c] - m * s;
}

__global__ void bn_apply_kernel(const float* __restrict__ X, float* __restrict__ Y,
                                int M, int N,
                                const float* __restrict__ sum, const float* __restrict__ sq,
                                const float* __restrict__ gam, const float* __restrict__ bet) {
    size_t idx = (size_t)blockIdx.x * blockDim.x + threadIdx.x;
    if (idx >= (size_t)M * N) return;
    int col = (int)(idx % N);
    float invM = 1.0f / (float)M;
    float m = sum[col] * invM;
    float v = sq[col] * invM - m * m;
    Y[idx] = gam[col] * (X[idx] - m) * rsqrtf(v + EPS) + bet[col];
}

// ================= cp.async tile stage =================
__device__ __forceinline__ void issue_tiles(uint32_t sbase, int stage, int tid,
                                            const __nv_bfloat16* Ah, const __nv_bfloat16* Al,
                                            const __nv_bfloat16* Bh, const __nv_bfloat16* Bl,
                                            int bm, int bn, int KPAD, int chunk) {
    uint32_t sb = sbase + stage * STAGE_STRIDE;
#pragma unroll
    for (int it = 0; it < 2; it++) {
        int i = tid + it * 256;
        int row = i >> 2, c16 = i & 3;
        uint32_t d = sb + row * 80 + c16 * 16;
        const __nv_bfloat16* sa = Ah + (size_t)(bm + row) * KPAD + chunk * 32 + c16 * 8;
        const __nv_bfloat16* sl = Al + (size_t)(bm + row) * KPAD + chunk * 32 + c16 * 8;
        CP16(d, sa);
        CP16(d + 10240, sl);
    }
    {
        int row = tid >> 2, c16 = tid & 3;
        uint32_t d = sb + 20480 + row * 80 + c16 * 16;
        const __nv_bfloat16* sbh = Bh + (size_t)(bn + row) * KPAD + chunk * 32 + c16 * 8;
        const __nv_bfloat16* sbl = Bl + (size_t)(bn + row) * KPAD + chunk * 32 + c16 * 8;
        CP16(d, sbh);
        CP16(d + 5120, sbl);
    }
}

// ================= mma.sync bf16x3 GEMM, double-buffered =================
// C = relu?(A @ Wt^T + biasf); A bf16 hi/lo [M][KPAD]; Wt hi/lo [384][KPAD]
// block 128x64, chunk K32, 8 warps (4m x 2n); optional fused column stats
__global__ void __launch_bounds__(256, 2)
mma_gemm(const __nv_bfloat16* __restrict__ Ah, const __nv_bfloat16* __restrict__ Al,
         const __nv_bfloat16* __restrict__ Bh, const __nv_bfloat16* __restrict__ Bl,
         const float* __restrict__ biasf,
         __nv_bfloat16* __restrict__ Ch, __nv_bfloat16* __restrict__ Cl,
         float* __restrict__ Cf,
         int KPAD, int nchunks, int do_relu,
         float* __restrict__ gsum, float* __restrict__ gsq) {
    extern __shared__ char dsm[];
    float* scs = (float*)(dsm + 2 * STAGE_STRIDE);
    float* scq = scs + 64;
    uint32_t sbase = smem_u32(dsm);

    int tid = threadIdx.x;
    int wid = tid >> 5, lane = tid & 31;
    int bm = blockIdx.y * 128, bn = blockIdx.x * 64;
    int wm = wid & 3, wn = wid >> 2;

    if (tid < 64) { scs[tid] = 0.f; scq[tid] = 0.f; }

    float acc[2][4][4];
#pragma unroll
    for (int i = 0; i < 2; i++)
#pragma unroll
        for (int j = 0; j < 4; j++)
#pragma unroll
            for (int k = 0; k < 4; k++) acc[i][j][k] = 0.f;

    int g = lane >> 3, r = lane & 7;
    int frag_row = (g & 1) * 8 + r;
    int frag_col = (g >> 1) * 8;

    issue_tiles(sbase, 0, tid, Ah, Al, Bh, Bl, bm, bn, KPAD, 0);
    CP_COMMIT();

    for (int c = 0; c < nchunks; c++) {
        if (c + 1 < nchunks) {
            issue_tiles(sbase, (c + 1) & 1, tid, Ah, Al, Bh, Bl, bm, bn, KPAD, c + 1);
            CP_COMMIT();
            CP_WAIT1();
        } else {
            CP_WAIT0();
        }
        __syncthreads();

        uint32_t baseAh = sbase + (c & 1) * STAGE_STRIDE;
        uint32_t baseAl = baseAh + 10240;
        uint32_t baseBh = baseAh + 20480;
        uint32_t baseBl = baseAh + 25600;
#pragma unroll
        for (int ks = 0; ks < 2; ks++) {
            int k0 = ks * 16;
            uint32_t ah[2][4], al[2][4], bh[2][4], bl[2][4];
#pragma unroll
            for (int mi = 0; mi < 2; mi++) {
                int row = wm * 32 + mi * 16 + frag_row;
                uint32_t off = (uint32_t)(row * AROW + k0 + frag_col) * 2;
                ldsm4(ah[mi], baseAh + off);
                ldsm4(al[mi], baseAl + off);
            }
#pragma unroll
            for (int j = 0; j < 2; j++) {
                int row = wn * 32 + j * 16 + frag_row;
                uint32_t off = (uint32_t)(row * AROW + k0 + frag_col) * 2;
                ldsm4(bh[j], baseBh + off);
                ldsm4(bl[j], baseBl + off);
            }
#pragma unroll
            for (int mi = 0; mi < 2; mi++)
#pragma unroll
                for (int nt = 0; nt < 4; nt++) {
                    int j = nt >> 1, sel = nt & 1;
                    mma16816(acc[mi][nt], ah[mi], bh[j][sel], bh[j][sel + 2]);
                    mma16816(acc[mi][nt], ah[mi], bl[j][sel], bl[j][sel + 2]);
                    mma16816(acc[mi][nt], al[mi], bh[j][sel], bh[j][sel + 2]);
                }
        }
        __syncthreads();
    }

    // ---- epilogue ----
    int tm = lane >> 2;
    int tn = (lane & 3) * 2;
    bool dosum = (gsum != nullptr);
#pragma unroll
    for (int nt = 0; nt < 4; nt++) {
        float s0 = 0.f, s1 = 0.f, q0 = 0.f, q1 = 0.f;
        int col = bn + wn * 32 + nt * 8 + tn;
        float b0 = biasf[col], b1 = biasf[col + 1];
#pragma unroll
        for (int mi = 0; mi < 2; mi++) {
            int row0 = bm + wm * 32 + mi * 16 + tm;
            float v0 = acc[mi][nt][0] + b0, v1 = acc[mi][nt][1] + b1;
            float v2 = acc[mi][nt][2] + b0, v3 = acc[mi][nt][3] + b1;
            if (do_relu) {
                v0 = fmaxf(v0, 0.f); v1 = fmaxf(v1, 0.f);
                v2 = fmaxf(v2, 0.f); v3 = fmaxf(v3, 0.f);
            }
            if (Cf) {
                *(float2*)(Cf + (size_t)row0 * D + col) = make_float2(v0, v1);
                *(float2*)(Cf + (size_t)(row0 + 8) * D + col) = make_float2(v2, v3);
            } else {
                __nv_bfloat16 h0 = __float2bfloat16_rn(v0), h1 = __float2bfloat16_rn(v1);
                __nv_bfloat16 h2 = __float2bfloat16_rn(v2), h3 = __float2bfloat16_rn(v3);
                uint32_t ph01 = ((uint32_t)__bfloat16_as_ushort(h1) << 16) | __bfloat16_as_ushort(h0);
                uint32_t ph23 = ((uint32_t)__bfloat16_as_ushort(h3) << 16) | __bfloat16_as_ushort(h2);
                __nv_bfloat16 l0 = __float2bfloat16_rn(v0 - __bfloat162float(h0));
                __nv_bfloat16 l1 = __float2bfloat16_rn(v1 - __bfloat162float(h1));
                __nv_bfloat16 l2 = __float2bfloat16_rn(v2 - __bfloat162float(h2));
                __nv_bfloat16 l3 = __float2bfloat16_rn(v3 - __bfloat162float(h3));
                uint32_t pl01 = ((uint32_t)__bfloat16_as_ushort(l1) << 16) | __bfloat16_as_ushort(l0);
                uint32_t pl23 = ((uint32_t)__bfloat16_as_ushort(l3) << 16) | __bfloat16_as_ushort(l2);
                *(uint32_t*)&Ch[(size_t)row0 * D + col] = ph01;
                *(uint32_t*)&Ch[(size_t)(row0 + 8) * D + col] = ph23;
                *(uint32_t*)&Cl[(size_t)row0 * D + col] = pl01;
                *(uint32_t*)&Cl[(size_t)(row0 + 8) * D + col] = pl23;
                // stats use the quantized value actually consumed downstream
                v0 = __bfloat162float(h0) + __bfloat162float(l0);
                v1 = __bfloat162float(h1) + __bfloat162float(l1);
                v2 = __bfloat162float(h2) + __bfloat162float(l2);
                v3 = __bfloat162float(h3) + __bfloat162float(l3);
            }
            s0 += v0 + v2; s1 += v1 + v3;
            q0 += v0 * v0 + v2 * v2; q1 += v1 * v1 + v3 * v3;
        }
        if (dosum) {
#pragma unroll
            for (int o = 4; o < 32; o <<= 1) {
                s0 += __shfl_xor_sync(0xffffffffu, s0, o);
                s1 += __shfl_xor_sync(0xffffffffu, s1, o);
                q0 += __shfl_xor_sync(0xffffffffu, q0, o);
                q1 += __shfl_xor_sync(0xffffffffu, q1, o);
            }
            if (lane < 4) {
                int cl = wn * 32 + nt * 8 + lane * 2;
                atomicAdd(&scs[cl], s0); atomicAdd(&scs[cl + 1], s1);
                atomicAdd(&scq[cl], q0); atomicAdd(&scq[cl + 1], q1);
            }
        }
    }
    if (dosum) {
        __syncthreads();
        if (tid < 64) {
            atomicAdd(&gsum[bn + tid], scs[tid]);
            atomicAdd(&gsq[bn + tid], scq[tid]);
        }
    }
}

// ================= graph kernels =================
__global__ void deg_kernel(const int* __restrict__ dst) {
    int e = blockIdx.x * blockDim.x + threadIdx.x;
    if (e < NEDGES) atomicAdd(&g_degi[dst[e]], 1);
}
__global__ void isq_kernel() {
    int n = blockIdx.x * blockDim.x + threadIdx.x;
    if (n < NNODES) g_isq[n] = rsqrtf((float)g_degi[n] + 1.0f);
}
__global__ void scan_kernel() {
    __shared__ int sh[1024];
    int tid = threadIdx.x;
    int base = tid * 32;
    int local[32];
    int s = 0;
    for (int i = 0; i < 32; i++) { local[i] = s; s += g_degi[base + i]; }
    sh[tid] = s;
    __syncthreads();
    for (int off = 1; off < 1024; off <<= 1) {
        int v = 0;
        if (tid >= off) v = sh[tid - off];
        __syncthreads();
        if (tid >= off) sh[tid] += v;
        __syncthreads();
    }
    int prev = (tid == 0) ? 0 : sh[tid - 1];
    for (int i = 0; i < 32; i++) {
        g_off[base + i] = prev + local[i];
        g_cursor[base + i] = prev + local[i];
    }
    if (tid == 1023) g_off[NNODES] = sh[1023];
}
__global__ void scatter_kernel(const int* __restrict__ src, const int* __restrict__ dst) {
    int e = blockIdx.x * blockDim.x + threadIdx.x;
    if (e < NEDGES) {
        int d = dst[e];
        int p = atomicAdd(&g_cursor[d], 1);
        g_csr[p] = src[e];
    }
}

// GCN aggregation: fp32 in, bias+relu, bf16 hi/lo out
__global__ void __launch_bounds__(128)
agg_kernel(const float* __restrict__ xw, const float* __restrict__ bias,
           __nv_bfloat16* __restrict__ oh, __nv_bfloat16* __restrict__ ol) {
    int n = blockIdx.x;
    int t = threadIdx.x;
    float isqn = g_isq[n];
    const float* selfrow = xw + (size_t)n * D;
    float sc = isqn * isqn;
    float a0 = selfrow[t] * sc;
    float a1 = selfrow[128 + t] * sc;
    float a2 = selfrow[256 + t] * sc;

    int beg = g_off[n], end = g_off[n + 1];
    __shared__ int ssrc[128];
    __shared__ float scoef[128];
    for (int p = beg; p < end; p += 128) {
        int cnt = min(128, end - p);
        __syncthreads();
        if (t < cnt) {
            int s = g_csr[p + t];
            ssrc[t] = s;
            scoef[t] = g_isq[s] * isqn;
        }
        __syncthreads();
        for (int j = 0; j < cnt; j++) {
            int s = ssrc[j];
            float c = scoef[j];
            const float* row = xw + (size_t)s * D;
            a0 += row[t] * c;
            a1 += row[128 + t] * c;
            a2 += row[256 + t] * c;
        }
    }
    float v[3] = { fmaxf(a0 + bias[t], 0.f),
                   fmaxf(a1 + bias[128 + t], 0.f),
                   fmaxf(a2 + bias[256 + t], 0.f) };
#pragma unroll
    for (int i = 0; i < 3; i++) {
        size_t idx = (size_t)n * D + i * 128 + t;
        __nv_bfloat16 h = __float2bfloat16_rn(v[i]);
        oh[idx] = h;
        ol[idx] = __float2bfloat16_rn(v[i] - __bfloat162float(h));
    }
}

// ================= tail kernels =================
__global__ void sel_kernel(const int* __restrict__ mask) {
    int b = threadIdx.x;
    int c = 0;
    for (int i = 0; i < NGRAPH; i++) {
        if (mask[b * NGRAPH + i]) {
            if (c < 2) g_sel[b * 2 + c] = i;
            c++;
        }
    }
}
__global__ void gather_kernel(const __nv_bfloat16* __restrict__ H, const __nv_bfloat16* __restrict__ L,
                              const float* __restrict__ scale, const float* __restrict__ shift) {
    int b = blockIdx.x >> 1;
    int j = blockIdx.x & 1;
    int node = b * NGRAPH + g_sel[b * 2 + j];
    int t = threadIdx.x;
    size_t idx = (size_t)node * D + t;
    float v = __bfloat162float(H[idx]) + __bfloat162float(L[idx]);
    g_flat[b * EFEAT + j * D + t] = v * scale[t] + shift[t];
}
__global__ void cat_gemm_kernel(const float* __restrict__ Wc, const float* __restrict__ bc) {
    __shared__ float sh[EFEAT];
    int b = blockIdx.x, t = threadIdx.x;
    sh[t] = g_flat[b * EFEAT + t];
    __syncthreads();
    float s = bc[t];
    for (int k = 0; k < EFEAT; k++) s += sh[k] * Wc[(size_t)k * EFEAT + t];
    g_outc[b * EFEAT + t] = fmaxf(s, 0.f);
}
__global__ void att_kernel(const float* __restrict__ gam, const float* __restrict__ bet) {
    int b = blockIdx.x, t = threadIdx.x;
    float m = g_sum[6 * EFEAT + t] / (float)BATCH;
    float v = g_sq[6 * EFEAT + t] / (float)BATCH - m * m;
    float h = gam[t] * (g_hsent[b * EFEAT + t] - m) * rsqrtf(v + EPS) + bet[t];
    g_att[b * EFEAT + t] = h + g_outc[b * EFEAT + t];
}
__global__ void out_kernel(const float* __restrict__ wout, const float* __restrict__ bout,
                           float* __restrict__ out) {
    int i = threadIdx.x;  // 192
    int b = i / 3, c = i % 3;
    float s = bout[c];
    for (int e = 0; e < EFEAT; e++) s += g_att[b * EFEAT + e] * wout[e * 3 + c];
    out[i] = s;
}

// ============================== launch ==============================
extern "C" void kernel_launch(void* const* d_in, const int* in_sizes, int n_in,
                              void* d_out, int out_size) {
    const float* last_h  = (const float*)d_in[0];
    const float* first_h = (const float*)d_in[1];
    const float* x_nodes = (const float*)d_in[2];
    const int*   eidx    = (const int*)d_in[3];
    const int*   mask    = (const int*)d_in[4];
    const float* w_pre1  = (const float*)d_in[5];
    const float* b_pre1  = (const float*)d_in[6];
    const float* w_pre2  = (const float*)d_in[7];
    const float* b_pre2  = (const float*)d_in[8];
    const float* w_conv  = (const float*)d_in[9];
    const float* b_conv  = (const float*)d_in[10];
    const float* bng_g   = (const float*)d_in[11];
    const float* bng_b   = (const float*)d_in[12];
    const float* w_post1 = (const float*)d_in[13];
    const float* b_post1 = (const float*)d_in[14];
    const float* w_post2 = (const float*)d_in[15];
    const float* b_post2 = (const float*)d_in[16];
    const float* w_cat   = (const float*)d_in[17];
    const float* b_cat   = (const float*)d_in[18];
    const float* bn_g    = (const float*)d_in[19];
    const float* bn_b    = (const float*)d_in[20];
    const float* w_out   = (const float*)d_in[21];
    const float* b_out   = (const float*)d_in[22];
    float* out = (float*)d_out;

    const int* esrc = eidx;
    const int* edst = eidx + NEDGES;

    float *sum, *sq, *outc, *hs, *csc, *csh, *bfp, *xw;
    __nv_bfloat16 *x0h, *x0l, *h1, *l1, *h2, *l2, *wth, *wtl;
    cudaGetSymbolAddress((void**)&sum, g_sum);
    cudaGetSymbolAddress((void**)&sq, g_sq);
    cudaGetSymbolAddress((void**)&outc, g_outc);
    cudaGetSymbolAddress((void**)&hs, g_hsent);
    cudaGetSymbolAddress((void**)&csc, g_cscale);
    cudaGetSymbolAddress((void**)&csh, g_cshift);
    cudaGetSymbolAddress((void**)&bfp, g_biasf);
    cudaGetSymbolAddress((void**)&xw, g_xw);
    cudaGetSymbolAddress((void**)&x0h, g_x0h);
    cudaGetSymbolAddress((void**)&x0l, g_x0l);
    cudaGetSymbolAddress((void**)&h1, g_h1);
    cudaGetSymbolAddress((void**)&l1, g_l1);
    cudaGetSymbolAddress((void**)&h2, g_h2);
    cudaGetSymbolAddress((void**)&l2, g_l2);
    cudaGetSymbolAddress((void**)&wth, g_wth);
    cudaGetSymbolAddress((void**)&wtl, g_wtl);

    cudaFuncSetAttribute(mma_gemm, cudaFuncAttributeMaxDynamicSharedMemorySize, DYN_SMEM);

    const float Mf = (float)NNODES;
    dim3 gg(D / 64, NNODES / 128);   // (6, 256)

    zero_kernel<<<192, 256>>>();
    hsent_kernel<<<dim3(BATCH, 4), EFEAT>>>(last_h, first_h);

    // degree / CSR
    deg_kernel<<<NEDGES / 256, 256>>>(edst);
    isq_kernel<<<NNODES / 256, 256>>>();
    scan_kernel<<<1, 1024>>>();
    scatter_kernel<<<NEDGES / 256, 256>>>(esrc, edst);

    // input prep + stage-0 weights (no BN fold)
    xprep_kernel<<<(NNODES * 320 + 255) / 256, 256>>>(x_nodes);
    wfold_kernel<<<(D * 320 + 255) / 256, 256>>>(w_pre1, 300, 320, nullptr,
                                                 wth + 0 * D * D, wtl + 0 * D * D);
    bfold_kernel<<<1, D>>>(w_pre1, 300, nullptr, b_pre1, bfp + 0 * D);

    // GEMM1 -> h1/l1, fused stats slot 0 (bng row 0)
    mma_gemm<<<gg, 256, DYN_SMEM>>>(x0h, x0l, wth + 0 * D * D, wtl + 0 * D * D, bfp + 0 * D,
                                    h1, l1, nullptr, 320, 10, 1, sum + 0 * EFEAT, sq + 0 * EFEAT);
    bncoef_kernel<<<1, D>>>(sum + 0 * EFEAT, sq + 0 * EFEAT, Mf, bng_g + 0 * D, bng_b + 0 * D,
                            csc + 0 * D, csh + 0 * D);
    wfold_kernel<<<(D * D + 255) / 256, 256>>>(w_pre2, D, D, csc + 0 * D,
                                               wth + 1 * D * D, wtl + 1 * D * D);
    bfold_kernel<<<1, D>>>(w_pre2, D, csh + 0 * D, b_pre2, bfp + 1 * D);

    // GEMM2 -> h2/l2, stats slot 1 (bng row 1)
    mma_gemm<<<gg, 256, DYN_SMEM>>>(h1, l1, wth + 1 * D * D, wtl + 1 * D * D, bfp + 1 * D,
                                    h2, l2, nullptr, D, 12, 1, sum + 1 * EFEAT, sq + 1 * EFEAT);
    bncoef_kernel<<<1, D>>>(sum + 1 * EFEAT, sq + 1 * EFEAT, Mf, bng_g + 1 * D, bng_b + 1 * D,
                            csc + 1 * D, csh + 1 * D);
    wfold_kernel<<<(D * D + 255) / 256, 256>>>(w_conv + 2 * D * D, D, D, csc + 1 * D,
                                               wth + 2 * D * D, wtl + 2 * D * D);
    bfold_kernel<<<1, D>>>(w_conv + 2 * D * D, D, csh + 1 * D, nullptr, bfp + 2 * D);

    // GEMM3 (only conv i=2 survives): -> fp32 xw, no relu, no stats
    mma_gemm<<<gg, 256, DYN_SMEM>>>(h2, l2, wth + 2 * D * D, wtl + 2 * D * D, bfp + 2 * D,
                                    nullptr, nullptr, xw, D, 12, 0, nullptr, nullptr);

    // GCN aggregation + bias + relu -> h1/l1 ; stats slot 2 (bng row 4)
    agg_kernel<<<NNODES, 128>>>(xw, b_conv + 2 * D, h1, l1);
    stats_bf16_kernel<<<256, D>>>(h1, l1, sum + 2 * EFEAT, sq + 2 * EFEAT);
    bncoef_kernel<<<1, D>>>(sum + 2 * EFEAT, sq + 2 * EFEAT, Mf, bng_g + 4 * D, bng_b + 4 * D,
                            csc + 2 * D, csh + 2 * D);
    wfold_kernel<<<(D * D + 255) / 256, 256>>>(w_post1, D, D, csc + 2 * D,
                                               wth + 3 * D * D, wtl + 3 * D * D);
    bfold_kernel<<<1, D>>>(w_post1, D, csh + 2 * D, b_post1, bfp + 3 * D);

    // GEMM4 -> h2/l2, stats slot 3 (bng row 5)
    mma_gemm<<<gg, 256, DYN_SMEM>>>(h1, l1, wth + 3 * D * D, wtl + 3 * D * D, bfp + 3 * D,
                                    h2, l2, nullptr, D, 12, 1, sum + 3 * EFEAT, sq + 3 * EFEAT);
    bncoef_kernel<<<1, D>>>(sum + 3 * EFEAT, sq + 3 * EFEAT, Mf, bng_g + 5 * D, bng_b + 5 * D,
                            csc + 3 * D, csh + 3 * D);
    wfold_kernel<<<(D * D + 255) / 256, 256>>>(w_post2, D, D, csc + 3 * D,
                                               wth + 4 * D * D, wtl + 4 * D * D);
    bfold_kernel<<<1, D>>>(w_post2, D, csh + 3 * D, b_post2, bfp + 4 * D);

    // GEMM5 -> h1/l1, stats slot 4 (bng row 6)
    mma_gemm<<<gg, 256, DYN_SMEM>>>(h2, l2, wth + 4 * D * D, wtl + 4 * D * D, bfp + 4 * D,
                                    h1, l1, nullptr, D, 12, 1, sum + 4 * EFEAT, sq + 4 * EFEAT);
    bncoef_kernel<<<1, D>>>(sum + 4 * EFEAT, sq + 4 * EFEAT, Mf, bng_g + 6 * D, bng_b + 6 * D,
                            csc + 4 * D, csh + 4 * D);

    // gather masked nodes (BN row 6 affine inline), cat-MLP, output head
    sel_kernel<<<1, BATCH>>>(mask);
    gather_kernel<<<BATCH * 2, D>>>(h1, l1, csc + 4 * D, csh + 4 * D);
    cat_gemm_kernel<<<BATCH, EFEAT>>>(w_cat, b_cat);
    stats_kernel<<<1, EFEAT>>>(outc, BATCH, EFEAT, sum + 5 * EFEAT, sq + 5 * EFEAT);
    bn_apply_kernel<<<(BATCH * EFEAT + 255) / 256, 256>>>(outc, outc, BATCH, EFEAT,
                                                          sum + 5 * EFEAT, sq + 5 * EFEAT,
                                                          bn_g + 0 * EFEAT, bn_b + 0 * EFEAT);
    stats_kernel<<<1, EFEAT>>>(hs, BATCH, EFEAT, sum + 6 * EFEAT, sq + 6 * EFEAT);
    att_kernel<<<BATCH, EFEAT>>>(bn_g + 1 * EFEAT, bn_b + 1 * EFEAT);
    out_kernel<<<1, 192>>>(w_out, b_out, out);
}

// round 6
// speedup vs baseline: 2.7539x; 1.2950x over previous
#include <cuda_runtime.h>
#include <cuda_fp16.h>
#include <cstdint>
#include <math.h>

// ---------------- problem constants ----------------
#define NNODES 32768
#define D      384
#define EFEAT  768
#define BATCH  64
#define SEQ    512
#define NGRAPH 512
#define NEDGES 1048576
#define EPS    1e-5f

// ---------------- device scratch (static, no allocs) ----------------
__device__ __half g_x0h[(size_t)NNODES * 320];
__device__ __half g_x0l[(size_t)NNODES * 320];
__device__ __half g_h1[(size_t)NNODES * D];
__device__ __half g_l1[(size_t)NNODES * D];
__device__ __half g_h2[(size_t)NNODES * D];
__device__ __half g_l2[(size_t)NNODES * D];
__device__ __half g_xw[(size_t)NNODES * D];
__device__ int    g_degi[NNODES];
__device__ float  g_isq[NNODES];
__device__ int    g_off[NNODES + 1];
__device__ int    g_cursor[NNODES];
__device__ int    g_csr[NEDGES];
__device__ float  g_sum[7 * EFEAT];
__device__ float  g_sq[7 * EFEAT];
__device__ float  g_hsent[BATCH * EFEAT];
__device__ float  g_flat[BATCH * EFEAT];
__device__ float  g_outc[BATCH * EFEAT];
__device__ int    g_sel[BATCH * 2];
// folded transposed weights fp16 hi/lo: [N=384][KPAD<=384]
__device__ __half g_wth[5][D * D];
__device__ __half g_wtl[5][D * D];
__device__ float  g_biasf[5][D];

// ================= helpers =================
__device__ __forceinline__ uint32_t smem_u32(const void* p) {
    uint32_t a;
    asm("{ .reg .u64 t; cvta.to.shared.u64 t, %1; cvt.u32.u64 %0, t; }" : "=r"(a) : "l"(p));
    return a;
}
__device__ __forceinline__ void ldsm4(uint32_t* r, uint32_t addr) {
    asm volatile("ldmatrix.sync.aligned.m8n8.x4.shared.b16 {%0,%1,%2,%3}, [%4];"
                 : "=r"(r[0]), "=r"(r[1]), "=r"(r[2]), "=r"(r[3]) : "r"(addr));
}
__device__ __forceinline__ void mma16816f(float* c, const uint32_t* a, uint32_t b0, uint32_t b1) {
    asm volatile("mma.sync.aligned.m16n8k16.row.col.f32.f16.f16.f32 "
                 "{%0,%1,%2,%3},{%4,%5,%6,%7},{%8,%9},{%0,%1,%2,%3};"
                 : "+f"(c[0]), "+f"(c[1]), "+f"(c[2]), "+f"(c[3])
                 : "r"(a[0]), "r"(a[1]), "r"(a[2]), "r"(a[3]), "r"(b0), "r"(b1));
}
#define CP16(d, s) asm volatile("cp.async.cg.shared.global [%0], [%1], 16;" :: "r"(d), "l"(s) : "memory")
#define CP_COMMIT() asm volatile("cp.async.commit_group;" ::: "memory")
#define CP_WAIT1() asm volatile("cp.async.wait_group 1;" ::: "memory")
#define CP_WAIT0() asm volatile("cp.async.wait_group 0;" ::: "memory")

// stage layout (bytes): Ah@0 (10240) Al@10240 Bh@20480 (5120) Bl@25600 (5120); stride 30720
#define STAGE_STRIDE 30720
#define DYN_SMEM (2 * STAGE_STRIDE + 512)
#define AROW 40  // halves; 80B row pitch

__device__ __forceinline__ float bn_scale_of(const float* sum, const float* sq, int k,
                                             float Mf, const float* gam) {
    float m = sum[k] / Mf;
    float v = sq[k] / Mf - m * m;
    return gam[k] * rsqrtf(v + EPS);
}
__device__ __forceinline__ float bn_shift_of(const float* sum, const float* sq, int k,
                                             float Mf, const float* gam, const float* bet) {
    float m = sum[k] / Mf;
    float v = sq[k] / Mf - m * m;
    float s = gam[k] * rsqrtf(v + EPS);
    return bet[k] - m * s;
}

// ================= misc kernels =================
__global__ void zero_kernel() {
    int i = blockIdx.x * blockDim.x + threadIdx.x;
    if (i < NNODES) g_degi[i] = 0;
    if (i < 7 * EFEAT) { g_sum[i] = 0.f; g_sq[i] = 0.f; }
    if (i < BATCH * EFEAT) g_hsent[i] = 0.f;
}

__global__ void hsent_kernel(const float* __restrict__ lh, const float* __restrict__ fh) {
    int b = blockIdx.x, chunk = blockIdx.y, t = threadIdx.x;
    size_t base = ((size_t)b * SEQ + chunk * 128) * EFEAT + t;
    float s = 0.f;
    for (int ss = 0; ss < 128; ss++)
        s += lh[base + (size_t)ss * EFEAT] + fh[base + (size_t)ss * EFEAT];
    atomicAdd(&g_hsent[b * EFEAT + t], s * (0.5f / 512.0f));
}

// x_nodes fp32 [N,300] -> fp16 hi/lo [N,320] zero-padded
__global__ void xprep_kernel(const float* __restrict__ X) {
    size_t idx = (size_t)blockIdx.x * blockDim.x + threadIdx.x;
    if (idx >= (size_t)NNODES * 320) return;
    int row = (int)(idx / 320), k = (int)(idx % 320);
    float v = (k < 300) ? X[(size_t)row * 300 + k] : 0.f;
    __half h = __float2half_rn(v);
    g_x0h[idx] = h;
    g_x0l[idx] = __float2half_rn(v - __half2float(h));
}

// W[K,384] fp32 (+inline BN scale from stats) -> transposed fp16 hi/lo [384][KPAD]
__global__ void wfold_kernel(const float* __restrict__ W, int K, int KPAD,
                             const float* __restrict__ sum, const float* __restrict__ sq,
                             const float* __restrict__ gam, float Mf,
                             __half* __restrict__ oh, __half* __restrict__ ol) {
    int idx = blockIdx.x * blockDim.x + threadIdx.x;
    if (idx >= D * KPAD) return;
    int n = idx / KPAD, k = idx % KPAD;
    float v = 0.f;
    if (k < K) {
        v = W[(size_t)k * D + n];
        if (sum) v *= bn_scale_of(sum, sq, k, Mf, gam);
    }
    __half h = __float2half_rn(v);
    oh[idx] = h;
    ol[idx] = __float2half_rn(v - __half2float(h));
}

// biasf[n] = base[n] + sum_k shift_k * W[k,n]   (grid D blocks, 128 threads)
__global__ void bfold_kernel(const float* __restrict__ W, int K,
                             const float* __restrict__ sum, const float* __restrict__ sq,
                             const float* __restrict__ gam, const float* __restrict__ bet,
                             float Mf, const float* __restrict__ base,
                             float* __restrict__ outb) {
    int n = blockIdx.x, t = threadIdx.x;
    float p = 0.f;
    for (int k = t; k < K; k += 128)
        p += bn_shift_of(sum, sq, k, Mf, gam, bet) * W[(size_t)k * D + n];
    __shared__ float red[128];
    red[t] = p;
    __syncthreads();
    for (int o = 64; o > 0; o >>= 1) {
        if (t < o) red[t] += red[t + o];
        __syncthreads();
    }
    if (t == 0) outb[n] = (base ? base[n] : 0.f) + red[0];
}

// fp32 column stats
__global__ void stats_kernel(const float* __restrict__ X, int M, int N,
                             float* __restrict__ sum, float* __restrict__ sq) {
    int col = threadIdx.x;
    int rows_per = (M + gridDim.x - 1) / gridDim.x;
    int r0 = blockIdx.x * rows_per;
    int r1 = min(M, r0 + rows_per);
    float s = 0.f, q = 0.f;
    for (int r = r0; r < r1; r++) {
        float v = X[(size_t)r * N + col];
        s += v; q += v * v;
    }
    atomicAdd(&sum[col], s);
    atomicAdd(&sq[col], q);
}

// fp16 hi/lo column stats
__global__ void stats_f16_kernel(const __half* __restrict__ H, const __half* __restrict__ L,
                                 float* __restrict__ sum, float* __restrict__ sq) {
    int col = threadIdx.x;
    int rows_per = (NNODES + gridDim.x - 1) / gridDim.x;
    int r0 = blockIdx.x * rows_per;
    int r1 = min(NNODES, r0 + rows_per);
    float s = 0.f, q = 0.f;
    for (int r = r0; r < r1; r++) {
        size_t i = (size_t)r * D + col;
        float v = __half2float(H[i]) + __half2float(L[i]);
        s += v; q += v * v;
    }
    atomicAdd(&sum[col], s);
    atomicAdd(&sq[col], q);
}

// ================= cp.async tile stage =================
__device__ __forceinline__ void issue_tiles(uint32_t sbase, int stage, int tid,
                                            const __half* Ah, const __half* Al,
                                            const __half* Bh, const __half* Bl,
                                            int bm, int bn, int KPAD, int chunk) {
    uint32_t sb = sbase + stage * STAGE_STRIDE;
#pragma unroll
    for (int it = 0; it < 2; it++) {
        int i = tid + it * 256;
        int row = i >> 2, c16 = i & 3;
        uint32_t d = sb + row * 80 + c16 * 16;
        const __half* sa = Ah + (size_t)(bm + row) * KPAD + chunk * 32 + c16 * 8;
        const __half* sl = Al + (size_t)(bm + row) * KPAD + chunk * 32 + c16 * 8;
        CP16(d, sa);
        CP16(d + 10240, sl);
    }
    {
        int row = tid >> 2, c16 = tid & 3;
        uint32_t d = sb + 20480 + row * 80 + c16 * 16;
        const __half* sbh = Bh + (size_t)(bn + row) * KPAD + chunk * 32 + c16 * 8;
        const __half* sbl = Bl + (size_t)(bn + row) * KPAD + chunk * 32 + c16 * 8;
        CP16(d, sbh);
        CP16(d + 5120, sbl);
    }
}

// ================= mma.sync fp16 3-pass GEMM, double-buffered =================
// C = relu?((Ah+Al) @ (Bh+Bl)^T + biasf), dropping AlBl (error ~2^-22)
// block 128x64, chunk K32, 8 warps (4m x 2n); optional fused column stats.
// Output: Cl!=null -> hi/lo fp16 pair; Cl==null -> single fp16 in Ch.
__global__ void __launch_bounds__(256, 2)
mma_gemm(const __half* __restrict__ Ah, const __half* __restrict__ Al,
         const __half* __restrict__ Bh, const __half* __restrict__ Bl,
         const float* __restrict__ biasf,
         __half* __restrict__ Ch, __half* __restrict__ Cl,
         int KPAD, int nchunks, int do_relu,
         float* __restrict__ gsum, float* __restrict__ gsq) {
    extern __shared__ char dsm[];
    float* scs = (float*)(dsm + 2 * STAGE_STRIDE);
    float* scq = scs + 64;
    uint32_t sbase = smem_u32(dsm);

    int tid = threadIdx.x;
    int wid = tid >> 5, lane = tid & 31;
    int bm = blockIdx.y * 128, bn = blockIdx.x * 64;
    int wm = wid & 3, wn = wid >> 2;

    if (tid < 64) { scs[tid] = 0.f; scq[tid] = 0.f; }

    float acc[2][4][4];
#pragma unroll
    for (int i = 0; i < 2; i++)
#pragma unroll
        for (int j = 0; j < 4; j++)
#pragma unroll
            for (int k = 0; k < 4; k++) acc[i][j][k] = 0.f;

    int g = lane >> 3, r = lane & 7;
    int frag_row = (g & 1) * 8 + r;
    int frag_col = (g >> 1) * 8;

    issue_tiles(sbase, 0, tid, Ah, Al, Bh, Bl, bm, bn, KPAD, 0);
    CP_COMMIT();

    for (int c = 0; c < nchunks; c++) {
        if (c + 1 < nchunks) {
            issue_tiles(sbase, (c + 1) & 1, tid, Ah, Al, Bh, Bl, bm, bn, KPAD, c + 1);
            CP_COMMIT();
            CP_WAIT1();
        } else {
            CP_WAIT0();
        }
        __syncthreads();

        uint32_t baseAh = sbase + (c & 1) * STAGE_STRIDE;
        uint32_t baseAl = baseAh + 10240;
        uint32_t baseBh = baseAh + 20480;
        uint32_t baseBl = baseAh + 25600;
#pragma unroll
        for (int ks = 0; ks < 2; ks++) {
            int k0 = ks * 16;
            uint32_t ah[2][4], al[2][4], bh[2][4], bl[2][4];
#pragma unroll
            for (int mi = 0; mi < 2; mi++) {
                int row = wm * 32 + mi * 16 + frag_row;
                uint32_t off = (uint32_t)(row * AROW + k0 + frag_col) * 2;
                ldsm4(ah[mi], baseAh + off);
                ldsm4(al[mi], baseAl + off);
            }
#pragma unroll
            for (int j = 0; j < 2; j++) {
                int row = wn * 32 + j * 16 + frag_row;
                uint32_t off = (uint32_t)(row * AROW + k0 + frag_col) * 2;
                ldsm4(bh[j], baseBh + off);
                ldsm4(bl[j], baseBl + off);
            }
#pragma unroll
            for (int mi = 0; mi < 2; mi++)
#pragma unroll
                for (int nt = 0; nt < 4; nt++) {
                    int j = nt >> 1, sel = nt & 1;
                    mma16816f(acc[mi][nt], ah[mi], bh[j][sel], bh[j][sel + 2]);
                    mma16816f(acc[mi][nt], ah[mi], bl[j][sel], bl[j][sel + 2]);
                    mma16816f(acc[mi][nt], al[mi], bh[j][sel], bh[j][sel + 2]);
                }
        }
        __syncthreads();
    }

    // ---- epilogue ----
    int tm = lane >> 2;
    int tn = (lane & 3) * 2;
    bool dosum = (gsum != nullptr);
#pragma unroll
    for (int nt = 0; nt < 4; nt++) {
        float s0 = 0.f, s1 = 0.f, q0 = 0.f, q1 = 0.f;
        int col = bn + wn * 32 + nt * 8 + tn;
        float b0 = biasf[col], b1 = biasf[col + 1];
#pragma unroll
        for (int mi = 0; mi < 2; mi++) {
            int row0 = bm + wm * 32 + mi * 16 + tm;
            float v0 = acc[mi][nt][0] + b0, v1 = acc[mi][nt][1] + b1;
            float v2 = acc[mi][nt][2] + b0, v3 = acc[mi][nt][3] + b1;
            if (do_relu) {
                v0 = fmaxf(v0, 0.f); v1 = fmaxf(v1, 0.f);
                v2 = fmaxf(v2, 0.f); v3 = fmaxf(v3, 0.f);
            }
            __half h0 = __float2half_rn(v0), h1 = __float2half_rn(v1);
            __half h2 = __float2half_rn(v2), h3 = __float2half_rn(v3);
            uint32_t ph01 = ((uint32_t)__half_as_ushort(h1) << 16) | __half_as_ushort(h0);
            uint32_t ph23 = ((uint32_t)__half_as_ushort(h3) << 16) | __half_as_ushort(h2);
            *(uint32_t*)&Ch[(size_t)row0 * D + col] = ph01;
            *(uint32_t*)&Ch[(size_t)(row0 + 8) * D + col] = ph23;
            if (Cl) {
                __half l0 = __float2half_rn(v0 - __half2float(h0));
                __half l1 = __float2half_rn(v1 - __half2float(h1));
                __half l2 = __float2half_rn(v2 - __half2float(h2));
                __half l3 = __float2half_rn(v3 - __half2float(h3));
                uint32_t pl01 = ((uint32_t)__half_as_ushort(l1) << 16) | __half_as_ushort(l0);
                uint32_t pl23 = ((uint32_t)__half_as_ushort(l3) << 16) | __half_as_ushort(l2);
                *(uint32_t*)&Cl[(size_t)row0 * D + col] = pl01;
                *(uint32_t*)&Cl[(size_t)(row0 + 8) * D + col] = pl23;
            }
            s0 += v0 + v2; s1 += v1 + v3;
            q0 += v0 * v0 + v2 * v2; q1 += v1 * v1 + v3 * v3;
        }
        if (dosum) {
#pragma unroll
            for (int o = 4; o < 32; o <<= 1) {
                s0 += __shfl_xor_sync(0xffffffffu, s0, o);
                s1 += __shfl_xor_sync(0xffffffffu, s1, o);
                q0 += __shfl_xor_sync(0xffffffffu, q0, o);
                q1 += __shfl_xor_sync(0xffffffffu, q1, o);
            }
            if (lane < 4) {
                int cl = wn * 32 + nt * 8 + lane * 2;
                atomicAdd(&scs[cl], s0); atomicAdd(&scs[cl + 1], s1);
                atomicAdd(&scq[cl], q0); atomicAdd(&scq[cl + 1], q1);
            }
        }
    }
    if (dosum) {
        __syncthreads();
        if (tid < 64) {
            atomicAdd(&gsum[bn + tid], scs[tid]);
            atomicAdd(&gsq[bn + tid], scq[tid]);
        }
    }
}

// ================= graph kernels =================
__global__ void deg_kernel(const int* __restrict__ dst) {
    int e = blockIdx.x * blockDim.x + threadIdx.x;
    if (e < NEDGES) atomicAdd(&g_degi[dst[e]], 1);
}
__global__ void isq_kernel() {
    int n = blockIdx.x * blockDim.x + threadIdx.x;
    if (n < NNODES) g_isq[n] = rsqrtf((float)g_degi[n] + 1.0f);
}
__global__ void scan_kernel() {
    __shared__ int sh[1024];
    int tid = threadIdx.x;
    int base = tid * 32;
    int local[32];
    int s = 0;
    for (int i = 0; i < 32; i++) { local[i] = s; s += g_degi[base + i]; }
    sh[tid] = s;
    __syncthreads();
    for (int off = 1; off < 1024; off <<= 1) {
        int v = 0;
        if (tid >= off) v = sh[tid - off];
        __syncthreads();
        if (tid >= off) sh[tid] += v;
        __syncthreads();
    }
    int prev = (tid == 0) ? 0 : sh[tid - 1];
    for (int i = 0; i < 32; i++) {
        g_off[base + i] = prev + local[i];
        g_cursor[base + i] = prev + local[i];
    }
    if (tid == 1023) g_off[NNODES] = sh[1023];
}
__global__ void scatter_kernel(const int* __restrict__ src, const int* __restrict__ dst) {
    int e = blockIdx.x * blockDim.x + threadIdx.x;
    if (e < NEDGES) {
        int d = dst[e];
        int p = atomicAdd(&g_cursor[d], 1);
        g_csr[p] = src[e];
    }
}

// GCN aggregation: fp16 in (half traffic), fp32 accumulate, bias+relu, fp16 hi/lo out
__global__ void __launch_bounds__(128)
agg_kernel(const __half* __restrict__ xw, const float* __restrict__ bias,
           __half* __restrict__ oh, __half* __restrict__ ol) {
    int n = blockIdx.x;
    int t = threadIdx.x;
    float isqn = g_isq[n];
    const __half* selfrow = xw + (size_t)n * D;
    float sc = isqn * isqn;
    float a0 = __half2float(selfrow[t]) * sc;
    float a1 = __half2float(selfrow[128 + t]) * sc;
    float a2 = __half2float(selfrow[256 + t]) * sc;

    int beg = g_off[n], end = g_off[n + 1];
    __shared__ int ssrc[128];
    __shared__ float scoef[128];
    for (int p = beg; p < end; p += 128) {
        int cnt = min(128, end - p);
        __syncthreads();
        if (t < cnt) {
            int s = g_csr[p + t];
            ssrc[t] = s;
            scoef[t] = g_isq[s] * isqn;
        }
        __syncthreads();
        for (int j = 0; j < cnt; j++) {
            int s = ssrc[j];
            float c = scoef[j];
            const __half* row = xw + (size_t)s * D;
            a0 += __half2float(row[t]) * c;
            a1 += __half2float(row[128 + t]) * c;
            a2 += __half2float(row[256 + t]) * c;
        }
    }
    float v[3] = { fmaxf(a0 + bias[t], 0.f),
                   fmaxf(a1 + bias[128 + t], 0.f),
                   fmaxf(a2 + bias[256 + t], 0.f) };
#pragma unroll
    for (int i = 0; i < 3; i++) {
        size_t idx = (size_t)n * D + i * 128 + t;
        __half h = __float2half_rn(v[i]);
        oh[idx] = h;
        ol[idx] = __float2half_rn(v[i] - __half2float(h));
    }
}

// ================= tail kernels =================
__global__ void sel_kernel(const int* __restrict__ mask) {
    int b = threadIdx.x;
    int c = 0;
    for (int i = 0; i < NGRAPH; i++) {
        if (mask[b * NGRAPH + i]) {
            if (c < 2) g_sel[b * 2 + c] = i;
            c++;
        }
    }
}
// gather 2 masked nodes per sample, BN (bng row 6 via stats slot 4) inline
__global__ void gather_kernel(const __half* __restrict__ H, const __half* __restrict__ L,
                              const float* __restrict__ sum, const float* __restrict__ sq,
                              const float* __restrict__ gam, const float* __restrict__ bet) {
    int b = blockIdx.x >> 1;
    int j = blockIdx.x & 1;
    int node = b * NGRAPH + g_sel[b * 2 + j];
    int t = threadIdx.x;
    size_t idx = (size_t)node * D + t;
    float v = __half2float(H[idx]) + __half2float(L[idx]);
    float s = bn_scale_of(sum, sq, t, (float)NNODES, gam);
    float sh = bn_shift_of(sum, sq, t, (float)NNODES, gam, bet);
    g_flat[b * EFEAT + j * D + t] = v * s + sh;
}
// outc = relu(flat @ w_cat + b_cat), fused column stats (slot 5)
__global__ void cat_gemm_kernel(const float* __restrict__ Wc, const float* __restrict__ bc,
                                float* __restrict__ sum, float* __restrict__ sq) {
    __shared__ float sh[EFEAT];
    int b = blockIdx.x, t = threadIdx.x;
    sh[t] = g_flat[b * EFEAT + t];
    __syncthreads();
    float s = bc[t];
    for (int k = 0; k < EFEAT; k++) s += sh[k] * Wc[(size_t)k * EFEAT + t];
    s = fmaxf(s, 0.f);
    g_outc[b * EFEAT + t] = s;
    atomicAdd(&sum[t], s);
    atomicAdd(&sq[t], s * s);
}
// att = BN1(hsent) + BN0(outc); out = att @ w_out + b_out   (one block per sample)
__global__ void attout_kernel(const float* __restrict__ sum5, const float* __restrict__ sq5,
                              const float* __restrict__ sum6, const float* __restrict__ sq6,
                              const float* __restrict__ bg, const float* __restrict__ bb,
                              const float* __restrict__ wout, const float* __restrict__ bout,
                              float* __restrict__ out) {
    __shared__ float satt[EFEAT];
    int b = blockIdx.x, t = threadIdx.x;
    float Bf = (float)BATCH;
    float m0 = sum5[t] / Bf, v0 = sq5[t] / Bf - m0 * m0;
    float oc = bg[t] * (g_outc[b * EFEAT + t] - m0) * rsqrtf(v0 + EPS) + bb[t];
    float m1 = sum6[t] / Bf, v1 = sq6[t] / Bf - m1 * m1;
    float hh = bg[EFEAT + t] * (g_hsent[b * EFEAT + t] - m1) * rsqrtf(v1 + EPS) + bb[EFEAT + t];
    satt[t] = hh + oc;
    __syncthreads();
    int w = t >> 5, lane = t & 31;
    if (w < 3) {
        int c = w;
        float p = 0.f;
        for (int e = lane; e < EFEAT; e += 32) p += satt[e] * wout[e * 3 + c];
#pragma unroll
        for (int o = 16; o > 0; o >>= 1) p += __shfl_xor_sync(0xffffffffu, p, o);
        if (lane == 0) out[b * 3 + c] = p + bout[c];
    }
}

// ============================== launch ==============================
extern "C" void kernel_launch(void* const* d_in, const int* in_sizes, int n_in,
                              void* d_out, int out_size) {
    const float* last_h  = (const float*)d_in[0];
    const float* first_h = (const float*)d_in[1];
    const float* x_nodes = (const float*)d_in[2];
    const int*   eidx    = (const int*)d_in[3];
    const int*   mask    = (const int*)d_in[4];
    const float* w_pre1  = (const float*)d_in[5];
    const float* b_pre1  = (const float*)d_in[6];
    const float* w_pre2  = (const float*)d_in[7];
    const float* b_pre2  = (const float*)d_in[8];
    const float* w_conv  = (const float*)d_in[9];
    const float* b_conv  = (const float*)d_in[10];
    const float* bng_g   = (const float*)d_in[11];
    const float* bng_b   = (const float*)d_in[12];
    const float* w_post1 = (const float*)d_in[13];
    const float* b_post1 = (const float*)d_in[14];
    const float* w_post2 = (const float*)d_in[15];
    const float* b_post2 = (const float*)d_in[16];
    const float* w_cat   = (const float*)d_in[17];
    const float* b_cat   = (const float*)d_in[18];
    const float* bn_g    = (const float*)d_in[19];
    const float* bn_b    = (const float*)d_in[20];
    const float* w_out   = (const float*)d_in[21];
    const float* b_out   = (const float*)d_in[22];
    float* out = (float*)d_out;

    const int* esrc = eidx;
    const int* edst = eidx + NEDGES;

    float *sum, *sq, *hs, *bfp;
    __half *x0h, *x0l, *h1, *l1, *h2, *l2, *wth, *wtl, *xw;
    cudaGetSymbolAddress((void**)&sum, g_sum);
    cudaGetSymbolAddress((void**)&sq, g_sq);
    cudaGetSymbolAddress((void**)&hs, g_hsent);
    cudaGetSymbolAddress((void**)&bfp, g_biasf);
    cudaGetSymbolAddress((void**)&xw, g_xw);
    cudaGetSymbolAddress((void**)&x0h, g_x0h);
    cudaGetSymbolAddress((void**)&x0l, g_x0l);
    cudaGetSymbolAddress((void**)&h1, g_h1);
    cudaGetSymbolAddress((void**)&l1, g_l1);
    cudaGetSymbolAddress((void**)&h2, g_h2);
    cudaGetSymbolAddress((void**)&l2, g_l2);
    cudaGetSymbolAddress((void**)&wth, g_wth);
    cudaGetSymbolAddress((void**)&wtl, g_wtl);

    cudaFuncSetAttribute(mma_gemm, cudaFuncAttributeMaxDynamicSharedMemorySize, DYN_SMEM);

    const float Mf = (float)NNODES;
    dim3 gg(D / 64, NNODES / 128);   // (6, 256)

    cudaStream_t s1, s2;
    cudaEvent_t e0, e1, e2;
    cudaStreamCreateWithFlags(&s1, cudaStreamNonBlocking);
    cudaStreamCreateWithFlags(&s2, cudaStreamNonBlocking);
    cudaEventCreateWithFlags(&e0, cudaEventDisableTiming);
    cudaEventCreateWithFlags(&e1, cudaEventDisableTiming);
    cudaEventCreateWithFlags(&e2, cudaEventDisableTiming);

    zero_kernel<<<192, 256>>>();
    cudaEventRecord(e0, 0);
    cudaStreamWaitEvent(s1, e0, 0);
    cudaStreamWaitEvent(s2, e0, 0);

    // side stream 1: sentence branch + its stats (slot 6)
    hsent_kernel<<<dim3(BATCH, 4), EFEAT, 0, s1>>>(last_h, first_h);
    stats_kernel<<<1, EFEAT, 0, s1>>>(hs, BATCH, EFEAT, sum + 6 * EFEAT, sq + 6 * EFEAT);
    cudaEventRecord(e1, s1);

    // side stream 2: degree / CSR / mask selection
    deg_kernel<<<NEDGES / 256, 256, 0, s2>>>(edst);
    isq_kernel<<<NNODES / 256, 256, 0, s2>>>();
    scan_kernel<<<1, 1024, 0, s2>>>();
    scatter_kernel<<<NEDGES / 256, 256, 0, s2>>>(esrc, edst);
    sel_kernel<<<1, BATCH, 0, s2>>>(mask);
    cudaEventRecord(e2, s2);

    // main: input prep + stage-0 weights (no BN fold; bias passed through)
    xprep_kernel<<<(NNODES * 320 + 255) / 256, 256>>>(x_nodes);
    wfold_kernel<<<(D * 320 + 255) / 256, 256>>>(w_pre1, 300, 320, nullptr, nullptr, nullptr, Mf,
                                                 wth + 0 * D * D, wtl + 0 * D * D);

    // GEMM1 -> h1/l1, fused stats slot 0 (bng row 0)
    mma_gemm<<<gg, 256, DYN_SMEM>>>(x0h, x0l, wth + 0 * D * D, wtl + 0 * D * D, b_pre1,
                                    h1, l1, 320, 10, 1, sum + 0 * EFEAT, sq + 0 * EFEAT);
    wfold_kernel<<<(D * D + 255) / 256, 256>>>(w_pre2, D, D, sum + 0 * EFEAT, sq + 0 * EFEAT,
                                               bng_g + 0 * D, Mf, wth + 1 * D * D, wtl + 1 * D * D);
    bfold_kernel<<<D, 128>>>(w_pre2, D, sum + 0 * EFEAT, sq + 0 * EFEAT,
                             bng_g + 0 * D, bng_b + 0 * D, Mf, b_pre2, bfp + 1 * D);

    // GEMM2 -> h2/l2, stats slot 1 (bng row 1)
    mma_gemm<<<gg, 256, DYN_SMEM>>>(h1, l1, wth + 1 * D * D, wtl + 1 * D * D, bfp + 1 * D,
                                    h2, l2, D, 12, 1, sum + 1 * EFEAT, sq + 1 * EFEAT);
    wfold_kernel<<<(D * D + 255) / 256, 256>>>(w_conv + 2 * D * D, D, D, sum + 1 * EFEAT, sq + 1 * EFEAT,
                                               bng_g + 1 * D, Mf, wth + 2 * D * D, wtl + 2 * D * D);
    bfold_kernel<<<D, 128>>>(w_conv + 2 * D * D, D, sum + 1 * EFEAT, sq + 1 * EFEAT,
                             bng_g + 1 * D, bng_b + 1 * D, Mf, nullptr, bfp + 2 * D);

    // GEMM3 (only conv i=2 survives) -> single fp16 xw, no relu, no stats
    mma_gemm<<<gg, 256, DYN_SMEM>>>(h2, l2, wth + 2 * D * D, wtl + 2 * D * D, bfp + 2 * D,
                                    xw, nullptr, D, 12, 0, nullptr, nullptr);

    // join CSR stream, aggregate, stats slot 2 (bng row 4)
    cudaStreamWaitEvent(0, e2, 0);
    agg_kernel<<<NNODES, 128>>>(xw, b_conv + 2 * D, h1, l1);
    stats_f16_kernel<<<256, D>>>(h1, l1, sum + 2 * EFEAT, sq + 2 * EFEAT);
    wfold_kernel<<<(D * D + 255) / 256, 256>>>(w_post1, D, D, sum + 2 * EFEAT, sq + 2 * EFEAT,
                                               bng_g + 4 * D, Mf, wth + 3 * D * D, wtl + 3 * D * D);
    bfold_kernel<<<D, 128>>>(w_post1, D, sum + 2 * EFEAT, sq + 2 * EFEAT,
                             bng_g + 4 * D, bng_b + 4 * D, Mf, b_post1, bfp + 3 * D);

    // GEMM4 -> h2/l2, stats slot 3 (bng row 5)
    mma_gemm<<<gg, 256, DYN_SMEM>>>(h1, l1, wth + 3 * D * D, wtl + 3 * D * D, bfp + 3 * D,
                                    h2, l2, D, 12, 1, sum + 3 * EFEAT, sq + 3 * EFEAT);
    wfold_kernel<<<(D * D + 255) / 256, 256>>>(w_post2, D, D, sum + 3 * EFEAT, sq + 3 * EFEAT,
                                               bng_g + 5 * D, Mf, wth + 4 * D * D, wtl + 4 * D * D);
    bfold_kernel<<<D, 128>>>(w_post2, D, sum + 3 * EFEAT, sq + 3 * EFEAT,
                             bng_g + 5 * D, bng_b + 5 * D, Mf, b_post2, bfp + 4 * D);

    // GEMM5 -> h1/l1, stats slot 4 (bng row 6)
    mma_gemm<<<gg, 256, DYN_SMEM>>>(h2, l2, wth + 4 * D * D, wtl + 4 * D * D, bfp + 4 * D,
                                    h1, l1, D, 12, 1, sum + 4 * EFEAT, sq + 4 * EFEAT);

    // tail: gather (BN row 6 inline) -> cat-MLP (+stats slot 5) -> att+out
    gather_kernel<<<BATCH * 2, D>>>(h1, l1, sum + 4 * EFEAT, sq + 4 * EFEAT,
                                    bng_g + 6 * D, bng_b + 6 * D);
    cat_gemm_kernel<<<BATCH, EFEAT>>>(w_cat, b_cat, sum + 5 * EFEAT, sq + 5 * EFEAT);
    cudaStreamWaitEvent(0, e1, 0);
    attout_kernel<<<BATCH, EFEAT>>>(sum + 5 * EFEAT, sq + 5 * EFEAT,
                                    sum + 6 * EFEAT, sq + 6 * EFEAT,
                                    bn_g, bn_b, w_out, b_out, out);

    cudaEventDestroy(e0);
    cudaEventDestroy(e1);
    cudaEventDestroy(e2);
    cudaStreamDestroy(s1);
    cudaStreamDestroy(s2);
}

// round 7
// speedup vs baseline: 2.8540x; 1.0363x over previous
#include <cuda_runtime.h>
#include <cuda_fp16.h>
#include <cstdint>
#include <math.h>

// ---------------- problem constants ----------------
#define NNODES 32768
#define D      384
#define EFEAT  768
#define BATCH  64
#define SEQ    512
#define NGRAPH 512
#define NEDGES 1048576
#define EPS    1e-5f

// ---------------- device scratch (static, no allocs) ----------------
__device__ __half g_x0h[(size_t)NNODES * 320];
__device__ __half g_x0l[(size_t)NNODES * 320];
__device__ __half g_h1[(size_t)NNODES * D];
__device__ __half g_l1[(size_t)NNODES * D];
__device__ __half g_h2[(size_t)NNODES * D];
__device__ __half g_l2[(size_t)NNODES * D];
__device__ __half g_xw[(size_t)NNODES * D];
__device__ int    g_degi[NNODES];
__device__ float  g_isq[NNODES];
__device__ int    g_off[NNODES + 1];
__device__ int    g_cursor[NNODES];
__device__ int    g_csr[NEDGES];
__device__ float  g_sum[7 * EFEAT];
__device__ float  g_sq[7 * EFEAT];
__device__ float  g_hsent[BATCH * EFEAT];
__device__ float  g_flat[BATCH * EFEAT];
__device__ float  g_outc[BATCH * EFEAT];
__device__ int    g_sel[BATCH * 2];
// folded transposed weights fp16 hi/lo: [N=384][KPAD<=384]
__device__ __half g_wth[5][D * D];
__device__ __half g_wtl[5][D * D];
__device__ float  g_biasf[5][D];

// ================= helpers =================
__device__ __forceinline__ uint32_t smem_u32(const void* p) {
    uint32_t a;
    asm("{ .reg .u64 t; cvta.to.shared.u64 t, %1; cvt.u32.u64 %0, t; }" : "=r"(a) : "l"(p));
    return a;
}
__device__ __forceinline__ void ldsm4(uint32_t* r, uint32_t addr) {
    asm volatile("ldmatrix.sync.aligned.m8n8.x4.shared.b16 {%0,%1,%2,%3}, [%4];"
                 : "=r"(r[0]), "=r"(r[1]), "=r"(r[2]), "=r"(r[3]) : "r"(addr));
}
__device__ __forceinline__ void mma16816f(float* c, const uint32_t* a, uint32_t b0, uint32_t b1) {
    asm volatile("mma.sync.aligned.m16n8k16.row.col.f32.f16.f16.f32 "
                 "{%0,%1,%2,%3},{%4,%5,%6,%7},{%8,%9},{%0,%1,%2,%3};"
                 : "+f"(c[0]), "+f"(c[1]), "+f"(c[2]), "+f"(c[3])
                 : "r"(a[0]), "r"(a[1]), "r"(a[2]), "r"(a[3]), "r"(b0), "r"(b1));
}
#define CP16(d, s) asm volatile("cp.async.cg.shared.global [%0], [%1], 16;" :: "r"(d), "l"(s) : "memory")
#define CP_COMMIT() asm volatile("cp.async.commit_group;" ::: "memory")
#define CP_WAIT1() asm volatile("cp.async.wait_group 1;" ::: "memory")
#define CP_WAIT0() asm volatile("cp.async.wait_group 0;" ::: "memory")

// stage layout (bytes): Ah@0 (10240) Al@10240 Bh@20480 (5120) Bl@25600 (5120); stride 30720
#define STAGE_STRIDE 30720
#define DYN_SMEM (2 * STAGE_STRIDE + 512)
#define AROW 40  // halves; 80B row pitch

__device__ __forceinline__ float bn_scale_of(const float* sum, const float* sq, int k,
                                             float Mf, const float* gam) {
    float m = sum[k] / Mf;
    float v = sq[k] / Mf - m * m;
    return gam[k] * rsqrtf(v + EPS);
}
__device__ __forceinline__ float bn_shift_of(const float* sum, const float* sq, int k,
                                             float Mf, const float* gam, const float* bet) {
    float m = sum[k] / Mf;
    float v = sq[k] / Mf - m * m;
    float s = gam[k] * rsqrtf(v + EPS);
    return bet[k] - m * s;
}

// ================= misc kernels =================
__global__ void zero_kernel() {
    int i = blockIdx.x * blockDim.x + threadIdx.x;
    if (i < NNODES) g_degi[i] = 0;
    if (i < 7 * EFEAT) { g_sum[i] = 0.f; g_sq[i] = 0.f; }
    if (i < BATCH * EFEAT) g_hsent[i] = 0.f;
}

__global__ void hsent_kernel(const float* __restrict__ lh, const float* __restrict__ fh) {
    int b = blockIdx.x, chunk = blockIdx.y, t = threadIdx.x;
    size_t base = ((size_t)b * SEQ + chunk * 128) * EFEAT + t;
    float s = 0.f;
    for (int ss = 0; ss < 128; ss++)
        s += lh[base + (size_t)ss * EFEAT] + fh[base + (size_t)ss * EFEAT];
    atomicAdd(&g_hsent[b * EFEAT + t], s * (0.5f / 512.0f));
}

// x_nodes fp32 [N,300] -> fp16 hi/lo [N,320] zero-padded
__global__ void xprep_kernel(const float* __restrict__ X) {
    size_t idx = (size_t)blockIdx.x * blockDim.x + threadIdx.x;
    if (idx >= (size_t)NNODES * 320) return;
    int row = (int)(idx / 320), k = (int)(idx % 320);
    float v = (k < 300) ? X[(size_t)row * 300 + k] : 0.f;
    __half h = __float2half_rn(v);
    g_x0h[idx] = h;
    g_x0l[idx] = __float2half_rn(v - __half2float(h));
}

// stage-0 weight prep (no BN fold): W[K,384] -> transposed fp16 hi/lo [384][KPAD]
__global__ void wprep0_kernel(const float* __restrict__ W, int K, int KPAD,
                              __half* __restrict__ oh, __half* __restrict__ ol) {
    int idx = blockIdx.x * blockDim.x + threadIdx.x;
    if (idx >= D * KPAD) return;
    int n = idx / KPAD, k = idx % KPAD;
    float v = (k < K) ? W[(size_t)k * D + n] : 0.f;
    __half h = __float2half_rn(v);
    oh[idx] = h;
    ol[idx] = __float2half_rn(v - __half2float(h));
}

// fused BN-fold: folded weight row (hi/lo) + folded bias, one block per output col n.
// K = D = 384, 128 threads x 3 k's each.
__global__ void fold_kernel(const float* __restrict__ W,
                            const float* __restrict__ sum, const float* __restrict__ sq,
                            const float* __restrict__ gam, const float* __restrict__ bet,
                            float Mf, const float* __restrict__ base,
                            __half* __restrict__ oh, __half* __restrict__ ol,
                            float* __restrict__ outb) {
    int n = blockIdx.x, t = threadIdx.x;
    float acc = 0.f;
#pragma unroll
    for (int i = 0; i < 3; i++) {
        int k = t + i * 128;
        float w = W[(size_t)k * D + n];
        float m = sum[k] / Mf;
        float var = sq[k] / Mf - m * m;
        float sc = gam[k] * rsqrtf(var + EPS);
        float sh = bet[k] - m * sc;
        float v = w * sc;
        __half h = __float2half_rn(v);
        oh[(size_t)n * D + k] = h;
        ol[(size_t)n * D + k] = __float2half_rn(v - __half2float(h));
        acc += sh * w;
    }
    __shared__ float red[128];
    red[t] = acc;
    __syncthreads();
    for (int o = 64; o > 0; o >>= 1) {
        if (t < o) red[t] += red[t + o];
        __syncthreads();
    }
    if (t == 0) outb[n] = (base ? base[n] : 0.f) + red[0];
}

// fp32 column stats
__global__ void stats_kernel(const float* __restrict__ X, int M, int N,
                             float* __restrict__ sum, float* __restrict__ sq) {
    int col = threadIdx.x;
    int rows_per = (M + gridDim.x - 1) / gridDim.x;
    int r0 = blockIdx.x * rows_per;
    int r1 = min(M, r0 + rows_per);
    float s = 0.f, q = 0.f;
    for (int r = r0; r < r1; r++) {
        float v = X[(size_t)r * N + col];
        s += v; q += v * v;
    }
    atomicAdd(&sum[col], s);
    atomicAdd(&sq[col], q);
}

// fp16 hi/lo column stats
__global__ void stats_f16_kernel(const __half* __restrict__ H, const __half* __restrict__ L,
                                 float* __restrict__ sum, float* __restrict__ sq) {
    int col = threadIdx.x;
    int rows_per = (NNODES + gridDim.x - 1) / gridDim.x;
    int r0 = blockIdx.x * rows_per;
    int r1 = min(NNODES, r0 + rows_per);
    float s = 0.f, q = 0.f;
    for (int r = r0; r < r1; r++) {
        size_t i = (size_t)r * D + col;
        float v = __half2float(H[i]) + __half2float(L[i]);
        s += v; q += v * v;
    }
    atomicAdd(&sum[col], s);
    atomicAdd(&sq[col], q);
}

// ================= cp.async tile stage =================
__device__ __forceinline__ void issue_tiles(uint32_t sbase, int stage, int tid,
                                            const __half* Ah, const __half* Al,
                                            const __half* Bh, const __half* Bl,
                                            int bm, int bn, int KPAD, int chunk) {
    uint32_t sb = sbase + stage * STAGE_STRIDE;
#pragma unroll
    for (int it = 0; it < 2; it++) {
        int i = tid + it * 256;
        int row = i >> 2, c16 = i & 3;
        uint32_t d = sb + row * 80 + c16 * 16;
        const __half* sa = Ah + (size_t)(bm + row) * KPAD + chunk * 32 + c16 * 8;
        const __half* sl = Al + (size_t)(bm + row) * KPAD + chunk * 32 + c16 * 8;
        CP16(d, sa);
        CP16(d + 10240, sl);
    }
    {
        int row = tid >> 2, c16 = tid & 3;
        uint32_t d = sb + 20480 + row * 80 + c16 * 16;
        const __half* sbh = Bh + (size_t)(bn + row) * KPAD + chunk * 32 + c16 * 8;
        const __half* sbl = Bl + (size_t)(bn + row) * KPAD + chunk * 32 + c16 * 8;
        CP16(d, sbh);
        CP16(d + 5120, sbl);
    }
}

// ================= mma.sync fp16 GEMM, double-buffered =================
// three_pass=1: C = (Ah+Al)@(Bh+Bl)^T dropping AlBl (err ~2^-22)
// three_pass=0: C = Ah@(Bh+Bl)^T (err ~2^-11; use only where output is fp16-rounded anyway)
// block 128x64, chunk K32, 8 warps (4m x 2n); optional fused column stats.
// Output: Cl!=null -> hi/lo fp16 pair; Cl==null -> single fp16 in Ch.
__global__ void __launch_bounds__(256, 2)
mma_gemm(const __half* __restrict__ Ah, const __half* __restrict__ Al,
         const __half* __restrict__ Bh, const __half* __restrict__ Bl,
         const float* __restrict__ biasf,
         __half* __restrict__ Ch, __half* __restrict__ Cl,
         int KPAD, int nchunks, int do_relu, int three_pass,
         float* __restrict__ gsum, float* __restrict__ gsq) {
    extern __shared__ char dsm[];
    float* scs = (float*)(dsm + 2 * STAGE_STRIDE);
    float* scq = scs + 64;
    uint32_t sbase = smem_u32(dsm);

    int tid = threadIdx.x;
    int wid = tid >> 5, lane = tid & 31;
    int bm = blockIdx.y * 128, bn = blockIdx.x * 64;
    int wm = wid & 3, wn = wid >> 2;

    if (tid < 64) { scs[tid] = 0.f; scq[tid] = 0.f; }

    float acc[2][4][4];
#pragma unroll
    for (int i = 0; i < 2; i++)
#pragma unroll
        for (int j = 0; j < 4; j++)
#pragma unroll
            for (int k = 0; k < 4; k++) acc[i][j][k] = 0.f;

    int g = lane >> 3, r = lane & 7;
    int frag_row = (g & 1) * 8 + r;
    int frag_col = (g >> 1) * 8;

    issue_tiles(sbase, 0, tid, Ah, Al, Bh, Bl, bm, bn, KPAD, 0);
    CP_COMMIT();

    for (int c = 0; c < nchunks; c++) {
        if (c + 1 < nchunks) {
            issue_tiles(sbase, (c + 1) & 1, tid, Ah, Al, Bh, Bl, bm, bn, KPAD, c + 1);
            CP_COMMIT();
            CP_WAIT1();
        } else {
            CP_WAIT0();
        }
        __syncthreads();

        uint32_t baseAh = sbase + (c & 1) * STAGE_STRIDE;
        uint32_t baseAl = baseAh + 10240;
        uint32_t baseBh = baseAh + 20480;
        uint32_t baseBl = baseAh + 25600;
#pragma unroll
        for (int ks = 0; ks < 2; ks++) {
            int k0 = ks * 16;
            uint32_t ah[2][4], al[2][4], bh[2][4], bl[2][4];
#pragma unroll
            for (int mi = 0; mi < 2; mi++) {
                int row = wm * 32 + mi * 16 + frag_row;
                uint32_t off = (uint32_t)(row * AROW + k0 + frag_col) * 2;
                ldsm4(ah[mi], baseAh + off);
                if (three_pass) ldsm4(al[mi], baseAl + off);
            }
#pragma unroll
            for (int j = 0; j < 2; j++) {
                int row = wn * 32 + j * 16 + frag_row;
                uint32_t off = (uint32_t)(row * AROW + k0 + frag_col) * 2;
                ldsm4(bh[j], baseBh + off);
                ldsm4(bl[j], baseBl + off);
            }
#pragma unroll
            for (int mi = 0; mi < 2; mi++)
#pragma unroll
                for (int nt = 0; nt < 4; nt++) {
                    int j = nt >> 1, sel = nt & 1;
                    mma16816f(acc[mi][nt], ah[mi], bh[j][sel], bh[j][sel + 2]);
                    mma16816f(acc[mi][nt], ah[mi], bl[j][sel], bl[j][sel + 2]);
                    if (three_pass)
                        mma16816f(acc[mi][nt], al[mi], bh[j][sel], bh[j][sel + 2]);
                }
        }
        __syncthreads();
    }

    // ---- epilogue ----
    int tm = lane >> 2;
    int tn = (lane & 3) * 2;
    bool dosum = (gsum != nullptr);
#pragma unroll
    for (int nt = 0; nt < 4; nt++) {
        float s0 = 0.f, s1 = 0.f, q0 = 0.f, q1 = 0.f;
        int col = bn + wn * 32 + nt * 8 + tn;
        float b0 = biasf[col], b1 = biasf[col + 1];
#pragma unroll
        for (int mi = 0; mi < 2; mi++) {
            int row0 = bm + wm * 32 + mi * 16 + tm;
            float v0 = acc[mi][nt][0] + b0, v1 = acc[mi][nt][1] + b1;
            float v2 = acc[mi][nt][2] + b0, v3 = acc[mi][nt][3] + b1;
            if (do_relu) {
                v0 = fmaxf(v0, 0.f); v1 = fmaxf(v1, 0.f);
                v2 = fmaxf(v2, 0.f); v3 = fmaxf(v3, 0.f);
            }
            __half h0 = __float2half_rn(v0), h1 = __float2half_rn(v1);
            __half h2 = __float2half_rn(v2), h3 = __float2half_rn(v3);
            uint32_t ph01 = ((uint32_t)__half_as_ushort(h1) << 16) | __half_as_ushort(h0);
            uint32_t ph23 = ((uint32_t)__half_as_ushort(h3) << 16) | __half_as_ushort(h2);
            *(uint32_t*)&Ch[(size_t)row0 * D + col] = ph01;
            *(uint32_t*)&Ch[(size_t)(row0 + 8) * D + col] = ph23;
            if (Cl) {
                __half l0 = __float2half_rn(v0 - __half2float(h0));
                __half l1 = __float2half_rn(v1 - __half2float(h1));
                __half l2 = __float2half_rn(v2 - __half2float(h2));
                __half l3 = __float2half_rn(v3 - __half2float(h3));
                uint32_t pl01 = ((uint32_t)__half_as_ushort(l1) << 16) | __half_as_ushort(l0);
                uint32_t pl23 = ((uint32_t)__half_as_ushort(l3) << 16) | __half_as_ushort(l2);
                *(uint32_t*)&Cl[(size_t)row0 * D + col] = pl01;
                *(uint32_t*)&Cl[(size_t)(row0 + 8) * D + col] = pl23;
            }
            s0 += v0 + v2; s1 += v1 + v3;
            q0 += v0 * v0 + v2 * v2; q1 += v1 * v1 + v3 * v3;
        }
        if (dosum) {
#pragma unroll
            for (int o = 4; o < 32; o <<= 1) {
                s0 += __shfl_xor_sync(0xffffffffu, s0, o);
                s1 += __shfl_xor_sync(0xffffffffu, s1, o);
                q0 += __shfl_xor_sync(0xffffffffu, q0, o);
                q1 += __shfl_xor_sync(0xffffffffu, q1, o);
            }
            if (lane < 4) {
                int cl = wn * 32 + nt * 8 + lane * 2;
                atomicAdd(&scs[cl], s0); atomicAdd(&scs[cl + 1], s1);
                atomicAdd(&scq[cl], q0); atomicAdd(&scq[cl + 1], q1);
            }
        }
    }
    if (dosum) {
        __syncthreads();
        if (tid < 64) {
            atomicAdd(&gsum[bn + tid], scs[tid]);
            atomicAdd(&gsq[bn + tid], scq[tid]);
        }
    }
}

// ================= graph kernels =================
__global__ void deg_kernel(const int* __restrict__ dst) {
    int e = blockIdx.x * blockDim.x + threadIdx.x;
    if (e < NEDGES) atomicAdd(&g_degi[dst[e]], 1);
}
__global__ void isq_kernel() {
    int n = blockIdx.x * blockDim.x + threadIdx.x;
    if (n < NNODES) g_isq[n] = rsqrtf((float)g_degi[n] + 1.0f);
}
__global__ void scan_kernel() {
    __shared__ int sh[1024];
    int tid = threadIdx.x;
    int base = tid * 32;
    int local[32];
    int s = 0;
    for (int i = 0; i < 32; i++) { local[i] = s; s += g_degi[base + i]; }
    sh[tid] = s;
    __syncthreads();
    for (int off = 1; off < 1024; off <<= 1) {
        int v = 0;
        if (tid >= off) v = sh[tid - off];
        __syncthreads();
        if (tid >= off) sh[tid] += v;
        __syncthreads();
    }
    int prev = (tid == 0) ? 0 : sh[tid - 1];
    for (int i = 0; i < 32; i++) {
        g_off[base + i] = prev + local[i];
        g_cursor[base + i] = prev + local[i];
    }
    if (tid == 1023) g_off[NNODES] = sh[1023];
}
__global__ void scatter_kernel(const int* __restrict__ src, const int* __restrict__ dst) {
    int e = blockIdx.x * blockDim.x + threadIdx.x;
    if (e < NEDGES) {
        int d = dst[e];
        int p = atomicAdd(&g_cursor[d], 1);
        g_csr[p] = src[e];
    }
}

// GCN aggregation: fp16 in, fp32 accumulate, bias+relu, fp16 hi/lo out
__global__ void __launch_bounds__(128)
agg_kernel(const __half* __restrict__ xw, const float* __restrict__ bias,
           __half* __restrict__ oh, __half* __restrict__ ol) {
    int n = blockIdx.x;
    int t = threadIdx.x;
    float isqn = g_isq[n];
    const __half* selfrow = xw + (size_t)n * D;
    float sc = isqn * isqn;
    float a0 = __half2float(selfrow[t]) * sc;
    float a1 = __half2float(selfrow[128 + t]) * sc;
    float a2 = __half2float(selfrow[256 + t]) * sc;

    int beg = g_off[n], end = g_off[n + 1];
    __shared__ int ssrc[128];
    __shared__ float scoef[128];
    for (int p = beg; p < end; p += 128) {
        int cnt = min(128, end - p);
        __syncthreads();
        if (t < cnt) {
            int s = g_csr[p + t];
            ssrc[t] = s;
            scoef[t] = g_isq[s] * isqn;
        }
        __syncthreads();
        for (int j = 0; j < cnt; j++) {
            int s = ssrc[j];
            float c = scoef[j];
            const __half* row = xw + (size_t)s * D;
            a0 += __half2float(row[t]) * c;
            a1 += __half2float(row[128 + t]) * c;
            a2 += __half2float(row[256 + t]) * c;
        }
    }
    float v[3] = { fmaxf(a0 + bias[t], 0.f),
                   fmaxf(a1 + bias[128 + t], 0.f),
                   fmaxf(a2 + bias[256 + t], 0.f) };
#pragma unroll
    for (int i = 0; i < 3; i++) {
        size_t idx = (size_t)n * D + i * 128 + t;
        __half h = __float2half_rn(v[i]);
        oh[idx] = h;
        ol[idx] = __float2half_rn(v[i] - __half2float(h));
    }
}

// ================= tail kernels =================
__global__ void sel_kernel(const int* __restrict__ mask) {
    int b = threadIdx.x;
    int c = 0;
    for (int i = 0; i < NGRAPH; i++) {
        if (mask[b * NGRAPH + i]) {
            if (c < 2) g_sel[b * 2 + c] = i;
            c++;
        }
    }
}
// gather 2 masked nodes per sample (single fp16 source), BN (stats slot 4) inline
__global__ void gather_kernel(const __half* __restrict__ H,
                              const float* __restrict__ sum, const float* __restrict__ sq,
                              const float* __restrict__ gam, const float* __restrict__ bet) {
    int b = blockIdx.x >> 1;
    int j = blockIdx.x & 1;
    int node = b * NGRAPH + g_sel[b * 2 + j];
    int t = threadIdx.x;
    float v = __half2float(H[(size_t)node * D + t]);
    float s = bn_scale_of(sum, sq, t, (float)NNODES, gam);
    float sh = bn_shift_of(sum, sq, t, (float)NNODES, gam, bet);
    g_flat[b * EFEAT + j * D + t] = v * s + sh;
}
// outc = relu(flat @ w_cat + b_cat), fused column stats (slot 5)
__global__ void cat_gemm_kernel(const float* __restrict__ Wc, const float* __restrict__ bc,
                                float* __restrict__ sum, float* __restrict__ sq) {
    __shared__ float sh[EFEAT];
    int b = blockIdx.x, t = threadIdx.x;
    sh[t] = g_flat[b * EFEAT + t];
    __syncthreads();
    float s = bc[t];
    for (int k = 0; k < EFEAT; k++) s += sh[k] * Wc[(size_t)k * EFEAT + t];
    s = fmaxf(s, 0.f);
    g_outc[b * EFEAT + t] = s;
    atomicAdd(&sum[t], s);
    atomicAdd(&sq[t], s * s);
}
// att = BN1(hsent) + BN0(outc); out = att @ w_out + b_out   (one block per sample)
__global__ void attout_kernel(const float* __restrict__ sum5, const float* __restrict__ sq5,
                              const float* __restrict__ sum6, const float* __restrict__ sq6,
                              const float* __restrict__ bg, const float* __restrict__ bb,
                              const float* __restrict__ wout, const float* __restrict__ bout,
                              float* __restrict__ out) {
    __shared__ float satt[EFEAT];
    int b = blockIdx.x, t = threadIdx.x;
    float Bf = (float)BATCH;
    float m0 = sum5[t] / Bf, v0 = sq5[t] / Bf - m0 * m0;
    float oc = bg[t] * (g_outc[b * EFEAT + t] - m0) * rsqrtf(v0 + EPS) + bb[t];
    float m1 = sum6[t] / Bf, v1 = sq6[t] / Bf - m1 * m1;
    float hh = bg[EFEAT + t] * (g_hsent[b * EFEAT + t] - m1) * rsqrtf(v1 + EPS) + bb[EFEAT + t];
    satt[t] = hh + oc;
    __syncthreads();
    int w = t >> 5, lane = t & 31;
    if (w < 3) {
        int c = w;
        float p = 0.f;
        for (int e = lane; e < EFEAT; e += 32) p += satt[e] * wout[e * 3 + c];
#pragma unroll
        for (int o = 16; o > 0; o >>= 1) p += __shfl_xor_sync(0xffffffffu, p, o);
        if (lane == 0) out[b * 3 + c] = p + bout[c];
    }
}

// ============================== launch ==============================
extern "C" void kernel_launch(void* const* d_in, const int* in_sizes, int n_in,
                              void* d_out, int out_size) {
    const float* last_h  = (const float*)d_in[0];
    const float* first_h = (const float*)d_in[1];
    const float* x_nodes = (const float*)d_in[2];
    const int*   eidx    = (const int*)d_in[3];
    const int*   mask    = (const int*)d_in[4];
    const float* w_pre1  = (const float*)d_in[5];
    const float* b_pre1  = (const float*)d_in[6];
    const float* w_pre2  = (const float*)d_in[7];
    const float* b_pre2  = (const float*)d_in[8];
    const float* w_conv  = (const float*)d_in[9];
    const float* b_conv  = (const float*)d_in[10];
    const float* bng_g   = (const float*)d_in[11];
    const float* bng_b   = (const float*)d_in[12];
    const float* w_post1 = (const float*)d_in[13];
    const float* b_post1 = (const float*)d_in[14];
    const float* w_post2 = (const float*)d_in[15];
    const float* b_post2 = (const float*)d_in[16];
    const float* w_cat   = (const float*)d_in[17];
    const float* b_cat   = (const float*)d_in[18];
    const float* bn_g    = (const float*)d_in[19];
    const float* bn_b    = (const float*)d_in[20];
    const float* w_out   = (const float*)d_in[21];
    const float* b_out   = (const float*)d_in[22];
    float* out = (float*)d_out;

    const int* esrc = eidx;
    const int* edst = eidx + NEDGES;

    float *sum, *sq, *hs, *bfp;
    __half *x0h, *x0l, *h1, *l1, *h2, *l2, *wth, *wtl, *xw;
    cudaGetSymbolAddress((void**)&sum, g_sum);
    cudaGetSymbolAddress((void**)&sq, g_sq);
    cudaGetSymbolAddress((void**)&hs, g_hsent);
    cudaGetSymbolAddress((void**)&bfp, g_biasf);
    cudaGetSymbolAddress((void**)&xw, g_xw);
    cudaGetSymbolAddress((void**)&x0h, g_x0h);
    cudaGetSymbolAddress((void**)&x0l, g_x0l);
    cudaGetSymbolAddress((void**)&h1, g_h1);
    cudaGetSymbolAddress((void**)&l1, g_l1);
    cudaGetSymbolAddress((void**)&h2, g_h2);
    cudaGetSymbolAddress((void**)&l2, g_l2);
    cudaGetSymbolAddress((void**)&wth, g_wth);
    cudaGetSymbolAddress((void**)&wtl, g_wtl);

    cudaFuncSetAttribute(mma_gemm, cudaFuncAttributeMaxDynamicSharedMemorySize, DYN_SMEM);

    const float Mf = (float)NNODES;
    dim3 gg(D / 64, NNODES / 128);   // (6, 256)

    cudaStream_t s1, s2;
    cudaEvent_t e0, e1, e2;
    cudaStreamCreateWithFlags(&s1, cudaStreamNonBlocking);
    cudaStreamCreateWithFlags(&s2, cudaStreamNonBlocking);
    cudaEventCreateWithFlags(&e0, cudaEventDisableTiming);
    cudaEventCreateWithFlags(&e1, cudaEventDisableTiming);
    cudaEventCreateWithFlags(&e2, cudaEventDisableTiming);

    zero_kernel<<<192, 256>>>();
    cudaEventRecord(e0, 0);
    cudaStreamWaitEvent(s1, e0, 0);
    cudaStreamWaitEvent(s2, e0, 0);

    // side stream 1: sentence branch + its stats (slot 6)
    hsent_kernel<<<dim3(BATCH, 4), EFEAT, 0, s1>>>(last_h, first_h);
    stats_kernel<<<1, EFEAT, 0, s1>>>(hs, BATCH, EFEAT, sum + 6 * EFEAT, sq + 6 * EFEAT);
    cudaEventRecord(e1, s1);

    // side stream 2: degree / CSR / mask selection
    deg_kernel<<<NEDGES / 256, 256, 0, s2>>>(edst);
    isq_kernel<<<NNODES / 256, 256, 0, s2>>>();
    scan_kernel<<<1, 1024, 0, s2>>>();
    scatter_kernel<<<NEDGES / 256, 256, 0, s2>>>(esrc, edst);
    sel_kernel<<<1, BATCH, 0, s2>>>(mask);
    cudaEventRecord(e2, s2);

    // main: input prep + stage-0 weights
    xprep_kernel<<<(NNODES * 320 + 255) / 256, 256>>>(x_nodes);
    wprep0_kernel<<<(D * 320 + 255) / 256, 256>>>(w_pre1, 300, 320,
                                                  wth + 0 * D * D, wtl + 0 * D * D);

    // GEMM1 (3-pass) -> h1/l1, fused stats slot 0 (bng row 0)
    mma_gemm<<<gg, 256, DYN_SMEM>>>(x0h, x0l, wth + 0 * D * D, wtl + 0 * D * D, b_pre1,
                                    h1, l1, 320, 10, 1, 1, sum + 0 * EFEAT, sq + 0 * EFEAT);
    fold_kernel<<<D, 128>>>(w_pre2, sum + 0 * EFEAT, sq + 0 * EFEAT,
                            bng_g + 0 * D, bng_b + 0 * D, Mf, b_pre2,
                            wth + 1 * D * D, wtl + 1 * D * D, bfp + 1 * D);

    // GEMM2 (3-pass) -> h2/l2, stats slot 1 (bng row 1)
    mma_gemm<<<gg, 256, DYN_SMEM>>>(h1, l1, wth + 1 * D * D, wtl + 1 * D * D, bfp + 1 * D,
                                    h2, l2, D, 12, 1, 1, sum + 1 * EFEAT, sq + 1 * EFEAT);
    fold_kernel<<<D, 128>>>(w_conv + 2 * D * D, sum + 1 * EFEAT, sq + 1 * EFEAT,
                            bng_g + 1 * D, bng_b + 1 * D, Mf, nullptr,
                            wth + 2 * D * D, wtl + 2 * D * D, bfp + 2 * D);

    // GEMM3 (2-pass; output fp16-rounded anyway) -> single fp16 xw
    mma_gemm<<<gg, 256, DYN_SMEM>>>(h2, l2, wth + 2 * D * D, wtl + 2 * D * D, bfp + 2 * D,
                                    xw, nullptr, D, 12, 0, 0, nullptr, nullptr);

    // join CSR stream, aggregate, stats slot 2 (bng row 4)
    cudaStreamWaitEvent(0, e2, 0);
    agg_kernel<<<NNODES, 128>>>(xw, b_conv + 2 * D, h1, l1);
    stats_f16_kernel<<<256, D>>>(h1, l1, sum + 2 * EFEAT, sq + 2 * EFEAT);
    fold_kernel<<<D, 128>>>(w_post1, sum + 2 * EFEAT, sq + 2 * EFEAT,
                            bng_g + 4 * D, bng_b + 4 * D, Mf, b_post1,
                            wth + 3 * D * D, wtl + 3 * D * D, bfp + 3 * D);

    // GEMM4 (3-pass) -> h2/l2, stats slot 3 (bng row 5)
    mma_gemm<<<gg, 256, DYN_SMEM>>>(h1, l1, wth + 3 * D * D, wtl + 3 * D * D, bfp + 3 * D,
                                    h2, l2, D, 12, 1, 1, sum + 3 * EFEAT, sq + 3 * EFEAT);
    fold_kernel<<<D, 128>>>(w_post2, sum + 3 * EFEAT, sq + 3 * EFEAT,
                            bng_g + 5 * D, bng_b + 5 * D, Mf, b_post2,
                            wth + 4 * D * D, wtl + 4 * D * D, bfp + 4 * D);

    // GEMM5 (3-pass, single fp16 out; only 128 rows + stats consumed) -> h1, stats slot 4
    mma_gemm<<<gg, 256, DYN_SMEM>>>(h2, l2, wth + 4 * D * D, wtl + 4 * D * D, bfp + 4 * D,
                                    h1, nullptr, D, 12, 1, 1, sum + 4 * EFEAT, sq + 4 * EFEAT);

    // tail: gather (BN row 6 inline) -> cat-MLP (+stats slot 5) -> att+out
    gather_kernel<<<BATCH * 2, D>>>(h1, sum + 4 * EFEAT, sq + 4 * EFEAT,
                                    bng_g + 6 * D, bng_b + 6 * D);
    cat_gemm_kernel<<<BATCH, EFEAT>>>(w_cat, b_cat, sum + 5 * EFEAT, sq + 5 * EFEAT);
    cudaStreamWaitEvent(0, e1, 0);
    attout_kernel<<<BATCH, EFEAT>>>(sum + 5 * EFEAT, sq + 5 * EFEAT,
                                    sum + 6 * EFEAT, sq + 6 * EFEAT,
                                    bn_g, bn_b, w_out, b_out, out);

    cudaEventDestroy(e0);
    cudaEventDestroy(e1);
    cudaEventDestroy(e2);
    cudaStreamDestroy(s1);
    cudaStreamDestroy(s2);
}

// round 8
// speedup vs baseline: 3.0380x; 1.0645x over previous
#include <cuda_runtime.h>
#include <cuda_fp16.h>
#include <cstdint>
#include <math.h>

// ---------------- problem constants ----------------
#define NNODES 32768
#define D      384
#define EFEAT  768
#define BATCH  64
#define SEQ    512
#define NGRAPH 512
#define NEDGES 1048576
#define EPS    1e-5f

// ---------------- device scratch (static, no allocs) ----------------
__device__ __half g_x0h[(size_t)NNODES * 320];
__device__ __half g_x0l[(size_t)NNODES * 320];
__device__ __half g_h1[(size_t)NNODES * D];
__device__ __half g_l1[(size_t)NNODES * D];
__device__ __half g_h2[(size_t)NNODES * D];
__device__ __half g_l2[(size_t)NNODES * D];
__device__ __half g_xw[(size_t)NNODES * D];
__device__ int    g_degi[NNODES];
__device__ float  g_isq[NNODES];
__device__ int    g_off[NNODES + 1];
__device__ int    g_cursor[NNODES];
__device__ int    g_csr[NEDGES];
__device__ float  g_sum[7 * EFEAT];
__device__ float  g_sq[7 * EFEAT];
__device__ float  g_hsent[BATCH * EFEAT];
__device__ float  g_flat[BATCH * EFEAT];
__device__ float  g_outc[BATCH * EFEAT];
__device__ int    g_sel[BATCH * 2];
// folded transposed weights fp16 hi/lo: [N=384][KPAD<=384]
__device__ __half g_wth[5][D * D];
__device__ __half g_wtl[5][D * D];
__device__ float  g_biasf[5][D];

// ================= helpers =================
__device__ __forceinline__ uint32_t smem_u32(const void* p) {
    uint32_t a;
    asm("{ .reg .u64 t; cvta.to.shared.u64 t, %1; cvt.u32.u64 %0, t; }" : "=r"(a) : "l"(p));
    return a;
}
__device__ __forceinline__ void ldsm4(uint32_t* r, uint32_t addr) {
    asm volatile("ldmatrix.sync.aligned.m8n8.x4.shared.b16 {%0,%1,%2,%3}, [%4];"
                 : "=r"(r[0]), "=r"(r[1]), "=r"(r[2]), "=r"(r[3]) : "r"(addr));
}
__device__ __forceinline__ void mma16816f(float* c, const uint32_t* a, uint32_t b0, uint32_t b1) {
    asm volatile("mma.sync.aligned.m16n8k16.row.col.f32.f16.f16.f32 "
                 "{%0,%1,%2,%3},{%4,%5,%6,%7},{%8,%9},{%0,%1,%2,%3};"
                 : "+f"(c[0]), "+f"(c[1]), "+f"(c[2]), "+f"(c[3])
                 : "r"(a[0]), "r"(a[1]), "r"(a[2]), "r"(a[3]), "r"(b0), "r"(b1));
}
#define CP16(d, s) asm volatile("cp.async.cg.shared.global [%0], [%1], 16;" :: "r"(d), "l"(s) : "memory")
#define CP_COMMIT() asm volatile("cp.async.commit_group;" ::: "memory")
#define CP_WAIT1() asm volatile("cp.async.wait_group 1;" ::: "memory")
#define CP_WAIT0() asm volatile("cp.async.wait_group 0;" ::: "memory")

// stage layout (bytes): Ah@0 (10240) Al@10240 Bh@20480 (5120) Bl@25600 (5120); stride 30720
#define STAGE_STRIDE 30720
#define DYN_SMEM (2 * STAGE_STRIDE + 512)
#define AROW 40  // halves; 80B row pitch

__device__ __forceinline__ float bn_scale_of(const float* sum, const float* sq, int k,
                                             float Mf, const float* gam) {
    float m = sum[k] / Mf;
    float v = sq[k] / Mf - m * m;
    return gam[k] * rsqrtf(v + EPS);
}
__device__ __forceinline__ float bn_shift_of(const float* sum, const float* sq, int k,
                                             float Mf, const float* gam, const float* bet) {
    float m = sum[k] / Mf;
    float v = sq[k] / Mf - m * m;
    float s = gam[k] * rsqrtf(v + EPS);
    return bet[k] - m * s;
}

// ================= misc kernels =================
__global__ void zero_kernel() {
    int i = blockIdx.x * blockDim.x + threadIdx.x;
    if (i < NNODES) g_degi[i] = 0;
    if (i < 7 * EFEAT) { g_sum[i] = 0.f; g_sq[i] = 0.f; }
    if (i < BATCH * EFEAT) g_hsent[i] = 0.f;
}

__global__ void hsent_kernel(const float* __restrict__ lh, const float* __restrict__ fh) {
    int b = blockIdx.x, chunk = blockIdx.y, t = threadIdx.x;
    size_t base = ((size_t)b * SEQ + chunk * 128) * EFEAT + t;
    float s = 0.f;
    for (int ss = 0; ss < 128; ss++)
        s += lh[base + (size_t)ss * EFEAT] + fh[base + (size_t)ss * EFEAT];
    atomicAdd(&g_hsent[b * EFEAT + t], s * (0.5f / 512.0f));
}

// x_nodes fp32 [N,300] -> fp16 hi/lo [N,320] zero-padded
__global__ void xprep_kernel(const float* __restrict__ X) {
    size_t idx = (size_t)blockIdx.x * blockDim.x + threadIdx.x;
    if (idx >= (size_t)NNODES * 320) return;
    int row = (int)(idx / 320), k = (int)(idx % 320);
    float v = (k < 300) ? X[(size_t)row * 300 + k] : 0.f;
    __half h = __float2half_rn(v);
    g_x0h[idx] = h;
    g_x0l[idx] = __float2half_rn(v - __half2float(h));
}

// stage-0 weight prep (no BN fold): W[K,384] -> transposed fp16 hi/lo [384][KPAD]
__global__ void wprep0_kernel(const float* __restrict__ W, int K, int KPAD,
                              __half* __restrict__ oh, __half* __restrict__ ol) {
    int idx = blockIdx.x * blockDim.x + threadIdx.x;
    if (idx >= D * KPAD) return;
    int n = idx / KPAD, k = idx % KPAD;
    float v = (k < K) ? W[(size_t)k * D + n] : 0.f;
    __half h = __float2half_rn(v);
    oh[idx] = h;
    ol[idx] = __float2half_rn(v - __half2float(h));
}

// fused BN-fold: folded weight row (hi/lo) + folded bias, one block per output col n.
__global__ void fold_kernel(const float* __restrict__ W,
                            const float* __restrict__ sum, const float* __restrict__ sq,
                            const float* __restrict__ gam, const float* __restrict__ bet,
                            float Mf, const float* __restrict__ base,
                            __half* __restrict__ oh, __half* __restrict__ ol,
                            float* __restrict__ outb) {
    int n = blockIdx.x, t = threadIdx.x;
    float acc = 0.f;
#pragma unroll
    for (int i = 0; i < 3; i++) {
        int k = t + i * 128;
        float w = W[(size_t)k * D + n];
        float m = sum[k] / Mf;
        float var = sq[k] / Mf - m * m;
        float sc = gam[k] * rsqrtf(var + EPS);
        float sh = bet[k] - m * sc;
        float v = w * sc;
        __half h = __float2half_rn(v);
        oh[(size_t)n * D + k] = h;
        ol[(size_t)n * D + k] = __float2half_rn(v - __half2float(h));
        acc += sh * w;
    }
    __shared__ float red[128];
    red[t] = acc;
    __syncthreads();
    for (int o = 64; o > 0; o >>= 1) {
        if (t < o) red[t] += red[t + o];
        __syncthreads();
    }
    if (t == 0) outb[n] = (base ? base[n] : 0.f) + red[0];
}

// fp32 column stats
__global__ void stats_kernel(const float* __restrict__ X, int M, int N,
                             float* __restrict__ sum, float* __restrict__ sq) {
    int col = threadIdx.x;
    int rows_per = (M + gridDim.x - 1) / gridDim.x;
    int r0 = blockIdx.x * rows_per;
    int r1 = min(M, r0 + rows_per);
    float s = 0.f, q = 0.f;
    for (int r = r0; r < r1; r++) {
        float v = X[(size_t)r * N + col];
        s += v; q += v * v;
    }
    atomicAdd(&sum[col], s);
    atomicAdd(&sq[col], q);
}

// fp16 hi/lo column stats
__global__ void stats_f16_kernel(const __half* __restrict__ H, const __half* __restrict__ L,
                                 float* __restrict__ sum, float* __restrict__ sq) {
    int col = threadIdx.x;
    int rows_per = (NNODES + gridDim.x - 1) / gridDim.x;
    int r0 = blockIdx.x * rows_per;
    int r1 = min(NNODES, r0 + rows_per);
    float s = 0.f, q = 0.f;
    for (int r = r0; r < r1; r++) {
        size_t i = (size_t)r * D + col;
        float v = __half2float(H[i]) + __half2float(L[i]);
        s += v; q += v * v;
    }
    atomicAdd(&sum[col], s);
    atomicAdd(&sq[col], q);
}

// ================= cp.async tile stage =================
__device__ __forceinline__ void issue_tiles(uint32_t sbase, int stage, int tid,
                                            const __half* Ah, const __half* Al,
                                            const __half* Bh, const __half* Bl,
                                            int bm, int bn, int KPAD, int chunk,
                                            int load_al) {
    uint32_t sb = sbase + stage * STAGE_STRIDE;
#pragma unroll
    for (int it = 0; it < 2; it++) {
        int i = tid + it * 256;
        int row = i >> 2, c16 = i & 3;
        uint32_t d = sb + row * 80 + c16 * 16;
        const __half* sa = Ah + (size_t)(bm + row) * KPAD + chunk * 32 + c16 * 8;
        CP16(d, sa);
        if (load_al) {
            const __half* sl = Al + (size_t)(bm + row) * KPAD + chunk * 32 + c16 * 8;
            CP16(d + 10240, sl);
        }
    }
    {
        int row = tid >> 2, c16 = tid & 3;
        uint32_t d = sb + 20480 + row * 80 + c16 * 16;
        const __half* sbh = Bh + (size_t)(bn + row) * KPAD + chunk * 32 + c16 * 8;
        const __half* sbl = Bl + (size_t)(bn + row) * KPAD + chunk * 32 + c16 * 8;
        CP16(d, sbh);
        CP16(d + 5120, sbl);
    }
}

// ================= mma.sync fp16 GEMM, double-buffered =================
// three_pass=1: C = (Ah+Al)@(Bh+Bl)^T dropping AlBl (err ~2^-22)
// three_pass=0: C = Ah@(Bh+Bl)^T (err ~2^-11; A-lo never loaded)
// block 128x64, chunk K32, 8 warps (4m x 2n); optional fused column stats.
// Output: Cl!=null -> hi/lo fp16 pair; Cl==null -> single fp16 in Ch.
__global__ void __launch_bounds__(256, 2)
mma_gemm(const __half* __restrict__ Ah, const __half* __restrict__ Al,
         const __half* __restrict__ Bh, const __half* __restrict__ Bl,
         const float* __restrict__ biasf,
         __half* __restrict__ Ch, __half* __restrict__ Cl,
         int KPAD, int nchunks, int do_relu, int three_pass,
         float* __restrict__ gsum, float* __restrict__ gsq) {
    extern __shared__ char dsm[];
    float* scs = (float*)(dsm + 2 * STAGE_STRIDE);
    float* scq = scs + 64;
    uint32_t sbase = smem_u32(dsm);

    int tid = threadIdx.x;
    int wid = tid >> 5, lane = tid & 31;
    int bm = blockIdx.y * 128, bn = blockIdx.x * 64;
    int wm = wid & 3, wn = wid >> 2;

    if (tid < 64) { scs[tid] = 0.f; scq[tid] = 0.f; }

    float acc[2][4][4];
#pragma unroll
    for (int i = 0; i < 2; i++)
#pragma unroll
        for (int j = 0; j < 4; j++)
#pragma unroll
            for (int k = 0; k < 4; k++) acc[i][j][k] = 0.f;

    int g = lane >> 3, r = lane & 7;
    int frag_row = (g & 1) * 8 + r;
    int frag_col = (g >> 1) * 8;

    issue_tiles(sbase, 0, tid, Ah, Al, Bh, Bl, bm, bn, KPAD, 0, three_pass);
    CP_COMMIT();

    for (int c = 0; c < nchunks; c++) {
        if (c + 1 < nchunks) {
            issue_tiles(sbase, (c + 1) & 1, tid, Ah, Al, Bh, Bl, bm, bn, KPAD, c + 1, three_pass);
            CP_COMMIT();
            CP_WAIT1();
        } else {
            CP_WAIT0();
        }
        __syncthreads();

        uint32_t baseAh = sbase + (c & 1) * STAGE_STRIDE;
        uint32_t baseAl = baseAh + 10240;
        uint32_t baseBh = baseAh + 20480;
        uint32_t baseBl = baseAh + 25600;
#pragma unroll
        for (int ks = 0; ks < 2; ks++) {
            int k0 = ks * 16;
            uint32_t ah[2][4], al[2][4], bh[2][4], bl[2][4];
#pragma unroll
            for (int mi = 0; mi < 2; mi++) {
                int row = wm * 32 + mi * 16 + frag_row;
                uint32_t off = (uint32_t)(row * AROW + k0 + frag_col) * 2;
                ldsm4(ah[mi], baseAh + off);
                if (three_pass) ldsm4(al[mi], baseAl + off);
            }
#pragma unroll
            for (int j = 0; j < 2; j++) {
                int row = wn * 32 + j * 16 + frag_row;
                uint32_t off = (uint32_t)(row * AROW + k0 + frag_col) * 2;
                ldsm4(bh[j], baseBh + off);
                ldsm4(bl[j], baseBl + off);
            }
#pragma unroll
            for (int mi = 0; mi < 2; mi++)
#pragma unroll
                for (int nt = 0; nt < 4; nt++) {
                    int j = nt >> 1, sel = nt & 1;
                    mma16816f(acc[mi][nt], ah[mi], bh[j][sel], bh[j][sel + 2]);
                    mma16816f(acc[mi][nt], ah[mi], bl[j][sel], bl[j][sel + 2]);
                    if (three_pass)
                        mma16816f(acc[mi][nt], al[mi], bh[j][sel], bh[j][sel + 2]);
                }
        }
        __syncthreads();
    }

    // ---- epilogue ----
    int tm = lane >> 2;
    int tn = (lane & 3) * 2;
    bool dosum = (gsum != nullptr);
#pragma unroll
    for (int nt = 0; nt < 4; nt++) {
        float s0 = 0.f, s1 = 0.f, q0 = 0.f, q1 = 0.f;
        int col = bn + wn * 32 + nt * 8 + tn;
        float b0 = biasf[col], b1 = biasf[col + 1];
#pragma unroll
        for (int mi = 0; mi < 2; mi++) {
            int row0 = bm + wm * 32 + mi * 16 + tm;
            float v0 = acc[mi][nt][0] + b0, v1 = acc[mi][nt][1] + b1;
            float v2 = acc[mi][nt][2] + b0, v3 = acc[mi][nt][3] + b1;
            if (do_relu) {
                v0 = fmaxf(v0, 0.f); v1 = fmaxf(v1, 0.f);
                v2 = fmaxf(v2, 0.f); v3 = fmaxf(v3, 0.f);
            }
            __half h0 = __float2half_rn(v0), h1 = __float2half_rn(v1);
            __half h2 = __float2half_rn(v2), h3 = __float2half_rn(v3);
            uint32_t ph01 = ((uint32_t)__half_as_ushort(h1) << 16) | __half_as_ushort(h0);
            uint32_t ph23 = ((uint32_t)__half_as_ushort(h3) << 16) | __half_as_ushort(h2);
            *(uint32_t*)&Ch[(size_t)row0 * D + col] = ph01;
            *(uint32_t*)&Ch[(size_t)(row0 + 8) * D + col] = ph23;
            if (Cl) {
                __half l0 = __float2half_rn(v0 - __half2float(h0));
                __half l1 = __float2half_rn(v1 - __half2float(h1));
                __half l2 = __float2half_rn(v2 - __half2float(h2));
                __half l3 = __float2half_rn(v3 - __half2float(h3));
                uint32_t pl01 = ((uint32_t)__half_as_ushort(l1) << 16) | __half_as_ushort(l0);
                uint32_t pl23 = ((uint32_t)__half_as_ushort(l3) << 16) | __half_as_ushort(l2);
                *(uint32_t*)&Cl[(size_t)row0 * D + col] = pl01;
                *(uint32_t*)&Cl[(size_t)(row0 + 8) * D + col] = pl23;
            }
            s0 += v0 + v2; s1 += v1 + v3;
            q0 += v0 * v0 + v2 * v2; q1 += v1 * v1 + v3 * v3;
        }
        if (dosum) {
#pragma unroll
            for (int o = 4; o < 32; o <<= 1) {
                s0 += __shfl_xor_sync(0xffffffffu, s0, o);
                s1 += __shfl_xor_sync(0xffffffffu, s1, o);
                q0 += __shfl_xor_sync(0xffffffffu, q0, o);
                q1 += __shfl_xor_sync(0xffffffffu, q1, o);
            }
            if (lane < 4) {
                int cl = wn * 32 + nt * 8 + lane * 2;
                atomicAdd(&scs[cl], s0); atomicAdd(&scs[cl + 1], s1);
                atomicAdd(&scq[cl], q0); atomicAdd(&scq[cl + 1], q1);
            }
        }
    }
    if (dosum) {
        __syncthreads();
        if (tid < 64) {
            atomicAdd(&gsum[bn + tid], scs[tid]);
            atomicAdd(&gsq[bn + tid], scq[tid]);
        }
    }
}

// ================= graph kernels =================
__global__ void deg_kernel(const int* __restrict__ dst) {
    int e = blockIdx.x * blockDim.x + threadIdx.x;
    if (e < NEDGES) atomicAdd(&g_degi[dst[e]], 1);
}
__global__ void isq_kernel() {
    int n = blockIdx.x * blockDim.x + threadIdx.x;
    if (n < NNODES) g_isq[n] = rsqrtf((float)g_degi[n] + 1.0f);
}
__global__ void scan_kernel() {
    __shared__ int sh[1024];
    int tid = threadIdx.x;
    int base = tid * 32;
    int local[32];
    int s = 0;
    for (int i = 0; i < 32; i++) { local[i] = s; s += g_degi[base + i]; }
    sh[tid] = s;
    __syncthreads();
    for (int off = 1; off < 1024; off <<= 1) {
        int v = 0;
        if (tid >= off) v = sh[tid - off];
        __syncthreads();
        if (tid >= off) sh[tid] += v;
        __syncthreads();
    }
    int prev = (tid == 0) ? 0 : sh[tid - 1];
    for (int i = 0; i < 32; i++) {
        g_off[base + i] = prev + local[i];
        g_cursor[base + i] = prev + local[i];
    }
    if (tid == 1023) g_off[NNODES] = sh[1023];
}
__global__ void scatter_kernel(const int* __restrict__ src, const int* __restrict__ dst) {
    int e = blockIdx.x * blockDim.x + threadIdx.x;
    if (e < NEDGES) {
        int d = dst[e];
        int p = atomicAdd(&g_cursor[d], 1);
        g_csr[p] = src[e];
    }
}

// GCN aggregation: fp16 in (u32/half2 loads), fp32 accumulate, bias+relu, fp16 hi/lo out
// 192 threads: thread t owns columns 2t, 2t+1 (one u32 per row)
#define AGG_T 192
__global__ void __launch_bounds__(AGG_T)
agg_kernel(const __half* __restrict__ xw, const float* __restrict__ bias,
           __half* __restrict__ oh, __half* __restrict__ ol) {
    int n = blockIdx.x;
    int t = threadIdx.x;
    float isqn = g_isq[n];
    float sc = isqn * isqn;
    const uint32_t* selfrow = (const uint32_t*)(xw + (size_t)n * D);
    uint32_t su = selfrow[t];
    __half2 sh2 = *(__half2*)&su;
    float a0 = __low2float(sh2) * sc;
    float a1 = __high2float(sh2) * sc;

    int beg = g_off[n], end = g_off[n + 1];
    __shared__ int ssrc[AGG_T];
    __shared__ float scoef[AGG_T];
    for (int p = beg; p < end; p += AGG_T) {
        int cnt = min(AGG_T, end - p);
        __syncthreads();
        if (t < cnt) {
            int s = g_csr[p + t];
            ssrc[t] = s;
            scoef[t] = g_isq[s] * isqn;
        }
        __syncthreads();
        for (int j = 0; j < cnt; j++) {
            int s = ssrc[j];
            float c = scoef[j];
            uint32_t u = ((const uint32_t*)(xw + (size_t)s * D))[t];
            __half2 h2v = *(__half2*)&u;
            a0 += __low2float(h2v) * c;
            a1 += __high2float(h2v) * c;
        }
    }
    float2 bb = *(const float2*)(bias + 2 * t);
    float v0 = fmaxf(a0 + bb.x, 0.f);
    float v1 = fmaxf(a1 + bb.y, 0.f);
    __half h0 = __float2half_rn(v0);
    __half h1 = __float2half_rn(v1);
    uint32_t ph = ((uint32_t)__half_as_ushort(h1) << 16) | __half_as_ushort(h0);
    __half l0 = __float2half_rn(v0 - __half2float(h0));
    __half l1 = __float2half_rn(v1 - __half2float(h1));
    uint32_t pl = ((uint32_t)__half_as_ushort(l1) << 16) | __half_as_ushort(l0);
    ((uint32_t*)(oh + (size_t)n * D))[t] = ph;
    ((uint32_t*)(ol + (size_t)n * D))[t] = pl;
}

// ================= tail kernels =================
__global__ void sel_kernel(const int* __restrict__ mask) {
    int b = threadIdx.x;
    int c = 0;
    for (int i = 0; i < NGRAPH; i++) {
        if (mask[b * NGRAPH + i]) {
            if (c < 2) g_sel[b * 2 + c] = i;
            c++;
        }
    }
}
// gather 2 masked nodes per sample (single fp16 source), BN (stats slot 4) inline
__global__ void gather_kernel(const __half* __restrict__ H,
                              const float* __restrict__ sum, const float* __restrict__ sq,
                              const float* __restrict__ gam, const float* __restrict__ bet) {
    int b = blockIdx.x >> 1;
    int j = blockIdx.x & 1;
    int node = b * NGRAPH + g_sel[b * 2 + j];
    int t = threadIdx.x;
    float v = __half2float(H[(size_t)node * D + t]);
    float s = bn_scale_of(sum, sq, t, (float)NNODES, gam);
    float sh = bn_shift_of(sum, sq, t, (float)NNODES, gam, bet);
    g_flat[b * EFEAT + j * D + t] = v * s + sh;
}
// outc = relu(flat @ w_cat + b_cat), fused column stats (slot 5)
__global__ void cat_gemm_kernel(const float* __restrict__ Wc, const float* __restrict__ bc,
                                float* __restrict__ sum, float* __restrict__ sq) {
    __shared__ float sh[EFEAT];
    int b = blockIdx.x, t = threadIdx.x;
    sh[t] = g_flat[b * EFEAT + t];
    __syncthreads();
    float s = bc[t];
    for (int k = 0; k < EFEAT; k++) s += sh[k] * Wc[(size_t)k * EFEAT + t];
    s = fmaxf(s, 0.f);
    g_outc[b * EFEAT + t] = s;
    atomicAdd(&sum[t], s);
    atomicAdd(&sq[t], s * s);
}
// att = BN1(hsent) + BN0(outc); out = att @ w_out + b_out   (one block per sample)
__global__ void attout_kernel(const float* __restrict__ sum5, const float* __restrict__ sq5,
                              const float* __restrict__ sum6, const float* __restrict__ sq6,
                              const float* __restrict__ bg, const float* __restrict__ bb,
                              const float* __restrict__ wout, const float* __restrict__ bout,
                              float* __restrict__ out) {
    __shared__ float satt[EFEAT];
    int b = blockIdx.x, t = threadIdx.x;
    float Bf = (float)BATCH;
    float m0 = sum5[t] / Bf, v0 = sq5[t] / Bf - m0 * m0;
    float oc = bg[t] * (g_outc[b * EFEAT + t] - m0) * rsqrtf(v0 + EPS) + bb[t];
    float m1 = sum6[t] / Bf, v1 = sq6[t] / Bf - m1 * m1;
    float hh = bg[EFEAT + t] * (g_hsent[b * EFEAT + t] - m1) * rsqrtf(v1 + EPS) + bb[EFEAT + t];
    satt[t] = hh + oc;
    __syncthreads();
    int w = t >> 5, lane = t & 31;
    if (w < 3) {
        int c = w;
        float p = 0.f;
        for (int e = lane; e < EFEAT; e += 32) p += satt[e] * wout[e * 3 + c];
#pragma unroll
        for (int o = 16; o > 0; o >>= 1) p += __shfl_xor_sync(0xffffffffu, p, o);
        if (lane == 0) out[b * 3 + c] = p + bout[c];
    }
}

// ============================== launch ==============================
extern "C" void kernel_launch(void* const* d_in, const int* in_sizes, int n_in,
                              void* d_out, int out_size) {
    const float* last_h  = (const float*)d_in[0];
    const float* first_h = (const float*)d_in[1];
    const float* x_nodes = (const float*)d_in[2];
    const int*   eidx    = (const int*)d_in[3];
    const int*   mask    = (const int*)d_in[4];
    const float* w_pre1  = (const float*)d_in[5];
    const float* b_pre1  = (const float*)d_in[6];
    const float* w_pre2  = (const float*)d_in[7];
    const float* b_pre2  = (const float*)d_in[8];
    const float* w_conv  = (const float*)d_in[9];
    const float* b_conv  = (const float*)d_in[10];
    const float* bng_g   = (const float*)d_in[11];
    const float* bng_b   = (const float*)d_in[12];
    const float* w_post1 = (const float*)d_in[13];
    const float* b_post1 = (const float*)d_in[14];
    const float* w_post2 = (const float*)d_in[15];
    const float* b_post2 = (const float*)d_in[16];
    const float* w_cat   = (const float*)d_in[17];
    const float* b_cat   = (const float*)d_in[18];
    const float* bn_g    = (const float*)d_in[19];
    const float* bn_b    = (const float*)d_in[20];
    const float* w_out   = (const float*)d_in[21];
    const float* b_out   = (const float*)d_in[22];
    float* out = (float*)d_out;

    const int* esrc = eidx;
    const int* edst = eidx + NEDGES;

    float *sum, *sq, *hs, *bfp;
    __half *x0h, *x0l, *h1, *l1, *h2, *l2, *wth, *wtl, *xw;
    cudaGetSymbolAddress((void**)&sum, g_sum);
    cudaGetSymbolAddress((void**)&sq, g_sq);
    cudaGetSymbolAddress((void**)&hs, g_hsent);
    cudaGetSymbolAddress((void**)&bfp, g_biasf);
    cudaGetSymbolAddress((void**)&xw, g_xw);
    cudaGetSymbolAddress((void**)&x0h, g_x0h);
    cudaGetSymbolAddress((void**)&x0l, g_x0l);
    cudaGetSymbolAddress((void**)&h1, g_h1);
    cudaGetSymbolAddress((void**)&l1, g_l1);
    cudaGetSymbolAddress((void**)&h2, g_h2);
    cudaGetSymbolAddress((void**)&l2, g_l2);
    cudaGetSymbolAddress((void**)&wth, g_wth);
    cudaGetSymbolAddress((void**)&wtl, g_wtl);

    cudaFuncSetAttribute(mma_gemm, cudaFuncAttributeMaxDynamicSharedMemorySize, DYN_SMEM);

    const float Mf = (float)NNODES;
    dim3 gg(D / 64, NNODES / 128);   // (6, 256)

    cudaStream_t s1, s2;
    cudaEvent_t e0, e1, e2;
    cudaStreamCreateWithFlags(&s1, cudaStreamNonBlocking);
    cudaStreamCreateWithFlags(&s2, cudaStreamNonBlocking);
    cudaEventCreateWithFlags(&e0, cudaEventDisableTiming);
    cudaEventCreateWithFlags(&e1, cudaEventDisableTiming);
    cudaEventCreateWithFlags(&e2, cudaEventDisableTiming);

    zero_kernel<<<192, 256>>>();
    cudaEventRecord(e0, 0);
    cudaStreamWaitEvent(s1, e0, 0);
    cudaStreamWaitEvent(s2, e0, 0);

    // side stream 1: sentence branch + its stats (slot 6)
    hsent_kernel<<<dim3(BATCH, 4), EFEAT, 0, s1>>>(last_h, first_h);
    stats_kernel<<<1, EFEAT, 0, s1>>>(hs, BATCH, EFEAT, sum + 6 * EFEAT, sq + 6 * EFEAT);
    cudaEventRecord(e1, s1);

    // side stream 2: degree / CSR / mask selection
    deg_kernel<<<NEDGES / 256, 256, 0, s2>>>(edst);
    isq_kernel<<<NNODES / 256, 256, 0, s2>>>();
    scan_kernel<<<1, 1024, 0, s2>>>();
    scatter_kernel<<<NEDGES / 256, 256, 0, s2>>>(esrc, edst);
    sel_kernel<<<1, BATCH, 0, s2>>>(mask);
    cudaEventRecord(e2, s2);

    // main: input prep + stage-0 weights
    xprep_kernel<<<(NNODES * 320 + 255) / 256, 256>>>(x_nodes);
    wprep0_kernel<<<(D * 320 + 255) / 256, 256>>>(w_pre1, 300, 320,
                                                  wth + 0 * D * D, wtl + 0 * D * D);

    // GEMM1 (3-pass) -> h1/l1, fused stats slot 0 (bng row 0)
    mma_gemm<<<gg, 256, DYN_SMEM>>>(x0h, x0l, wth + 0 * D * D, wtl + 0 * D * D, b_pre1,
                                    h1, l1, 320, 10, 1, 1, sum + 0 * EFEAT, sq + 0 * EFEAT);
    fold_kernel<<<D, 128>>>(w_pre2, sum + 0 * EFEAT, sq + 0 * EFEAT,
                            bng_g + 0 * D, bng_b + 0 * D, Mf, b_pre2,
                            wth + 1 * D * D, wtl + 1 * D * D, bfp + 1 * D);

    // GEMM2 (3-pass) -> h2/l2, stats slot 1 (bng row 1)
    mma_gemm<<<gg, 256, DYN_SMEM>>>(h1, l1, wth + 1 * D * D, wtl + 1 * D * D, bfp + 1 * D,
                                    h2, l2, D, 12, 1, 1, sum + 1 * EFEAT, sq + 1 * EFEAT);
    fold_kernel<<<D, 128>>>(w_conv + 2 * D * D, sum + 1 * EFEAT, sq + 1 * EFEAT,
                            bng_g + 1 * D, bng_b + 1 * D, Mf, nullptr,
                            wth + 2 * D * D, wtl + 2 * D * D, bfp + 2 * D);

    // GEMM3 (2-pass; output fp16-rounded anyway) -> single fp16 xw
    mma_gemm<<<gg, 256, DYN_SMEM>>>(h2, l2, wth + 2 * D * D, wtl + 2 * D * D, bfp + 2 * D,
                                    xw, nullptr, D, 12, 0, 0, nullptr, nullptr);

    // join CSR stream, aggregate, stats slot 2 (bng row 4)
    cudaStreamWaitEvent(0, e2, 0);
    agg_kernel<<<NNODES, AGG_T>>>(xw, b_conv + 2 * D, h1, l1);
    stats_f16_kernel<<<256, D>>>(h1, l1, sum + 2 * EFEAT, sq + 2 * EFEAT);
    fold_kernel<<<D, 128>>>(w_post1, sum + 2 * EFEAT, sq + 2 * EFEAT,
                            bng_g + 4 * D, bng_b + 4 * D, Mf, b_post1,
                            wth + 3 * D * D, wtl + 3 * D * D, bfp + 3 * D);

    // GEMM4 (3-pass, single fp16 out — G5 consumes hi only) -> h2, stats slot 3 (bng row 5)
    mma_gemm<<<gg, 256, DYN_SMEM>>>(h1, l1, wth + 3 * D * D, wtl + 3 * D * D, bfp + 3 * D,
                                    h2, nullptr, D, 12, 1, 1, sum + 3 * EFEAT, sq + 3 * EFEAT);
    fold_kernel<<<D, 128>>>(w_post2, sum + 3 * EFEAT, sq + 3 * EFEAT,
                            bng_g + 5 * D, bng_b + 5 * D, Mf, b_post2,
                            wth + 4 * D * D, wtl + 4 * D * D, bfp + 4 * D);

    // GEMM5 (2-pass, single fp16 out; only 128 rows + stats consumed) -> h1, stats slot 4
    mma_gemm<<<gg, 256, DYN_SMEM>>>(h2, nullptr, wth + 4 * D * D, wtl + 4 * D * D, bfp + 4 * D,
                                    h1, nullptr, D, 12, 1, 0, sum + 4 * EFEAT, sq + 4 * EFEAT);

    // tail: gather (BN row 6 inline) -> cat-MLP (+stats slot 5) -> att+out
    gather_kernel<<<BATCH * 2, D>>>(h1, sum + 4 * EFEAT, sq + 4 * EFEAT,
                                    bng_g + 6 * D, bng_b + 6 * D);
    cat_gemm_kernel<<<BATCH, EFEAT>>>(w_cat, b_cat, sum + 5 * EFEAT, sq + 5 * EFEAT);
    cudaStreamWaitEvent(0, e1, 0);
    attout_kernel<<<BATCH, EFEAT>>>(sum + 5 * EFEAT, sq + 5 * EFEAT,
                                    sum + 6 * EFEAT, sq + 6 * EFEAT,
                                    bn_g, bn_b, w_out, b_out, out);

    cudaEventDestroy(e0);
    cudaEventDestroy(e1);
    cudaEventDestroy(e2);
    cudaStreamDestroy(s1);
    cudaStreamDestroy(s2);
}

// round 9
// speedup vs baseline: 3.1899x; 1.0500x over previous
#include <cuda_runtime.h>
#include <cuda_fp16.h>
#include <cstdint>
#include <math.h>

// ---------------- problem constants ----------------
#define NNODES 32768
#define D      384
#define EFEAT  768
#define BATCH  64
#define SEQ    512
#define NGRAPH 512
#define NEDGES 1048576
#define EPS    1e-5f

// ---------------- device scratch (static, no allocs) ----------------
__device__ __half g_x0h[(size_t)NNODES * 320];
__device__ __half g_x0l[(size_t)NNODES * 320];
__device__ __half g_h1[(size_t)NNODES * D];
__device__ __half g_l1[(size_t)NNODES * D];
__device__ __half g_h2[(size_t)NNODES * D];
__device__ __half g_xw[(size_t)NNODES * D];
__device__ int    g_degi[NNODES];
__device__ float  g_isq[NNODES];
__device__ int    g_off[NNODES + 1];
__device__ int    g_cursor[NNODES];
__device__ int    g_csr[NEDGES];
__device__ float  g_sum[7 * EFEAT];
__device__ float  g_sq[7 * EFEAT];
__device__ float  g_hsent[BATCH * EFEAT];
__device__ float  g_flat[BATCH * EFEAT];
__device__ float  g_outc[BATCH * EFEAT];
__device__ int    g_sel[BATCH * 2];
// folded transposed weights fp16 hi/lo: [N=384][KPAD<=384]
__device__ __half g_wth[5][D * D];
__device__ __half g_wtl[5][D * D];
__device__ float  g_biasf[5][D];

// ================= helpers =================
__device__ __forceinline__ uint32_t smem_u32(const void* p) {
    uint32_t a;
    asm("{ .reg .u64 t; cvta.to.shared.u64 t, %1; cvt.u32.u64 %0, t; }" : "=r"(a) : "l"(p));
    return a;
}
__device__ __forceinline__ void ldsm4(uint32_t* r, uint32_t addr) {
    asm volatile("ldmatrix.sync.aligned.m8n8.x4.shared.b16 {%0,%1,%2,%3}, [%4];"
                 : "=r"(r[0]), "=r"(r[1]), "=r"(r[2]), "=r"(r[3]) : "r"(addr));
}
__device__ __forceinline__ void mma16816f(float* c, const uint32_t* a, uint32_t b0, uint32_t b1) {
    asm volatile("mma.sync.aligned.m16n8k16.row.col.f32.f16.f16.f32 "
                 "{%0,%1,%2,%3},{%4,%5,%6,%7},{%8,%9},{%0,%1,%2,%3};"
                 : "+f"(c[0]), "+f"(c[1]), "+f"(c[2]), "+f"(c[3])
                 : "r"(a[0]), "r"(a[1]), "r"(a[2]), "r"(a[3]), "r"(b0), "r"(b1));
}
#define CP16(d, s) asm volatile("cp.async.cg.shared.global [%0], [%1], 16;" :: "r"(d), "l"(s) : "memory")
#define CP_COMMIT() asm volatile("cp.async.commit_group;" ::: "memory")
#define CP_WAIT1() asm volatile("cp.async.wait_group 1;" ::: "memory")
#define CP_WAIT0() asm volatile("cp.async.wait_group 0;" ::: "memory")

// stage layout (bytes): Ah@0 (10240) Al@10240 Bh@20480 (5120) Bl@25600 (5120); stride 30720
#define STAGE_STRIDE 30720
#define DYN_SMEM (2 * STAGE_STRIDE + 512)
#define AROW 40  // halves; 80B row pitch

__device__ __forceinline__ float bn_scale_of(const float* sum, const float* sq, int k,
                                             float Mf, const float* gam) {
    float m = sum[k] / Mf;
    float v = sq[k] / Mf - m * m;
    return gam[k] * rsqrtf(v + EPS);
}
__device__ __forceinline__ float bn_shift_of(const float* sum, const float* sq, int k,
                                             float Mf, const float* gam, const float* bet) {
    float m = sum[k] / Mf;
    float v = sq[k] / Mf - m * m;
    float s = gam[k] * rsqrtf(v + EPS);
    return bet[k] - m * s;
}

// ================= misc kernels =================
__global__ void zero_kernel() {
    int i = blockIdx.x * blockDim.x + threadIdx.x;
    if (i < NNODES) g_degi[i] = 0;
    if (i < 7 * EFEAT) { g_sum[i] = 0.f; g_sq[i] = 0.f; }
    if (i < BATCH * EFEAT) g_hsent[i] = 0.f;
}

__global__ void hsent_kernel(const float* __restrict__ lh, const float* __restrict__ fh) {
    int b = blockIdx.x, chunk = blockIdx.y, t = threadIdx.x;
    size_t base = ((size_t)b * SEQ + chunk * 128) * EFEAT + t;
    float s = 0.f;
    for (int ss = 0; ss < 128; ss++)
        s += lh[base + (size_t)ss * EFEAT] + fh[base + (size_t)ss * EFEAT];
    atomicAdd(&g_hsent[b * EFEAT + t], s * (0.5f / 512.0f));
}

// x_nodes fp32 [N,300] -> fp16 hi/lo [N,320] zero-padded
__global__ void xprep_kernel(const float* __restrict__ X) {
    size_t idx = (size_t)blockIdx.x * blockDim.x + threadIdx.x;
    if (idx >= (size_t)NNODES * 320) return;
    int row = (int)(idx / 320), k = (int)(idx % 320);
    float v = (k < 300) ? X[(size_t)row * 300 + k] : 0.f;
    __half h = __float2half_rn(v);
    g_x0h[idx] = h;
    g_x0l[idx] = __float2half_rn(v - __half2float(h));
}

// stage-0 weight prep (no BN fold): W[K,384] -> transposed fp16 hi/lo [384][KPAD]
__global__ void wprep0_kernel(const float* __restrict__ W, int K, int KPAD,
                              __half* __restrict__ oh, __half* __restrict__ ol) {
    int idx = blockIdx.x * blockDim.x + threadIdx.x;
    if (idx >= D * KPAD) return;
    int n = idx / KPAD, k = idx % KPAD;
    float v = (k < K) ? W[(size_t)k * D + n] : 0.f;
    __half h = __float2half_rn(v);
    oh[idx] = h;
    ol[idx] = __float2half_rn(v - __half2float(h));
}

// fused BN-fold: folded weight row (hi/lo) + folded bias, one block per output col n.
__global__ void fold_kernel(const float* __restrict__ W,
                            const float* __restrict__ sum, const float* __restrict__ sq,
                            const float* __restrict__ gam, const float* __restrict__ bet,
                            float Mf, const float* __restrict__ base,
                            __half* __restrict__ oh, __half* __restrict__ ol,
                            float* __restrict__ outb) {
    int n = blockIdx.x, t = threadIdx.x;
    float acc = 0.f;
#pragma unroll
    for (int i = 0; i < 3; i++) {
        int k = t + i * 128;
        float w = W[(size_t)k * D + n];
        float m = sum[k] / Mf;
        float var = sq[k] / Mf - m * m;
        float sc = gam[k] * rsqrtf(var + EPS);
        float sh = bet[k] - m * sc;
        float v = w * sc;
        __half h = __float2half_rn(v);
        oh[(size_t)n * D + k] = h;
        ol[(size_t)n * D + k] = __float2half_rn(v - __half2float(h));
        acc += sh * w;
    }
    __shared__ float red[128];
    red[t] = acc;
    __syncthreads();
    for (int o = 64; o > 0; o >>= 1) {
        if (t < o) red[t] += red[t + o];
        __syncthreads();
    }
    if (t == 0) outb[n] = (base ? base[n] : 0.f) + red[0];
}

// fp32 column stats
__global__ void stats_kernel(const float* __restrict__ X, int M, int N,
                             float* __restrict__ sum, float* __restrict__ sq) {
    int col = threadIdx.x;
    int rows_per = (M + gridDim.x - 1) / gridDim.x;
    int r0 = blockIdx.x * rows_per;
    int r1 = min(M, r0 + rows_per);
    float s = 0.f, q = 0.f;
    for (int r = r0; r < r1; r++) {
        float v = X[(size_t)r * N + col];
        s += v; q += v * v;
    }
    atomicAdd(&sum[col], s);
    atomicAdd(&sq[col], q);
}

// single fp16 column stats
__global__ void stats_f16_kernel(const __half* __restrict__ H,
                                 float* __restrict__ sum, float* __restrict__ sq) {
    int col = threadIdx.x;
    int rows_per = (NNODES + gridDim.x - 1) / gridDim.x;
    int r0 = blockIdx.x * rows_per;
    int r1 = min(NNODES, r0 + rows_per);
    float s = 0.f, q = 0.f;
    for (int r = r0; r < r1; r++) {
        float v = __half2float(H[(size_t)r * D + col]);
        s += v; q += v * v;
    }
    atomicAdd(&sum[col], s);
    atomicAdd(&sq[col], q);
}

// ================= cp.async tile stage =================
__device__ __forceinline__ void issue_tiles(uint32_t sbase, int stage, int tid,
                                            const __half* Ah, const __half* Al,
                                            const __half* Bh, const __half* Bl,
                                            int bm, int bn, int KPAD, int chunk,
                                            int load_al) {
    uint32_t sb = sbase + stage * STAGE_STRIDE;
#pragma unroll
    for (int it = 0; it < 2; it++) {
        int i = tid + it * 256;
        int row = i >> 2, c16 = i & 3;
        uint32_t d = sb + row * 80 + c16 * 16;
        const __half* sa = Ah + (size_t)(bm + row) * KPAD + chunk * 32 + c16 * 8;
        CP16(d, sa);
        if (load_al) {
            const __half* sl = Al + (size_t)(bm + row) * KPAD + chunk * 32 + c16 * 8;
            CP16(d + 10240, sl);
        }
    }
    {
        int row = tid >> 2, c16 = tid & 3;
        uint32_t d = sb + 20480 + row * 80 + c16 * 16;
        const __half* sbh = Bh + (size_t)(bn + row) * KPAD + chunk * 32 + c16 * 8;
        const __half* sbl = Bl + (size_t)(bn + row) * KPAD + chunk * 32 + c16 * 8;
        CP16(d, sbh);
        CP16(d + 5120, sbl);
    }
}

// ================= mma.sync fp16 GEMM, double-buffered =================
// three_pass=1: C = (Ah+Al)@(Bh+Bl)^T dropping AlBl (err ~2^-22)
// three_pass=0: C = Ah@(Bh+Bl)^T (err ~2^-11; A-lo never loaded)
// block 128x64, chunk K32, 8 warps (4m x 2n); optional fused column stats.
// Output: Cl!=null -> hi/lo fp16 pair; Cl==null -> single fp16 in Ch.
__global__ void __launch_bounds__(256, 2)
mma_gemm(const __half* __restrict__ Ah, const __half* __restrict__ Al,
         const __half* __restrict__ Bh, const __half* __restrict__ Bl,
         const float* __restrict__ biasf,
         __half* __restrict__ Ch, __half* __restrict__ Cl,
         int KPAD, int nchunks, int do_relu, int three_pass,
         float* __restrict__ gsum, float* __restrict__ gsq) {
    extern __shared__ char dsm[];
    float* scs = (float*)(dsm + 2 * STAGE_STRIDE);
    float* scq = scs + 64;
    uint32_t sbase = smem_u32(dsm);

    int tid = threadIdx.x;
    int wid = tid >> 5, lane = tid & 31;
    int bm = blockIdx.y * 128, bn = blockIdx.x * 64;
    int wm = wid & 3, wn = wid >> 2;

    if (tid < 64) { scs[tid] = 0.f; scq[tid] = 0.f; }

    float acc[2][4][4];
#pragma unroll
    for (int i = 0; i < 2; i++)
#pragma unroll
        for (int j = 0; j < 4; j++)
#pragma unroll
            for (int k = 0; k < 4; k++) acc[i][j][k] = 0.f;

    int g = lane >> 3, r = lane & 7;
    int frag_row = (g & 1) * 8 + r;
    int frag_col = (g >> 1) * 8;

    issue_tiles(sbase, 0, tid, Ah, Al, Bh, Bl, bm, bn, KPAD, 0, three_pass);
    CP_COMMIT();

    for (int c = 0; c < nchunks; c++) {
        if (c + 1 < nchunks) {
            issue_tiles(sbase, (c + 1) & 1, tid, Ah, Al, Bh, Bl, bm, bn, KPAD, c + 1, three_pass);
            CP_COMMIT();
            CP_WAIT1();
        } else {
            CP_WAIT0();
        }
        __syncthreads();

        uint32_t baseAh = sbase + (c & 1) * STAGE_STRIDE;
        uint32_t baseAl = baseAh + 10240;
        uint32_t baseBh = baseAh + 20480;
        uint32_t baseBl = baseAh + 25600;
#pragma unroll
        for (int ks = 0; ks < 2; ks++) {
            int k0 = ks * 16;
            uint32_t ah[2][4], al[2][4], bh[2][4], bl[2][4];
#pragma unroll
            for (int mi = 0; mi < 2; mi++) {
                int row = wm * 32 + mi * 16 + frag_row;
                uint32_t off = (uint32_t)(row * AROW + k0 + frag_col) * 2;
                ldsm4(ah[mi], baseAh + off);
                if (three_pass) ldsm4(al[mi], baseAl + off);
            }
#pragma unroll
            for (int j = 0; j < 2; j++) {
                int row = wn * 32 + j * 16 + frag_row;
                uint32_t off = (uint32_t)(row * AROW + k0 + frag_col) * 2;
                ldsm4(bh[j], baseBh + off);
                ldsm4(bl[j], baseBl + off);
            }
#pragma unroll
            for (int mi = 0; mi < 2; mi++)
#pragma unroll
                for (int nt = 0; nt < 4; nt++) {
                    int j = nt >> 1, sel = nt & 1;
                    mma16816f(acc[mi][nt], ah[mi], bh[j][sel], bh[j][sel + 2]);
                    mma16816f(acc[mi][nt], ah[mi], bl[j][sel], bl[j][sel + 2]);
                    if (three_pass)
                        mma16816f(acc[mi][nt], al[mi], bh[j][sel], bh[j][sel + 2]);
                }
        }
        __syncthreads();
    }

    // ---- epilogue ----
    int tm = lane >> 2;
    int tn = (lane & 3) * 2;
    bool dosum = (gsum != nullptr);
#pragma unroll
    for (int nt = 0; nt < 4; nt++) {
        float s0 = 0.f, s1 = 0.f, q0 = 0.f, q1 = 0.f;
        int col = bn + wn * 32 + nt * 8 + tn;
        float b0 = biasf[col], b1 = biasf[col + 1];
#pragma unroll
        for (int mi = 0; mi < 2; mi++) {
            int row0 = bm + wm * 32 + mi * 16 + tm;
            float v0 = acc[mi][nt][0] + b0, v1 = acc[mi][nt][1] + b1;
            float v2 = acc[mi][nt][2] + b0, v3 = acc[mi][nt][3] + b1;
            if (do_relu) {
                v0 = fmaxf(v0, 0.f); v1 = fmaxf(v1, 0.f);
                v2 = fmaxf(v2, 0.f); v3 = fmaxf(v3, 0.f);
            }
            __half h0 = __float2half_rn(v0), h1 = __float2half_rn(v1);
            __half h2 = __float2half_rn(v2), h3 = __float2half_rn(v3);
            uint32_t ph01 = ((uint32_t)__half_as_ushort(h1) << 16) | __half_as_ushort(h0);
            uint32_t ph23 = ((uint32_t)__half_as_ushort(h3) << 16) | __half_as_ushort(h2);
            *(uint32_t*)&Ch[(size_t)row0 * D + col] = ph01;
            *(uint32_t*)&Ch[(size_t)(row0 + 8) * D + col] = ph23;
            if (Cl) {
                __half l0 = __float2half_rn(v0 - __half2float(h0));
                __half l1 = __float2half_rn(v1 - __half2float(h1));
                __half l2 = __float2half_rn(v2 - __half2float(h2));
                __half l3 = __float2half_rn(v3 - __half2float(h3));
                uint32_t pl01 = ((uint32_t)__half_as_ushort(l1) << 16) | __half_as_ushort(l0);
                uint32_t pl23 = ((uint32_t)__half_as_ushort(l3) << 16) | __half_as_ushort(l2);
                *(uint32_t*)&Cl[(size_t)row0 * D + col] = pl01;
                *(uint32_t*)&Cl[(size_t)(row0 + 8) * D + col] = pl23;
            }
            s0 += v0 + v2; s1 += v1 + v3;
            q0 += v0 * v0 + v2 * v2; q1 += v1 * v1 + v3 * v3;
        }
        if (dosum) {
#pragma unroll
            for (int o = 4; o < 32; o <<= 1) {
                s0 += __shfl_xor_sync(0xffffffffu, s0, o);
                s1 += __shfl_xor_sync(0xffffffffu, s1, o);
                q0 += __shfl_xor_sync(0xffffffffu, q0, o);
                q1 += __shfl_xor_sync(0xffffffffu, q1, o);
            }
            if (lane < 4) {
                int cl = wn * 32 + nt * 8 + lane * 2;
                atomicAdd(&scs[cl], s0); atomicAdd(&scs[cl + 1], s1);
                atomicAdd(&scq[cl], q0); atomicAdd(&scq[cl + 1], q1);
            }
        }
    }
    if (dosum) {
        __syncthreads();
        if (tid < 64) {
            atomicAdd(&gsum[bn + tid], scs[tid]);
            atomicAdd(&gsq[bn + tid], scq[tid]);
        }
    }
}

// ================= graph kernels =================
__global__ void deg_kernel(const int* __restrict__ dst) {
    int e = blockIdx.x * blockDim.x + threadIdx.x;
    if (e < NEDGES) atomicAdd(&g_degi[dst[e]], 1);
}
__global__ void isq_kernel() {
    int n = blockIdx.x * blockDim.x + threadIdx.x;
    if (n < NNODES) g_isq[n] = rsqrtf((float)g_degi[n] + 1.0f);
}
__global__ void scan_kernel() {
    __shared__ int sh[1024];
    int tid = threadIdx.x;
    int base = tid * 32;
    int local[32];
    int s = 0;
    for (int i = 0; i < 32; i++) { local[i] = s; s += g_degi[base + i]; }
    sh[tid] = s;
    __syncthreads();
    for (int off = 1; off < 1024; off <<= 1) {
        int v = 0;
        if (tid >= off) v = sh[tid - off];
        __syncthreads();
        if (tid >= off) sh[tid] += v;
        __syncthreads();
    }
    int prev = (tid == 0) ? 0 : sh[tid - 1];
    for (int i = 0; i < 32; i++) {
        g_off[base + i] = prev + local[i];
        g_cursor[base + i] = prev + local[i];
    }
    if (tid == 1023) g_off[NNODES] = sh[1023];
}
__global__ void scatter_kernel(const int* __restrict__ src, const int* __restrict__ dst) {
    int e = blockIdx.x * blockDim.x + threadIdx.x;
    if (e < NEDGES) {
        int d = dst[e];
        int p = atomicAdd(&g_cursor[d], 1);
        g_csr[p] = src[e];
    }
}

// GCN aggregation: fp16 in (u32/half2 loads), fp32 accumulate, bias+relu, single fp16 out
#define AGG_T 192
__global__ void __launch_bounds__(AGG_T)
agg_kernel(const __half* __restrict__ xw, const float* __restrict__ bias,
           __half* __restrict__ oh) {
    int n = blockIdx.x;
    int t = threadIdx.x;
    float isqn = g_isq[n];
    float sc = isqn * isqn;
    const uint32_t* selfrow = (const uint32_t*)(xw + (size_t)n * D);
    uint32_t su = selfrow[t];
    __half2 sh2 = *(__half2*)&su;
    float a0 = __low2float(sh2) * sc;
    float a1 = __high2float(sh2) * sc;

    int beg = g_off[n], end = g_off[n + 1];
    __shared__ int ssrc[AGG_T];
    __shared__ float scoef[AGG_T];
    for (int p = beg; p < end; p += AGG_T) {
        int cnt = min(AGG_T, end - p);
        __syncthreads();
        if (t < cnt) {
            int s = g_csr[p + t];
            ssrc[t] = s;
            scoef[t] = g_isq[s] * isqn;
        }
        __syncthreads();
        for (int j = 0; j < cnt; j++) {
            int s = ssrc[j];
            float c = scoef[j];
            uint32_t u = ((const uint32_t*)(xw + (size_t)s * D))[t];
            __half2 h2v = *(__half2*)&u;
            a0 += __low2float(h2v) * c;
            a1 += __high2float(h2v) * c;
        }
    }
    float2 bb = *(const float2*)(bias + 2 * t);
    float v0 = fmaxf(a0 + bb.x, 0.f);
    float v1 = fmaxf(a1 + bb.y, 0.f);
    __half h0 = __float2half_rn(v0);
    __half h1 = __float2half_rn(v1);
    uint32_t ph = ((uint32_t)__half_as_ushort(h1) << 16) | __half_as_ushort(h0);
    ((uint32_t*)(oh + (size_t)n * D))[t] = ph;
}

// ================= tail kernels =================
__global__ void sel_kernel(const int* __restrict__ mask) {
    int b = threadIdx.x;
    int c = 0;
    for (int i = 0; i < NGRAPH; i++) {
        if (mask[b * NGRAPH + i]) {
            if (c < 2) g_sel[b * 2 + c] = i;
            c++;
        }
    }
}
// gather 2 masked nodes per sample (single fp16 source), BN (stats slot 4) inline
__global__ void gather_kernel(const __half* __restrict__ H,
                              const float* __restrict__ sum, const float* __restrict__ sq,
                              const float* __restrict__ gam, const float* __restrict__ bet) {
    int b = blockIdx.x >> 1;
    int j = blockIdx.x & 1;
    int node = b * NGRAPH + g_sel[b * 2 + j];
    int t = threadIdx.x;
    float v = __half2float(H[(size_t)node * D + t]);
    float s = bn_scale_of(sum, sq, t, (float)NNODES, gam);
    float sh = bn_shift_of(sum, sq, t, (float)NNODES, gam, bet);
    g_flat[b * EFEAT + j * D + t] = v * s + sh;
}
// outc = relu(flat @ w_cat + b_cat), fused column stats (slot 5)
__global__ void cat_gemm_kernel(const float* __restrict__ Wc, const float* __restrict__ bc,
                                float* __restrict__ sum, float* __restrict__ sq) {
    __shared__ float sh[EFEAT];
    int b = blockIdx.x, t = threadIdx.x;
    sh[t] = g_flat[b * EFEAT + t];
    __syncthreads();
    float s = bc[t];
    for (int k = 0; k < EFEAT; k++) s += sh[k] * Wc[(size_t)k * EFEAT + t];
    s = fmaxf(s, 0.f);
    g_outc[b * EFEAT + t] = s;
    atomicAdd(&sum[t], s);
    atomicAdd(&sq[t], s * s);
}
// att = BN1(hsent) + BN0(outc); out = att @ w_out + b_out   (one block per sample)
__global__ void attout_kernel(const float* __restrict__ sum5, const float* __restrict__ sq5,
                              const float* __restrict__ sum6, const float* __restrict__ sq6,
                              const float* __restrict__ bg, const float* __restrict__ bb,
                              const float* __restrict__ wout, const float* __restrict__ bout,
                              float* __restrict__ out) {
    __shared__ float satt[EFEAT];
    int b = blockIdx.x, t = threadIdx.x;
    float Bf = (float)BATCH;
    float m0 = sum5[t] / Bf, v0 = sq5[t] / Bf - m0 * m0;
    float oc = bg[t] * (g_outc[b * EFEAT + t] - m0) * rsqrtf(v0 + EPS) + bb[t];
    float m1 = sum6[t] / Bf, v1 = sq6[t] / Bf - m1 * m1;
    float hh = bg[EFEAT + t] * (g_hsent[b * EFEAT + t] - m1) * rsqrtf(v1 + EPS) + bb[EFEAT + t];
    satt[t] = hh + oc;
    __syncthreads();
    int w = t >> 5, lane = t & 31;
    if (w < 3) {
        int c = w;
        float p = 0.f;
        for (int e = lane; e < EFEAT; e += 32) p += satt[e] * wout[e * 3 + c];
#pragma unroll
        for (int o = 16; o > 0; o >>= 1) p += __shfl_xor_sync(0xffffffffu, p, o);
        if (lane == 0) out[b * 3 + c] = p + bout[c];
    }
}

// ============================== launch ==============================
extern "C" void kernel_launch(void* const* d_in, const int* in_sizes, int n_in,
                              void* d_out, int out_size) {
    const float* last_h  = (const float*)d_in[0];
    const float* first_h = (const float*)d_in[1];
    const float* x_nodes = (const float*)d_in[2];
    const int*   eidx    = (const int*)d_in[3];
    const int*   mask    = (const int*)d_in[4];
    const float* w_pre1  = (const float*)d_in[5];
    const float* b_pre1  = (const float*)d_in[6];
    const float* w_pre2  = (const float*)d_in[7];
    const float* b_pre2  = (const float*)d_in[8];
    const float* w_conv  = (const float*)d_in[9];
    const float* b_conv  = (const float*)d_in[10];
    const float* bng_g   = (const float*)d_in[11];
    const float* bng_b   = (const float*)d_in[12];
    const float* w_post1 = (const float*)d_in[13];
    const float* b_post1 = (const float*)d_in[14];
    const float* w_post2 = (const float*)d_in[15];
    const float* b_post2 = (const float*)d_in[16];
    const float* w_cat   = (const float*)d_in[17];
    const float* b_cat   = (const float*)d_in[18];
    const float* bn_g    = (const float*)d_in[19];
    const float* bn_b    = (const float*)d_in[20];
    const float* w_out   = (const float*)d_in[21];
    const float* b_out   = (const float*)d_in[22];
    float* out = (float*)d_out;

    const int* esrc = eidx;
    const int* edst = eidx + NEDGES;

    float *sum, *sq, *hs, *bfp;
    __half *x0h, *x0l, *h1, *l1, *h2, *wth, *wtl, *xw;
    cudaGetSymbolAddress((void**)&sum, g_sum);
    cudaGetSymbolAddress((void**)&sq, g_sq);
    cudaGetSymbolAddress((void**)&hs, g_hsent);
    cudaGetSymbolAddress((void**)&bfp, g_biasf);
    cudaGetSymbolAddress((void**)&xw, g_xw);
    cudaGetSymbolAddress((void**)&x0h, g_x0h);
    cudaGetSymbolAddress((void**)&x0l, g_x0l);
    cudaGetSymbolAddress((void**)&h1, g_h1);
    cudaGetSymbolAddress((void**)&l1, g_l1);
    cudaGetSymbolAddress((void**)&h2, g_h2);
    cudaGetSymbolAddress((void**)&wth, g_wth);
    cudaGetSymbolAddress((void**)&wtl, g_wtl);

    cudaFuncSetAttribute(mma_gemm, cudaFuncAttributeMaxDynamicSharedMemorySize, DYN_SMEM);

    const float Mf = (float)NNODES;
    dim3 gg(D / 64, NNODES / 128);   // (6, 256)

    cudaStream_t s1, s2;
    cudaEvent_t e0, e1, e2;
    cudaStreamCreateWithFlags(&s1, cudaStreamNonBlocking);
    cudaStreamCreateWithFlags(&s2, cudaStreamNonBlocking);
    cudaEventCreateWithFlags(&e0, cudaEventDisableTiming);
    cudaEventCreateWithFlags(&e1, cudaEventDisableTiming);
    cudaEventCreateWithFlags(&e2, cudaEventDisableTiming);

    zero_kernel<<<192, 256>>>();
    cudaEventRecord(e0, 0);
    cudaStreamWaitEvent(s1, e0, 0);
    cudaStreamWaitEvent(s2, e0, 0);

    // side stream 1: sentence branch + its stats (slot 6)
    hsent_kernel<<<dim3(BATCH, 4), EFEAT, 0, s1>>>(last_h, first_h);
    stats_kernel<<<1, EFEAT, 0, s1>>>(hs, BATCH, EFEAT, sum + 6 * EFEAT, sq + 6 * EFEAT);
    cudaEventRecord(e1, s1);

    // side stream 2: degree / CSR / mask selection
    deg_kernel<<<NEDGES / 256, 256, 0, s2>>>(edst);
    isq_kernel<<<NNODES / 256, 256, 0, s2>>>();
    scan_kernel<<<1, 1024, 0, s2>>>();
    scatter_kernel<<<NEDGES / 256, 256, 0, s2>>>(esrc, edst);
    sel_kernel<<<1, BATCH, 0, s2>>>(mask);
    cudaEventRecord(e2, s2);

    // main: input prep + stage-0 weights
    xprep_kernel<<<(NNODES * 320 + 255) / 256, 256>>>(x_nodes);
    wprep0_kernel<<<(D * 320 + 255) / 256, 256>>>(w_pre1, 300, 320,
                                                  wth + 0 * D * D, wtl + 0 * D * D);

    // GEMM1 (3-pass) -> h1/l1, fused stats slot 0 (bng row 0)
    mma_gemm<<<gg, 256, DYN_SMEM>>>(x0h, x0l, wth + 0 * D * D, wtl + 0 * D * D, b_pre1,
                                    h1, l1, 320, 10, 1, 1, sum + 0 * EFEAT, sq + 0 * EFEAT);
    fold_kernel<<<D, 128>>>(w_pre2, sum + 0 * EFEAT, sq + 0 * EFEAT,
                            bng_g + 0 * D, bng_b + 0 * D, Mf, b_pre2,
                            wth + 1 * D * D, wtl + 1 * D * D, bfp + 1 * D);

    // GEMM2 (3-pass, single fp16 out — G3 consumes hi only) -> h2, stats slot 1 (bng row 1)
    mma_gemm<<<gg, 256, DYN_SMEM>>>(h1, l1, wth + 1 * D * D, wtl + 1 * D * D, bfp + 1 * D,
                                    h2, nullptr, D, 12, 1, 1, sum + 1 * EFEAT, sq + 1 * EFEAT);
    fold_kernel<<<D, 128>>>(w_conv + 2 * D * D, sum + 1 * EFEAT, sq + 1 * EFEAT,
                            bng_g + 1 * D, bng_b + 1 * D, Mf, nullptr,
                            wth + 2 * D * D, wtl + 2 * D * D, bfp + 2 * D);

    // GEMM3 (2-pass; output fp16-rounded anyway) -> single fp16 xw
    mma_gemm<<<gg, 256, DYN_SMEM>>>(h2, nullptr, wth + 2 * D * D, wtl + 2 * D * D, bfp + 2 * D,
                                    xw, nullptr, D, 12, 0, 0, nullptr, nullptr);

    // join CSR stream, aggregate (single fp16 out), stats slot 2 (bng row 4)
    cudaStreamWaitEvent(0, e2, 0);
    agg_kernel<<<NNODES, AGG_T>>>(xw, b_conv + 2 * D, h1);
    stats_f16_kernel<<<256, D>>>(h1, sum + 2 * EFEAT, sq + 2 * EFEAT);
    fold_kernel<<<D, 128>>>(w_post1, sum + 2 * EFEAT, sq + 2 * EFEAT,
                            bng_g + 4 * D, bng_b + 4 * D, Mf, b_post1,
                            wth + 3 * D * D, wtl + 3 * D * D, bfp + 3 * D);

    // GEMM4 (2-pass, single fp16 out) -> h2, stats slot 3 (bng row 5)
    mma_gemm<<<gg, 256, DYN_SMEM>>>(h1, nullptr, wth + 3 * D * D, wtl + 3 * D * D, bfp + 3 * D,
                                    h2, nullptr, D, 12, 1, 0, sum + 3 * EFEAT, sq + 3 * EFEAT);
    fold_kernel<<<D, 128>>>(w_post2, sum + 3 * EFEAT, sq + 3 * EFEAT,
                            bng_g + 5 * D, bng_b + 5 * D, Mf, b_post2,
                            wth + 4 * D * D, wtl + 4 * D * D, bfp + 4 * D);

    // GEMM5 (2-pass, single fp16 out; only 128 rows + stats consumed) -> h1, stats slot 4
    mma_gemm<<<gg, 256, DYN_SMEM>>>(h2, nullptr, wth + 4 * D * D, wtl + 4 * D * D, bfp + 4 * D,
                                    h1, nullptr, D, 12, 1, 0, sum + 4 * EFEAT, sq + 4 * EFEAT);

    // tail: gather (BN row 6 inline) -> cat-MLP (+stats slot 5) -> att+out
    gather_kernel<<<BATCH * 2, D>>>(h1, sum + 4 * EFEAT, sq + 4 * EFEAT,
                                    bng_g + 6 * D, bng_b + 6 * D);
    cat_gemm_kernel<<<BATCH, EFEAT>>>(w_cat, b_cat, sum + 5 * EFEAT, sq + 5 * EFEAT);
    cudaStreamWaitEvent(0, e1, 0);
    attout_kernel<<<BATCH, EFEAT>>>(sum + 5 * EFEAT, sq + 5 * EFEAT,
                                    sum + 6 * EFEAT, sq + 6 * EFEAT,
                                    bn_g, bn_b, w_out, b_out, out);

    cudaEventDestroy(e0);
    cudaEventDestroy(e1);
    cudaEventDestroy(e2);
    cudaStreamDestroy(s1);
    cudaStreamDestroy(s2);
}